// round 3
// baseline (speedup 1.0000x reference)
#include <cuda_runtime.h>
#include <cuda_bf16.h>
#include <math.h>

// ---------------------------------------------------------------------------
// Problem constants
// ---------------------------------------------------------------------------
#define N_NODES_MAX 20000
#define D1 128   // conv1 out
#define D2 64    // conv2 out
#define D3 128   // mlp hidden 1
#define D4 64    // mlp hidden 2
#define NCLS 10

// ---------------------------------------------------------------------------
// Scratch (static device globals; no allocations anywhere)
// ---------------------------------------------------------------------------
__device__ float g_XR [N_NODES_MAX * D1];  // x @ W1_rel
__device__ float g_H1 [N_NODES_MAX * D1];  // x @ W1_root + b1  (+= scatter)
__device__ float g_XR2[N_NODES_MAX * D2];  // h1 @ W2_rel
__device__ float g_H2 [N_NODES_MAX * D2];  // h1 @ W2_root + b2 (+= scatter)
__device__ float g_H3 [N_NODES_MAX * D3];
__device__ float g_H4 [N_NODES_MAX * D4];

// ---------------------------------------------------------------------------
// Tiled SGEMM:  C[M,N] = A[M,K] @ W[K,N] (+bias) (+relu)
// BN == N (single block-column). M ragged.
// ---------------------------------------------------------------------------
template<int BM, int BN, int BK, int TM, int TN, bool BIAS, bool RELU>
__global__ void __launch_bounds__((BM/TM)*(BN/TN))
sgemm_kernel(const float* __restrict__ A, const float* __restrict__ W,
             const float* __restrict__ bias, float* __restrict__ C,
             int M, int K)
{
    constexpr int T = (BM / TM) * (BN / TN);
    constexpr int N = BN;

    __shared__ float As[BK][BM];
    __shared__ float Ws[BK][BN];

    const int tid = threadIdx.x;
    const int tx  = tid % (BN / TN);
    const int ty  = tid / (BN / TN);
    const int rowBase = blockIdx.x * BM;

    float acc[TM][TN];
    #pragma unroll
    for (int i = 0; i < TM; i++)
        #pragma unroll
        for (int j = 0; j < TN; j++) acc[i][j] = 0.f;

    for (int k0 = 0; k0 < K; k0 += BK) {
        // --- load A tile (transposed into As[k][row]) ---
        constexpr int A_F4  = BM * BK / 4;
        constexpr int A_IT  = A_F4 / T;
        #pragma unroll
        for (int it = 0; it < A_IT; it++) {
            int i  = tid + it * T;
            int r  = i / (BK / 4);
            int c4 = i % (BK / 4);
            float4 v = make_float4(0.f, 0.f, 0.f, 0.f);
            int gr = rowBase + r;
            if (gr < M)
                v = *(const float4*)(A + (size_t)gr * K + k0 + c4 * 4);
            As[c4 * 4 + 0][r] = v.x;
            As[c4 * 4 + 1][r] = v.y;
            As[c4 * 4 + 2][r] = v.z;
            As[c4 * 4 + 3][r] = v.w;
        }
        // --- load W tile ---
        constexpr int W_F4 = BK * BN / 4;
        constexpr int W_IT = W_F4 / T;
        #pragma unroll
        for (int it = 0; it < W_IT; it++) {
            int i  = tid + it * T;
            int r  = i / (BN / 4);
            int c4 = i % (BN / 4);
            *(float4*)&Ws[r][c4 * 4] =
                *(const float4*)(W + (size_t)(k0 + r) * N + c4 * 4);
        }
        __syncthreads();

        #pragma unroll
        for (int k = 0; k < BK; k++) {
            float ra[TM], rb[TN];
            #pragma unroll
            for (int i = 0; i < TM; i++) ra[i] = As[k][ty * TM + i];
            #pragma unroll
            for (int j = 0; j < TN; j++) rb[j] = Ws[k][tx * TN + j];
            #pragma unroll
            for (int i = 0; i < TM; i++)
                #pragma unroll
                for (int j = 0; j < TN; j++)
                    acc[i][j] = fmaf(ra[i], rb[j], acc[i][j]);
        }
        __syncthreads();
    }

    // --- epilogue ---
    #pragma unroll
    for (int i = 0; i < TM; i++) {
        int gr = rowBase + ty * TM + i;
        if (gr >= M) continue;
        #pragma unroll
        for (int j = 0; j < TN; j++) {
            int col = tx * TN + j;
            float v = acc[i][j];
            if (BIAS) v += bias[col];
            if (RELU) v = fmaxf(v, 0.f);
            C[(size_t)gr * N + col] = v;
        }
    }
}

// ---------------------------------------------------------------------------
// Edge scatter:  dst_feat[dst] += src_feat[src], F floats/row.
// One warp per edge; vectorized global reductions.
// edge_index is INT32 (JAX downcasts int64 without x64 mode).
// ---------------------------------------------------------------------------
template<int F>
__global__ void scatter_add_kernel(const float* __restrict__ src_feat,
                                   float* __restrict__ dst_feat,
                                   const int* __restrict__ ei,
                                   int nEdges)
{
    int e = blockIdx.x * (blockDim.x >> 5) + (threadIdx.x >> 5);
    if (e >= nEdges) return;
    int lane = threadIdx.x & 31;

    int s = ei[e];
    int d = ei[nEdges + e];

    if (F == 128) {
        const float4 v = *(const float4*)(src_feat + (size_t)s * 128 + lane * 4);
        float* dp = dst_feat + (size_t)d * 128 + lane * 4;
        asm volatile("red.global.add.v4.f32 [%0], {%1,%2,%3,%4};"
                     :: "l"(dp), "f"(v.x), "f"(v.y), "f"(v.z), "f"(v.w)
                     : "memory");
    } else { // F == 64
        const float2 v = *(const float2*)(src_feat + (size_t)s * 64 + lane * 2);
        float* dp = dst_feat + (size_t)d * 64 + lane * 2;
        asm volatile("red.global.add.v2.f32 [%0], {%1,%2};"
                     :: "l"(dp), "f"(v.x), "f"(v.y)
                     : "memory");
    }
}

// ---------------------------------------------------------------------------
// In-place relu (float4)
// ---------------------------------------------------------------------------
__global__ void relu_kernel(float* __restrict__ p, int n4)
{
    int i = blockIdx.x * blockDim.x + threadIdx.x;
    if (i >= n4) return;
    float4 v = ((float4*)p)[i];
    v.x = fmaxf(v.x, 0.f); v.y = fmaxf(v.y, 0.f);
    v.z = fmaxf(v.z, 0.f); v.w = fmaxf(v.w, 0.f);
    ((float4*)p)[i] = v;
}

// ---------------------------------------------------------------------------
// Head: logits = H4 @ lin3 + b3  (K=64, N=10)  then log_softmax.
// One warp per node; lanes 0..9 own one class each.
// ---------------------------------------------------------------------------
__global__ void head_kernel(const float* __restrict__ H4,
                            const float* __restrict__ W3,
                            const float* __restrict__ b3,
                            float* __restrict__ out, int M)
{
    int node = blockIdx.x * (blockDim.x >> 5) + (threadIdx.x >> 5);
    if (node >= M) return;
    int lane = threadIdx.x & 31;

    float acc = -1e30f;
    if (lane < NCLS) {
        acc = b3[lane];
        const float* h = H4 + (size_t)node * D4;
        #pragma unroll
        for (int k = 0; k < D4; k++)
            acc = fmaf(__ldg(h + k), __ldg(W3 + k * NCLS + lane), acc);
    }
    // warp-wide max
    float m = acc;
    #pragma unroll
    for (int o = 16; o > 0; o >>= 1)
        m = fmaxf(m, __shfl_xor_sync(0xffffffffu, m, o));
    float ex = (lane < NCLS) ? expf(acc - m) : 0.f;
    float ssum = ex;
    #pragma unroll
    for (int o = 16; o > 0; o >>= 1)
        ssum += __shfl_xor_sync(0xffffffffu, ssum, o);
    float lse = m + logf(ssum);
    if (lane < NCLS)
        out[(size_t)node * NCLS + lane] = acc - lse;
}

// ---------------------------------------------------------------------------
// Launch
// ---------------------------------------------------------------------------
extern "C" void kernel_launch(void* const* d_in, const int* in_sizes, int n_in,
                              void* d_out, int out_size)
{
    const float* x      = (const float*)d_in[0];
    const int*   ei     = (const int*)d_in[1];     // int32 edge_index [2, E]
    const float* W1_rel = (const float*)d_in[2];
    const float* W1_rt  = (const float*)d_in[3];
    const float* b1     = (const float*)d_in[4];
    const float* W2_rel = (const float*)d_in[5];
    const float* W2_rt  = (const float*)d_in[6];
    const float* b2     = (const float*)d_in[7];
    const float* L1w    = (const float*)d_in[8];
    const float* L1b    = (const float*)d_in[9];
    const float* L2w    = (const float*)d_in[10];
    const float* L2b    = (const float*)d_in[11];
    const float* L3w    = (const float*)d_in[12];
    const float* L3b    = (const float*)d_in[13];
    float*       out    = (float*)d_out;

    const int DIN = 256;
    const int M   = in_sizes[0] / DIN;       // 20000
    const int nE  = in_sizes[1] / 2;         // 320000

    float *XR, *H1, *XR2, *H2, *H3, *H4;
    cudaGetSymbolAddress((void**)&XR,  g_XR);
    cudaGetSymbolAddress((void**)&H1,  g_H1);
    cudaGetSymbolAddress((void**)&XR2, g_XR2);
    cudaGetSymbolAddress((void**)&H2,  g_H2);
    cudaGetSymbolAddress((void**)&H3,  g_H3);
    cudaGetSymbolAddress((void**)&H4,  g_H4);

    const int gM128 = (M + 127) / 128;

    // conv1: XR = x@W1_rel ; H1 = x@W1_root + b1
    sgemm_kernel<128,128,16,8,8,false,false><<<gM128, 256>>>(x, W1_rel, nullptr, XR, M, DIN);
    sgemm_kernel<128,128,16,8,8,true ,false><<<gM128, 256>>>(x, W1_rt,  b1,      H1, M, DIN);

    // H1[dst] += XR[src]
    {
        int warpsPerBlk = 8;
        int blks = (nE + warpsPerBlk - 1) / warpsPerBlk;
        scatter_add_kernel<128><<<blks, warpsPerBlk * 32>>>(XR, H1, ei, nE);
    }

    // relu(H1)
    {
        int n4 = M * D1 / 4;
        relu_kernel<<<(n4 + 255) / 256, 256>>>(H1, n4);
    }

    // conv2: XR2 = H1@W2_rel ; H2 = H1@W2_root + b2
    sgemm_kernel<128,64,16,8,8,false,false><<<gM128, 128>>>(H1, W2_rel, nullptr, XR2, M, D1);
    sgemm_kernel<128,64,16,8,8,true ,false><<<gM128, 128>>>(H1, W2_rt,  b2,      H2,  M, D1);

    // H2[dst] += XR2[src]   (no relu after conv2 in reference)
    {
        int warpsPerBlk = 8;
        int blks = (nE + warpsPerBlk - 1) / warpsPerBlk;
        scatter_add_kernel<64><<<blks, warpsPerBlk * 32>>>(XR2, H2, ei, nE);
    }

    // MLP: H3 = relu(H2@L1w + L1b) ; H4 = relu(H3@L2w + L2b)
    sgemm_kernel<128,128,16,8,8,true,true><<<gM128, 256>>>(H2, L1w, L1b, H3, M, D2);
    sgemm_kernel<128,64 ,16,8,8,true,true><<<gM128, 128>>>(H3, L2w, L2b, H4, M, D3);

    // head: logits + log_softmax
    {
        int warpsPerBlk = 8;
        int blks = (M + warpsPerBlk - 1) / warpsPerBlk;
        head_kernel<<<blks, warpsPerBlk * 32>>>(H4, L3w, L3b, out, M);
    }
}

// round 4
// speedup vs baseline: 1.2913x; 1.2913x over previous
#include <cuda_runtime.h>
#include <cuda_bf16.h>
#include <math.h>

// ---------------------------------------------------------------------------
// Problem constants
// ---------------------------------------------------------------------------
#define N_NODES_MAX 20000
#define D1 128
#define D2 64
#define D3 128
#define D4 64
#define NCLS 10

// ---------------------------------------------------------------------------
// Scratch (static device globals; no allocations anywhere)
// ---------------------------------------------------------------------------
__device__ float g_XR [N_NODES_MAX * D1];  // x @ W1_rel
__device__ float g_H1 [N_NODES_MAX * D1];  // x @ W1_root + b1  (+= scatter)
__device__ float g_XR2[N_NODES_MAX * D2];  // relu(H1) @ W2_rel
__device__ float g_H2 [N_NODES_MAX * D2];  // relu(H1) @ W2_root + b2 (+= scatter)
__device__ float g_H3 [N_NODES_MAX * D3];  // relu(H2 @ L1w + L1b)

// ---------------------------------------------------------------------------
// Generic tiled SGEMM, dual-output via blockIdx.z.
//   z==0: C0 = f(A) @ W0 (+bias0) ; z==1: C1 = f(A) @ W1 (+bias1)
// f = relu if RELU_IN. BN == N (full width). TM must be 4, TN in {4,8}.
// ---------------------------------------------------------------------------
template<int BM, int BN, int BK, int TM, int TN, bool RELU_IN, bool RELU_OUT>
__global__ void __launch_bounds__((BM/TM)*(BN/TN))
gemm_kernel(const float* __restrict__ A,
            const float* __restrict__ W0, const float* __restrict__ W1,
            const float* __restrict__ bias0, const float* __restrict__ bias1,
            float* __restrict__ C0, float* __restrict__ C1,
            int M, int K)
{
    static_assert(TM == 4 && (TN % 4) == 0, "tile config");
    constexpr int T = (BM / TM) * (BN / TN);
    constexpr int N = BN;
    constexpr int PAD = 4;

    const float* __restrict__ W    = blockIdx.z ? W1 : W0;
    const float* __restrict__ bias = blockIdx.z ? bias1 : bias0;
    float* __restrict__       C    = blockIdx.z ? C1 : C0;

    __shared__ float As[BK][BM + PAD];
    __shared__ float Ws[BK][BN];

    const int tid = threadIdx.x;
    const int tx  = tid % (BN / TN);
    const int ty  = tid / (BN / TN);
    const int rowBase = blockIdx.x * BM;

    float acc[TM][TN];
    #pragma unroll
    for (int i = 0; i < TM; i++)
        #pragma unroll
        for (int j = 0; j < TN; j++) acc[i][j] = 0.f;

    for (int k0 = 0; k0 < K; k0 += BK) {
        // --- A tile (transposed into As[k][row]) ---
        constexpr int A_F4 = BM * BK / 4;
        constexpr int A_IT = A_F4 / T;
        #pragma unroll
        for (int it = 0; it < A_IT; it++) {
            int i  = tid + it * T;
            int r  = i / (BK / 4);
            int c4 = i % (BK / 4);
            float4 v = make_float4(0.f, 0.f, 0.f, 0.f);
            int gr = rowBase + r;
            if (gr < M)
                v = *(const float4*)(A + (size_t)gr * K + k0 + c4 * 4);
            if (RELU_IN) {
                v.x = fmaxf(v.x, 0.f); v.y = fmaxf(v.y, 0.f);
                v.z = fmaxf(v.z, 0.f); v.w = fmaxf(v.w, 0.f);
            }
            As[c4 * 4 + 0][r] = v.x;
            As[c4 * 4 + 1][r] = v.y;
            As[c4 * 4 + 2][r] = v.z;
            As[c4 * 4 + 3][r] = v.w;
        }
        // --- W tile ---
        constexpr int W_F4 = BK * BN / 4;
        constexpr int W_IT = W_F4 / T;
        #pragma unroll
        for (int it = 0; it < W_IT; it++) {
            int i  = tid + it * T;
            int r  = i / (BN / 4);
            int c4 = i % (BN / 4);
            *(float4*)&Ws[r][c4 * 4] =
                *(const float4*)(W + (size_t)(k0 + r) * N + c4 * 4);
        }
        __syncthreads();

        #pragma unroll 8
        for (int k = 0; k < BK; k++) {
            float ra[TM], rb[TN];
            *(float4*)ra = *(const float4*)&As[k][ty * TM];
            #pragma unroll
            for (int jj = 0; jj < TN / 4; jj++)
                *(float4*)&rb[jj * 4] = *(const float4*)&Ws[k][tx * TN + jj * 4];
            #pragma unroll
            for (int i = 0; i < TM; i++)
                #pragma unroll
                for (int j = 0; j < TN; j++)
                    acc[i][j] = fmaf(ra[i], rb[j], acc[i][j]);
        }
        __syncthreads();
    }

    // --- epilogue (float4 stores) ---
    #pragma unroll
    for (int i = 0; i < TM; i++) {
        int gr = rowBase + ty * TM + i;
        if (gr >= M) continue;
        #pragma unroll
        for (int jj = 0; jj < TN / 4; jj++) {
            int col = tx * TN + jj * 4;
            float4 v;
            v.x = acc[i][jj*4+0]; v.y = acc[i][jj*4+1];
            v.z = acc[i][jj*4+2]; v.w = acc[i][jj*4+3];
            if (bias) {
                v.x += bias[col+0]; v.y += bias[col+1];
                v.z += bias[col+2]; v.w += bias[col+3];
            }
            if (RELU_OUT) {
                v.x = fmaxf(v.x, 0.f); v.y = fmaxf(v.y, 0.f);
                v.z = fmaxf(v.z, 0.f); v.w = fmaxf(v.w, 0.f);
            }
            *(float4*)(C + (size_t)gr * N + col) = v;
        }
    }
}

// ---------------------------------------------------------------------------
// Edge scatter: dst_feat[dst] += src_feat[src]. One warp per edge.
// edge_index is int32.
// ---------------------------------------------------------------------------
template<int F>
__global__ void scatter_add_kernel(const float* __restrict__ src_feat,
                                   float* __restrict__ dst_feat,
                                   const int* __restrict__ ei,
                                   int nEdges)
{
    int e = blockIdx.x * (blockDim.x >> 5) + (threadIdx.x >> 5);
    if (e >= nEdges) return;
    int lane = threadIdx.x & 31;

    int s = ei[e];
    int d = ei[nEdges + e];

    if (F == 128) {
        const float4 v = *(const float4*)(src_feat + (size_t)s * 128 + lane * 4);
        float* dp = dst_feat + (size_t)d * 128 + lane * 4;
        asm volatile("red.global.add.v4.f32 [%0], {%1,%2,%3,%4};"
                     :: "l"(dp), "f"(v.x), "f"(v.y), "f"(v.z), "f"(v.w)
                     : "memory");
    } else { // F == 64
        const float2 v = *(const float2*)(src_feat + (size_t)s * 64 + lane * 2);
        float* dp = dst_feat + (size_t)d * 64 + lane * 2;
        asm volatile("red.global.add.v2.f32 [%0], {%1,%2};"
                     :: "l"(dp), "f"(v.x), "f"(v.y)
                     : "memory");
    }
}

// ---------------------------------------------------------------------------
// Fused mlp2 + head:
//   H4 = relu(H3 @ L2w + L2b)   (GEMM tile, staged in smem)
//   out = log_softmax(H4 @ L3w + b3)
// BM=64, N=64, K=128. 256 threads. Phase 2: warp w handles rows w*8..w*8+7.
// ---------------------------------------------------------------------------
__global__ void __launch_bounds__(256)
mlp2_head_kernel(const float* __restrict__ A,   // H3 [M,128]
                 const float* __restrict__ W,   // L2w [128,64]
                 const float* __restrict__ b,   // L2b [64]
                 const float* __restrict__ W3,  // L3w [64,10]
                 const float* __restrict__ b3,  // [10]
                 float* __restrict__ out, int M)
{
    constexpr int BM = 64, BN = 64, BK = 32, TM = 4, TN = 4;
    constexpr int K = 128;
    constexpr int T = 256;
    constexpr int PAD = 4;

    __shared__ float As[BK][BM + PAD];
    __shared__ float Ws[BK][BN];
    __shared__ float Ct[BM][BN + PAD];
    __shared__ float W3s[D4 * NCLS];
    __shared__ float b3s[NCLS];

    const int tid = threadIdx.x;
    const int tx  = tid % (BN / TN);
    const int ty  = tid / (BN / TN);
    const int rowBase = blockIdx.x * BM;

    // preload head weights (covered by first __syncthreads below)
    for (int i = tid; i < D4 * NCLS; i += T) W3s[i] = W3[i];
    if (tid < NCLS) b3s[tid] = b3[tid];

    float acc[TM][TN];
    #pragma unroll
    for (int i = 0; i < TM; i++)
        #pragma unroll
        for (int j = 0; j < TN; j++) acc[i][j] = 0.f;

    for (int k0 = 0; k0 < K; k0 += BK) {
        constexpr int A_IT = BM * BK / 4 / T;
        #pragma unroll
        for (int it = 0; it < A_IT; it++) {
            int i  = tid + it * T;
            int r  = i / (BK / 4);
            int c4 = i % (BK / 4);
            float4 v = make_float4(0.f, 0.f, 0.f, 0.f);
            int gr = rowBase + r;
            if (gr < M)
                v = *(const float4*)(A + (size_t)gr * K + k0 + c4 * 4);
            As[c4 * 4 + 0][r] = v.x;
            As[c4 * 4 + 1][r] = v.y;
            As[c4 * 4 + 2][r] = v.z;
            As[c4 * 4 + 3][r] = v.w;
        }
        constexpr int W_IT = BK * BN / 4 / T;
        #pragma unroll
        for (int it = 0; it < W_IT; it++) {
            int i  = tid + it * T;
            int r  = i / (BN / 4);
            int c4 = i % (BN / 4);
            *(float4*)&Ws[r][c4 * 4] =
                *(const float4*)(W + (size_t)(k0 + r) * BN + c4 * 4);
        }
        __syncthreads();

        #pragma unroll 8
        for (int k = 0; k < BK; k++) {
            float ra[TM], rb[TN];
            *(float4*)ra = *(const float4*)&As[k][ty * TM];
            *(float4*)rb = *(const float4*)&Ws[k][tx * TN];
            #pragma unroll
            for (int i = 0; i < TM; i++)
                #pragma unroll
                for (int j = 0; j < TN; j++)
                    acc[i][j] = fmaf(ra[i], rb[j], acc[i][j]);
        }
        __syncthreads();
    }

    // epilogue: bias + relu -> Ct
    #pragma unroll
    for (int i = 0; i < TM; i++) {
        int r = ty * TM + i;
        #pragma unroll
        for (int j = 0; j < TN; j++) {
            int col = tx * TN + j;
            Ct[r][col] = fmaxf(acc[i][j] + b[col], 0.f);
        }
    }
    __syncthreads();

    // phase 2: per-warp head + log_softmax
    int warp = tid >> 5;
    int lane = tid & 31;
    #pragma unroll
    for (int rr = 0; rr < 8; rr++) {
        int r  = warp * 8 + rr;
        int gr = rowBase + r;
        if (gr >= M) continue;

        float acc2 = -1e30f;
        if (lane < NCLS) {
            acc2 = b3s[lane];
            #pragma unroll 8
            for (int k = 0; k < D4; k++)
                acc2 = fmaf(Ct[r][k], W3s[k * NCLS + lane], acc2);
        }
        float m = acc2;
        #pragma unroll
        for (int o = 16; o > 0; o >>= 1)
            m = fmaxf(m, __shfl_xor_sync(0xffffffffu, m, o));
        float ex = (lane < NCLS) ? expf(acc2 - m) : 0.f;
        float ssum = ex;
        #pragma unroll
        for (int o = 16; o > 0; o >>= 1)
            ssum += __shfl_xor_sync(0xffffffffu, ssum, o);
        float lse = m + logf(ssum);
        if (lane < NCLS)
            out[(size_t)gr * NCLS + lane] = acc2 - lse;
    }
}

// ---------------------------------------------------------------------------
// Launch
// ---------------------------------------------------------------------------
extern "C" void kernel_launch(void* const* d_in, const int* in_sizes, int n_in,
                              void* d_out, int out_size)
{
    const float* x      = (const float*)d_in[0];
    const int*   ei     = (const int*)d_in[1];     // int32 edge_index [2, E]
    const float* W1_rel = (const float*)d_in[2];
    const float* W1_rt  = (const float*)d_in[3];
    const float* b1     = (const float*)d_in[4];
    const float* W2_rel = (const float*)d_in[5];
    const float* W2_rt  = (const float*)d_in[6];
    const float* b2     = (const float*)d_in[7];
    const float* L1w    = (const float*)d_in[8];
    const float* L1b    = (const float*)d_in[9];
    const float* L2w    = (const float*)d_in[10];
    const float* L2b    = (const float*)d_in[11];
    const float* L3w    = (const float*)d_in[12];
    const float* L3b    = (const float*)d_in[13];
    float*       out    = (float*)d_out;

    const int DIN = 256;
    const int M   = in_sizes[0] / DIN;       // 20000
    const int nE  = in_sizes[1] / 2;         // 320000

    float *XR, *H1, *XR2, *H2, *H3;
    cudaGetSymbolAddress((void**)&XR,  g_XR);
    cudaGetSymbolAddress((void**)&H1,  g_H1);
    cudaGetSymbolAddress((void**)&XR2, g_XR2);
    cudaGetSymbolAddress((void**)&H2,  g_H2);
    cudaGetSymbolAddress((void**)&H3,  g_H3);

    const int gM64 = (M + 63) / 64;

    // conv1 (dual): XR = x@W1_rel ; H1 = x@W1_root + b1
    gemm_kernel<64,128,32,4,8,false,false>
        <<<dim3(gM64,1,2), 256>>>(x, W1_rel, W1_rt, nullptr, b1, XR, H1, M, DIN);

    // H1[dst] += XR[src]
    {
        int blks = (nE + 7) / 8;
        scatter_add_kernel<128><<<blks, 8 * 32>>>(XR, H1, ei, nE);
    }

    // conv2 (dual, relu on input): XR2 = relu(H1)@W2_rel ; H2 = relu(H1)@W2_root + b2
    gemm_kernel<64,64,32,4,4,true,false>
        <<<dim3(gM64,1,2), 256>>>(H1, W2_rel, W2_rt, nullptr, b2, XR2, H2, M, D1);

    // H2[dst] += XR2[src]
    {
        int blks = (nE + 7) / 8;
        scatter_add_kernel<64><<<blks, 8 * 32>>>(XR2, H2, ei, nE);
    }

    // mlp1: H3 = relu(H2 @ L1w + L1b)
    gemm_kernel<64,128,32,4,8,false,true>
        <<<dim3(gM64,1,1), 256>>>(H2, L1w, nullptr, L1b, nullptr, H3, nullptr, M, D2);

    // mlp2 + head fused
    mlp2_head_kernel<<<gM64, 256>>>(H3, L2w, L2b, L3w, L3b, out, M);
}

// round 5
// speedup vs baseline: 1.2916x; 1.0003x over previous
#include <cuda_runtime.h>
#include <cuda_bf16.h>
#include <math.h>

// ---------------------------------------------------------------------------
// Problem constants
// ---------------------------------------------------------------------------
#define N_NODES_MAX 20000
#define D1 128
#define D2 64
#define D3 128
#define D4 64
#define NCLS 10

// ---------------------------------------------------------------------------
// Scratch (static device globals; no allocations anywhere)
// ---------------------------------------------------------------------------
__device__ float g_XR [N_NODES_MAX * D1];  // x @ W1_rel
__device__ float g_H1 [N_NODES_MAX * D1];  // x @ W1_root + b1  (+= scatter)
__device__ float g_XR2[N_NODES_MAX * D2];  // relu(H1) @ W2_rel
__device__ float g_H2 [N_NODES_MAX * D2];  // relu(H1) @ W2_root + b2 (+= scatter)
__device__ float g_H3 [N_NODES_MAX * D3];  // relu(H2 @ L1w + L1b)

// ---------------------------------------------------------------------------
// Generic tiled SGEMM, dual-output via blockIdx.z.
//   z==0: C0 = f(A) @ W0 (+bias0) ; z==1: C1 = f(A) @ W1 (+bias1)
// f = relu if RELU_IN. BN == N (full width).
// ---------------------------------------------------------------------------
template<int BM, int BN, int BK, int TM, int TN, bool RELU_IN, bool RELU_OUT>
__global__ void __launch_bounds__((BM/TM)*(BN/TN))
gemm_kernel(const float* __restrict__ A,
            const float* __restrict__ W0, const float* __restrict__ W1,
            const float* __restrict__ bias0, const float* __restrict__ bias1,
            float* __restrict__ C0, float* __restrict__ C1,
            int M, int K)
{
    static_assert(TM == 4 && (TN % 4) == 0, "tile config");
    constexpr int T = (BM / TM) * (BN / TN);
    constexpr int N = BN;
    constexpr int PAD = 4;

    const float* __restrict__ W    = blockIdx.z ? W1 : W0;
    const float* __restrict__ bias = blockIdx.z ? bias1 : bias0;
    float* __restrict__       C    = blockIdx.z ? C1 : C0;

    __shared__ float As[BK][BM + PAD];
    __shared__ float Ws[BK][BN];

    const int tid = threadIdx.x;
    const int tx  = tid % (BN / TN);
    const int ty  = tid / (BN / TN);
    const int rowBase = blockIdx.x * BM;

    float acc[TM][TN];
    #pragma unroll
    for (int i = 0; i < TM; i++)
        #pragma unroll
        for (int j = 0; j < TN; j++) acc[i][j] = 0.f;

    for (int k0 = 0; k0 < K; k0 += BK) {
        // --- A tile (transposed into As[k][row]) ---
        constexpr int A_F4 = BM * BK / 4;
        constexpr int A_IT = A_F4 / T;
        #pragma unroll
        for (int it = 0; it < A_IT; it++) {
            int i  = tid + it * T;
            int r  = i / (BK / 4);
            int c4 = i % (BK / 4);
            float4 v = make_float4(0.f, 0.f, 0.f, 0.f);
            int gr = rowBase + r;
            if (gr < M)
                v = *(const float4*)(A + (size_t)gr * K + k0 + c4 * 4);
            if (RELU_IN) {
                v.x = fmaxf(v.x, 0.f); v.y = fmaxf(v.y, 0.f);
                v.z = fmaxf(v.z, 0.f); v.w = fmaxf(v.w, 0.f);
            }
            As[c4 * 4 + 0][r] = v.x;
            As[c4 * 4 + 1][r] = v.y;
            As[c4 * 4 + 2][r] = v.z;
            As[c4 * 4 + 3][r] = v.w;
        }
        // --- W tile ---
        constexpr int W_F4 = BK * BN / 4;
        constexpr int W_IT = W_F4 / T;
        #pragma unroll
        for (int it = 0; it < W_IT; it++) {
            int i  = tid + it * T;
            int r  = i / (BN / 4);
            int c4 = i % (BN / 4);
            *(float4*)&Ws[r][c4 * 4] =
                *(const float4*)(W + (size_t)(k0 + r) * N + c4 * 4);
        }
        __syncthreads();

        #pragma unroll 8
        for (int k = 0; k < BK; k++) {
            float ra[TM], rb[TN];
            *(float4*)ra = *(const float4*)&As[k][ty * TM];
            #pragma unroll
            for (int jj = 0; jj < TN / 4; jj++)
                *(float4*)&rb[jj * 4] = *(const float4*)&Ws[k][tx * TN + jj * 4];
            #pragma unroll
            for (int i = 0; i < TM; i++)
                #pragma unroll
                for (int j = 0; j < TN; j++)
                    acc[i][j] = fmaf(ra[i], rb[j], acc[i][j]);
        }
        __syncthreads();
    }

    // --- epilogue (float4 stores) ---
    #pragma unroll
    for (int i = 0; i < TM; i++) {
        int gr = rowBase + ty * TM + i;
        if (gr >= M) continue;
        #pragma unroll
        for (int jj = 0; jj < TN / 4; jj++) {
            int col = tx * TN + jj * 4;
            float4 v;
            v.x = acc[i][jj*4+0]; v.y = acc[i][jj*4+1];
            v.z = acc[i][jj*4+2]; v.w = acc[i][jj*4+3];
            if (bias) {
                v.x += bias[col+0]; v.y += bias[col+1];
                v.z += bias[col+2]; v.w += bias[col+3];
            }
            if (RELU_OUT) {
                v.x = fmaxf(v.x, 0.f); v.y = fmaxf(v.y, 0.f);
                v.z = fmaxf(v.z, 0.f); v.w = fmaxf(v.w, 0.f);
            }
            *(float4*)(C + (size_t)gr * N + col) = v;
        }
    }
}

// ---------------------------------------------------------------------------
// Batched edge scatter, F=128: 8 edges per warp (full warp per edge, float4).
// Indices fetched warp-wide then shfl-broadcast; 8 independent gathers in
// flight (MLP=8) before the 8 reductions.
// ---------------------------------------------------------------------------
__global__ void __launch_bounds__(256)
scatter_add128_kernel(const float* __restrict__ src_feat,
                      float* __restrict__ dst_feat,
                      const int* __restrict__ ei, int nEdges)
{
    const int w    = blockIdx.x * (blockDim.x >> 5) + (threadIdx.x >> 5);
    const int lane = threadIdx.x & 31;
    const int eb   = w * 8;
    if (eb >= nEdges) return;
    const int n = min(8, nEdges - eb);

    int idx = 0;
    if (lane < 8) {
        if (lane < n) idx = ei[eb + lane];
    } else if (lane < 16) {
        if (lane - 8 < n) idx = ei[nEdges + eb + (lane - 8)];
    }

    float4 v[8];
    #pragma unroll
    for (int i = 0; i < 8; i++) {
        int s = __shfl_sync(0xffffffffu, idx, i);
        if (i < n)
            v[i] = *(const float4*)(src_feat + (size_t)s * 128 + lane * 4);
    }
    #pragma unroll
    for (int i = 0; i < 8; i++) {
        int d = __shfl_sync(0xffffffffu, idx, 8 + i);
        if (i < n) {
            float* dp = dst_feat + (size_t)d * 128 + lane * 4;
            asm volatile("red.global.add.v4.f32 [%0], {%1,%2,%3,%4};"
                         :: "l"(dp), "f"(v[i].x), "f"(v[i].y), "f"(v[i].z), "f"(v[i].w)
                         : "memory");
        }
    }
}

// ---------------------------------------------------------------------------
// Batched edge scatter, F=64: 16 edges per warp (half-warp per edge, float4).
// ---------------------------------------------------------------------------
__global__ void __launch_bounds__(256)
scatter_add64_kernel(const float* __restrict__ src_feat,
                     float* __restrict__ dst_feat,
                     const int* __restrict__ ei, int nEdges)
{
    const int w    = blockIdx.x * (blockDim.x >> 5) + (threadIdx.x >> 5);
    const int lane = threadIdx.x & 31;
    const int eb   = w * 16;
    if (eb >= nEdges) return;
    const int n    = min(16, nEdges - eb);
    const int half = lane >> 4;     // which edge of the pair
    const int sub  = lane & 15;     // 16 lanes x float4 = 64 floats

    int idx = 0;
    if (lane < 16) {
        if (lane < n) idx = ei[eb + lane];
    } else {
        if (lane - 16 < n) idx = ei[nEdges + eb + (lane - 16)];
    }

    float4 v[8];
    #pragma unroll
    for (int it = 0; it < 8; it++) {
        int e = it * 2 + half;
        int s = __shfl_sync(0xffffffffu, idx, e);
        if (e < n)
            v[it] = *(const float4*)(src_feat + (size_t)s * 64 + sub * 4);
    }
    #pragma unroll
    for (int it = 0; it < 8; it++) {
        int e = it * 2 + half;
        int d = __shfl_sync(0xffffffffu, idx, 16 + e);
        if (e < n) {
            float* dp = dst_feat + (size_t)d * 64 + sub * 4;
            asm volatile("red.global.add.v4.f32 [%0], {%1,%2,%3,%4};"
                         :: "l"(dp), "f"(v[it].x), "f"(v[it].y), "f"(v[it].z), "f"(v[it].w)
                         : "memory");
        }
    }
}

// ---------------------------------------------------------------------------
// Fused mlp2 + head:
//   H4 = relu(H3 @ L2w + L2b)   (GEMM tile, staged in smem)
//   out = log_softmax(H4 @ L3w + b3)
// ---------------------------------------------------------------------------
__global__ void __launch_bounds__(256)
mlp2_head_kernel(const float* __restrict__ A,   // H3 [M,128]
                 const float* __restrict__ W,   // L2w [128,64]
                 const float* __restrict__ b,   // L2b [64]
                 const float* __restrict__ W3,  // L3w [64,10]
                 const float* __restrict__ b3,  // [10]
                 float* __restrict__ out, int M)
{
    constexpr int BM = 64, BN = 64, BK = 32, TM = 4, TN = 4;
    constexpr int K = 128;
    constexpr int T = 256;
    constexpr int PAD = 4;

    __shared__ float As[BK][BM + PAD];
    __shared__ float Ws[BK][BN];
    __shared__ float Ct[BM][BN + PAD];
    __shared__ float W3s[D4 * NCLS];
    __shared__ float b3s[NCLS];

    const int tid = threadIdx.x;
    const int tx  = tid % (BN / TN);
    const int ty  = tid / (BN / TN);
    const int rowBase = blockIdx.x * BM;

    for (int i = tid; i < D4 * NCLS; i += T) W3s[i] = W3[i];
    if (tid < NCLS) b3s[tid] = b3[tid];

    float acc[TM][TN];
    #pragma unroll
    for (int i = 0; i < TM; i++)
        #pragma unroll
        for (int j = 0; j < TN; j++) acc[i][j] = 0.f;

    for (int k0 = 0; k0 < K; k0 += BK) {
        constexpr int A_IT = BM * BK / 4 / T;
        #pragma unroll
        for (int it = 0; it < A_IT; it++) {
            int i  = tid + it * T;
            int r  = i / (BK / 4);
            int c4 = i % (BK / 4);
            float4 v = make_float4(0.f, 0.f, 0.f, 0.f);
            int gr = rowBase + r;
            if (gr < M)
                v = *(const float4*)(A + (size_t)gr * K + k0 + c4 * 4);
            As[c4 * 4 + 0][r] = v.x;
            As[c4 * 4 + 1][r] = v.y;
            As[c4 * 4 + 2][r] = v.z;
            As[c4 * 4 + 3][r] = v.w;
        }
        constexpr int W_IT = BK * BN / 4 / T;
        #pragma unroll
        for (int it = 0; it < W_IT; it++) {
            int i  = tid + it * T;
            int r  = i / (BN / 4);
            int c4 = i % (BN / 4);
            *(float4*)&Ws[r][c4 * 4] =
                *(const float4*)(W + (size_t)(k0 + r) * BN + c4 * 4);
        }
        __syncthreads();

        #pragma unroll 8
        for (int k = 0; k < BK; k++) {
            float ra[TM], rb[TN];
            *(float4*)ra = *(const float4*)&As[k][ty * TM];
            *(float4*)rb = *(const float4*)&Ws[k][tx * TN];
            #pragma unroll
            for (int i = 0; i < TM; i++)
                #pragma unroll
                for (int j = 0; j < TN; j++)
                    acc[i][j] = fmaf(ra[i], rb[j], acc[i][j]);
        }
        __syncthreads();
    }

    #pragma unroll
    for (int i = 0; i < TM; i++) {
        int r = ty * TM + i;
        #pragma unroll
        for (int j = 0; j < TN; j++) {
            int col = tx * TN + j;
            Ct[r][col] = fmaxf(acc[i][j] + b[col], 0.f);
        }
    }
    __syncthreads();

    int warp = tid >> 5;
    int lane = tid & 31;
    #pragma unroll
    for (int rr = 0; rr < 8; rr++) {
        int r  = warp * 8 + rr;
        int gr = rowBase + r;
        if (gr >= M) continue;

        float acc2 = -1e30f;
        if (lane < NCLS) {
            acc2 = b3s[lane];
            #pragma unroll 8
            for (int k = 0; k < D4; k++)
                acc2 = fmaf(Ct[r][k], W3s[k * NCLS + lane], acc2);
        }
        float m = acc2;
        #pragma unroll
        for (int o = 16; o > 0; o >>= 1)
            m = fmaxf(m, __shfl_xor_sync(0xffffffffu, m, o));
        float ex = (lane < NCLS) ? expf(acc2 - m) : 0.f;
        float ssum = ex;
        #pragma unroll
        for (int o = 16; o > 0; o >>= 1)
            ssum += __shfl_xor_sync(0xffffffffu, ssum, o);
        float lse = m + logf(ssum);
        if (lane < NCLS)
            out[(size_t)gr * NCLS + lane] = acc2 - lse;
    }
}

// ---------------------------------------------------------------------------
// Launch
// ---------------------------------------------------------------------------
extern "C" void kernel_launch(void* const* d_in, const int* in_sizes, int n_in,
                              void* d_out, int out_size)
{
    const float* x      = (const float*)d_in[0];
    const int*   ei     = (const int*)d_in[1];     // int32 edge_index [2, E]
    const float* W1_rel = (const float*)d_in[2];
    const float* W1_rt  = (const float*)d_in[3];
    const float* b1     = (const float*)d_in[4];
    const float* W2_rel = (const float*)d_in[5];
    const float* W2_rt  = (const float*)d_in[6];
    const float* b2     = (const float*)d_in[7];
    const float* L1w    = (const float*)d_in[8];
    const float* L1b    = (const float*)d_in[9];
    const float* L2w    = (const float*)d_in[10];
    const float* L2b    = (const float*)d_in[11];
    const float* L3w    = (const float*)d_in[12];
    const float* L3b    = (const float*)d_in[13];
    float*       out    = (float*)d_out;

    const int DIN = 256;
    const int M   = in_sizes[0] / DIN;       // 20000
    const int nE  = in_sizes[1] / 2;         // 320000

    float *XR, *H1, *XR2, *H2, *H3;
    cudaGetSymbolAddress((void**)&XR,  g_XR);
    cudaGetSymbolAddress((void**)&H1,  g_H1);
    cudaGetSymbolAddress((void**)&XR2, g_XR2);
    cudaGetSymbolAddress((void**)&H2,  g_H2);
    cudaGetSymbolAddress((void**)&H3,  g_H3);

    const int gM64 = (M + 63) / 64;

    // conv1 (dual): XR = x@W1_rel ; H1 = x@W1_root + b1
    gemm_kernel<64,128,32,4,8,false,false>
        <<<dim3(gM64,1,2), 256>>>(x, W1_rel, W1_rt, nullptr, b1, XR, H1, M, DIN);

    // H1[dst] += XR[src]  (8 edges per warp)
    {
        int warps = (nE + 7) / 8;
        int blks  = (warps + 7) / 8;
        scatter_add128_kernel<<<blks, 256>>>(XR, H1, ei, nE);
    }

    // conv2 (dual, relu on input): XR2 = relu(H1)@W2_rel ; H2 = relu(H1)@W2_root + b2
    gemm_kernel<64,64,32,4,8,true,false>
        <<<dim3(gM64,1,2), 128>>>(H1, W2_rel, W2_rt, nullptr, b2, XR2, H2, M, D1);

    // H2[dst] += XR2[src]  (16 edges per warp)
    {
        int warps = (nE + 15) / 16;
        int blks  = (warps + 7) / 8;
        scatter_add64_kernel<<<blks, 256>>>(XR2, H2, ei, nE);
    }

    // mlp1: H3 = relu(H2 @ L1w + L1b)
    gemm_kernel<64,128,32,4,8,false,true>
        <<<dim3(gM64,1,1), 256>>>(H2, L1w, nullptr, L1b, nullptr, H3, nullptr, M, D2);

    // mlp2 + head fused
    mlp2_head_kernel<<<gM64, 256>>>(H3, L2w, L2b, L3w, L3b, out, M);
}

// round 8
// speedup vs baseline: 1.7317x; 1.3408x over previous
#include <cuda_runtime.h>
#include <cuda_bf16.h>
#include <math.h>
#include <stdint.h>

// ---------------------------------------------------------------------------
// Problem constants
// ---------------------------------------------------------------------------
#define N_NODES_MAX 20000
#define DIN 256
#define D1 128
#define D2 64
#define D3 128
#define D4 64
#define NCLS 10

// ---------------------------------------------------------------------------
// Scratch (static device globals; no allocations anywhere)
// ---------------------------------------------------------------------------
__device__ float g_XR [N_NODES_MAX * D1];
__device__ float g_H1 [N_NODES_MAX * D1];
__device__ float g_XR2[N_NODES_MAX * D2];
__device__ float g_H2 [N_NODES_MAX * D2];
__device__ float g_H3 [N_NODES_MAX * D3];

// bf16 split operands for conv1 tensor-core GEMM
__device__ __nv_bfloat16 g_Ahi[N_NODES_MAX * DIN];
__device__ __nv_bfloat16 g_Alo[N_NODES_MAX * DIN];
// weights transposed to [n][k] K-major: slot 0 = W1_rel, slot 1 = W1_root
__device__ __nv_bfloat16 g_Bhi[2 * D1 * DIN];
__device__ __nv_bfloat16 g_Blo[2 * D1 * DIN];

// ---------------------------------------------------------------------------
// mma.sync helpers (sm_80+ baseline ISA; compiles for plain compute_100)
// ---------------------------------------------------------------------------
__device__ __forceinline__ uint32_t smem_u32(const void* p) {
    uint32_t a;
    asm("{ .reg .u64 t; cvta.to.shared.u64 t, %1; cvt.u32.u64 %0, t; }"
        : "=r"(a) : "l"(p));
    return a;
}
__device__ __forceinline__ void ldsm_x4(uint32_t& r0, uint32_t& r1,
                                        uint32_t& r2, uint32_t& r3,
                                        uint32_t addr) {
    asm volatile("ldmatrix.sync.aligned.m8n8.x4.shared.b16 {%0,%1,%2,%3}, [%4];"
                 : "=r"(r0), "=r"(r1), "=r"(r2), "=r"(r3) : "r"(addr));
}
__device__ __forceinline__ void mma_bf16(float& c0, float& c1, float& c2, float& c3,
                                         uint32_t a0, uint32_t a1, uint32_t a2, uint32_t a3,
                                         uint32_t b0, uint32_t b1) {
    asm volatile(
        "mma.sync.aligned.m16n8k16.row.col.f32.bf16.bf16.f32 "
        "{%0,%1,%2,%3}, {%4,%5,%6,%7}, {%8,%9}, {%0,%1,%2,%3};"
        : "+f"(c0), "+f"(c1), "+f"(c2), "+f"(c3)
        : "r"(a0), "r"(a1), "r"(a2), "r"(a3), "r"(b0), "r"(b1));
}

// ---------------------------------------------------------------------------
// Prep kernels: fp32 -> bf16 hi/lo split
// ---------------------------------------------------------------------------
__global__ void prep_x_kernel(const float* __restrict__ x, int n4)
{
    int i = blockIdx.x * blockDim.x + threadIdx.x;
    if (i >= n4) return;
    float4 v = *(const float4*)(x + (size_t)i * 4);
    __nv_bfloat16 h[4], l[4];
    float f[4] = {v.x, v.y, v.z, v.w};
    #pragma unroll
    for (int j = 0; j < 4; j++) {
        h[j] = __float2bfloat16(f[j]);
        l[j] = __float2bfloat16(f[j] - __bfloat162float(h[j]));
    }
    *(uint2*)(g_Ahi + (size_t)i * 4) = *(uint2*)h;
    *(uint2*)(g_Alo + (size_t)i * 4) = *(uint2*)l;
}

__global__ void prep_w_kernel(const float* __restrict__ Wrel,
                              const float* __restrict__ Wroot)
{
    int idx = blockIdx.x * blockDim.x + threadIdx.x;   // over 2*256*128
    if (idx >= 2 * DIN * D1) return;
    int w   = idx / (DIN * D1);
    int rem = idx % (DIN * D1);
    int k   = rem / D1;
    int n   = rem % D1;
    float f = (w ? Wroot : Wrel)[k * D1 + n];
    __nv_bfloat16 h = __float2bfloat16(f);
    __nv_bfloat16 l = __float2bfloat16(f - __bfloat162float(h));
    g_Bhi[(size_t)w * D1 * DIN + (size_t)n * DIN + k] = h;
    g_Blo[(size_t)w * D1 * DIN + (size_t)n * DIN + k] = l;
}

// ---------------------------------------------------------------------------
// conv1 via mma.sync bf16 split:
//   blockIdx.y==0: XR = x @ W1_rel            (no bias)
//   blockIdx.y==1: H1 = x @ W1_root + b1
// Block: 256 thr = 8 warps (2x4), tile M128 x N128, K chunks of 32.
// Terms: Ah*Bh + Ah*Bl + Al*Bh (fp32 accum).
// smem rows are 64B (32 bf16); 16B-granule XOR swizzle (2-way conflicts ok).
// ---------------------------------------------------------------------------
#define C1_SM_AH 0
#define C1_SM_AL 8192
#define C1_SM_BH 16384
#define C1_SM_BL 24576

__global__ void __launch_bounds__(256)
conv1_mma_kernel(const float* __restrict__ b1, int M)
{
    __shared__ char smem[32768];
    const uint32_t sbase = smem_u32(smem);

    const int tid  = threadIdx.x;
    const int wid  = tid >> 5;
    const int lane = tid & 31;
    const int rowBase = blockIdx.x * 128;
    const int out  = blockIdx.y;

    const __nv_bfloat16* __restrict__ Bh = g_Bhi + (size_t)out * D1 * DIN;
    const __nv_bfloat16* __restrict__ Bl = g_Blo + (size_t)out * D1 * DIN;

    const int mBase = (wid >> 2) * 64;   // 0 or 64
    const int nBase = (wid & 3) * 32;    // 0,32,64,96

    // ldmatrix lane roles
    const int qr    = lane & 7;
    const int half1 = (lane >> 3) & 1;
    const int half2 = (lane >> 4) & 1;

    float c[4][4][4];
    #pragma unroll
    for (int i = 0; i < 4; i++)
        #pragma unroll
        for (int j = 0; j < 4; j++)
            #pragma unroll
            for (int q = 0; q < 4; q++) c[i][j][q] = 0.f;

    for (int ch = 0; ch < 8; ch++) {
        const int k0 = ch * 32;
        // ---- stage chunk into smem ----
        #pragma unroll
        for (int it = 0; it < 2; it++) {
            int i  = tid + it * 256;       // 0..511
            int r  = i >> 2;               // 0..127
            int kc = i & 3;                // 16B chunk within 64B row
            uint32_t so = (uint32_t)(r * 64 + ((kc ^ (r & 3)) << 4));
            int gr = rowBase + r;
            uint4 vh = make_uint4(0,0,0,0), vl = vh;
            if (gr < M) {
                vh = *(const uint4*)(g_Ahi + (size_t)gr * DIN + k0 + kc * 8);
                vl = *(const uint4*)(g_Alo + (size_t)gr * DIN + k0 + kc * 8);
            }
            *(uint4*)(smem + C1_SM_AH + so) = vh;
            *(uint4*)(smem + C1_SM_AL + so) = vl;
            uint4 wh = *(const uint4*)(Bh + (size_t)r * DIN + k0 + kc * 8);
            uint4 wl = *(const uint4*)(Bl + (size_t)r * DIN + k0 + kc * 8);
            *(uint4*)(smem + C1_SM_BH + so) = wh;
            *(uint4*)(smem + C1_SM_BL + so) = wl;
        }
        __syncthreads();

        // ---- 2 k16 steps ----
        #pragma unroll
        for (int ks = 0; ks < 2; ks++) {
            const int kk = ks * 16;
            // A fragment addresses: rows mBase+mt*16+qr+half1*8, k = kk+half2*8
            uint32_t ah[4][4], al[4][4];
            #pragma unroll
            for (int mt = 0; mt < 4; mt++) {
                int r  = mBase + mt * 16 + qr + half1 * 8;
                int kA = kk + half2 * 8;
                uint32_t so = (uint32_t)(r * 64 + (((kA >> 3) ^ (r & 3)) << 4));
                ldsm_x4(ah[mt][0], ah[mt][1], ah[mt][2], ah[mt][3],
                        sbase + C1_SM_AH + so);
                ldsm_x4(al[mt][0], al[mt][1], al[mt][2], al[mt][3],
                        sbase + C1_SM_AL + so);
            }
            // B fragments: n rows nBase+pair*16+qr+half2*8, k = kk+half1*8
            uint32_t bh[2][4], bl[2][4];
            #pragma unroll
            for (int pr = 0; pr < 2; pr++) {
                int r  = nBase + pr * 16 + qr + half2 * 8;
                int kB = kk + half1 * 8;
                uint32_t so = (uint32_t)(r * 64 + (((kB >> 3) ^ (r & 3)) << 4));
                ldsm_x4(bh[pr][0], bh[pr][1], bh[pr][2], bh[pr][3],
                        sbase + C1_SM_BH + so);
                ldsm_x4(bl[pr][0], bl[pr][1], bl[pr][2], bl[pr][3],
                        sbase + C1_SM_BL + so);
            }
            // ---- mma: 3 terms ----
            #pragma unroll
            for (int mt = 0; mt < 4; mt++) {
                #pragma unroll
                for (int nt = 0; nt < 4; nt++) {
                    uint32_t b0h = bh[nt >> 1][(nt & 1) * 2];
                    uint32_t b1h = bh[nt >> 1][(nt & 1) * 2 + 1];
                    uint32_t b0l = bl[nt >> 1][(nt & 1) * 2];
                    uint32_t b1l = bl[nt >> 1][(nt & 1) * 2 + 1];
                    float* cc = c[mt][nt];
                    mma_bf16(cc[0], cc[1], cc[2], cc[3],
                             ah[mt][0], ah[mt][1], ah[mt][2], ah[mt][3], b0h, b1h);
                    mma_bf16(cc[0], cc[1], cc[2], cc[3],
                             ah[mt][0], ah[mt][1], ah[mt][2], ah[mt][3], b0l, b1l);
                    mma_bf16(cc[0], cc[1], cc[2], cc[3],
                             al[mt][0], al[mt][1], al[mt][2], al[mt][3], b0h, b1h);
                }
            }
        }
        __syncthreads();
    }

    // ---- epilogue ----
    float* __restrict__ dst = out ? g_H1 : g_XR;
    const int gid = lane >> 2;
    const int tig = lane & 3;
    #pragma unroll
    for (int mt = 0; mt < 4; mt++) {
        #pragma unroll
        for (int nt = 0; nt < 4; nt++) {
            int col  = nBase + nt * 8 + tig * 2;
            int row0 = rowBase + mBase + mt * 16 + gid;
            float bx = 0.f, by = 0.f;
            if (out) { bx = b1[col]; by = b1[col + 1]; }
            if (row0 < M) {
                float2 v; v.x = c[mt][nt][0] + bx; v.y = c[mt][nt][1] + by;
                *(float2*)(dst + (size_t)row0 * D1 + col) = v;
            }
            int row1 = row0 + 8;
            if (row1 < M) {
                float2 v; v.x = c[mt][nt][2] + bx; v.y = c[mt][nt][3] + by;
                *(float2*)(dst + (size_t)row1 * D1 + col) = v;
            }
        }
    }
}

// ---------------------------------------------------------------------------
// Generic tiled SGEMM, dual-output via blockIdx.z (fp32 path for small GEMMs)
// ---------------------------------------------------------------------------
template<int BM, int BN, int BK, int TM, int TN, bool RELU_IN, bool RELU_OUT>
__global__ void __launch_bounds__((BM/TM)*(BN/TN))
gemm_kernel(const float* __restrict__ A,
            const float* __restrict__ W0, const float* __restrict__ W1,
            const float* __restrict__ bias0, const float* __restrict__ bias1,
            float* __restrict__ C0, float* __restrict__ C1,
            int M, int K)
{
    static_assert(TM == 4 && (TN % 4) == 0, "tile config");
    constexpr int T = (BM / TM) * (BN / TN);
    constexpr int N = BN;
    constexpr int PAD = 4;

    const float* __restrict__ W    = blockIdx.z ? W1 : W0;
    const float* __restrict__ bias = blockIdx.z ? bias1 : bias0;
    float* __restrict__       C    = blockIdx.z ? C1 : C0;

    __shared__ float As[BK][BM + PAD];
    __shared__ float Ws[BK][BN];

    const int tid = threadIdx.x;
    const int tx  = tid % (BN / TN);
    const int ty  = tid / (BN / TN);
    const int rowBase = blockIdx.x * BM;

    float acc[TM][TN];
    #pragma unroll
    for (int i = 0; i < TM; i++)
        #pragma unroll
        for (int j = 0; j < TN; j++) acc[i][j] = 0.f;

    for (int k0 = 0; k0 < K; k0 += BK) {
        constexpr int A_IT = BM * BK / 4 / T;
        #pragma unroll
        for (int it = 0; it < A_IT; it++) {
            int i  = tid + it * T;
            int r  = i / (BK / 4);
            int c4 = i % (BK / 4);
            float4 v = make_float4(0.f, 0.f, 0.f, 0.f);
            int gr = rowBase + r;
            if (gr < M)
                v = *(const float4*)(A + (size_t)gr * K + k0 + c4 * 4);
            if (RELU_IN) {
                v.x = fmaxf(v.x, 0.f); v.y = fmaxf(v.y, 0.f);
                v.z = fmaxf(v.z, 0.f); v.w = fmaxf(v.w, 0.f);
            }
            As[c4 * 4 + 0][r] = v.x;
            As[c4 * 4 + 1][r] = v.y;
            As[c4 * 4 + 2][r] = v.z;
            As[c4 * 4 + 3][r] = v.w;
        }
        constexpr int W_IT = BK * BN / 4 / T;
        #pragma unroll
        for (int it = 0; it < W_IT; it++) {
            int i  = tid + it * T;
            int r  = i / (BN / 4);
            int c4 = i % (BN / 4);
            *(float4*)&Ws[r][c4 * 4] =
                *(const float4*)(W + (size_t)(k0 + r) * N + c4 * 4);
        }
        __syncthreads();

        #pragma unroll 8
        for (int k = 0; k < BK; k++) {
            float ra[TM], rb[TN];
            *(float4*)ra = *(const float4*)&As[k][ty * TM];
            #pragma unroll
            for (int jj = 0; jj < TN / 4; jj++)
                *(float4*)&rb[jj * 4] = *(const float4*)&Ws[k][tx * TN + jj * 4];
            #pragma unroll
            for (int i = 0; i < TM; i++)
                #pragma unroll
                for (int j = 0; j < TN; j++)
                    acc[i][j] = fmaf(ra[i], rb[j], acc[i][j]);
        }
        __syncthreads();
    }

    #pragma unroll
    for (int i = 0; i < TM; i++) {
        int gr = rowBase + ty * TM + i;
        if (gr >= M) continue;
        #pragma unroll
        for (int jj = 0; jj < TN / 4; jj++) {
            int col = tx * TN + jj * 4;
            float4 v;
            v.x = acc[i][jj*4+0]; v.y = acc[i][jj*4+1];
            v.z = acc[i][jj*4+2]; v.w = acc[i][jj*4+3];
            if (bias) {
                v.x += bias[col+0]; v.y += bias[col+1];
                v.z += bias[col+2]; v.w += bias[col+3];
            }
            if (RELU_OUT) {
                v.x = fmaxf(v.x, 0.f); v.y = fmaxf(v.y, 0.f);
                v.z = fmaxf(v.z, 0.f); v.w = fmaxf(v.w, 0.f);
            }
            *(float4*)(C + (size_t)gr * N + col) = v;
        }
    }
}

// ---------------------------------------------------------------------------
// Batched edge scatters (measured win in R4)
// ---------------------------------------------------------------------------
__global__ void __launch_bounds__(256)
scatter_add128_kernel(const float* __restrict__ src_feat,
                      float* __restrict__ dst_feat,
                      const int* __restrict__ ei, int nEdges)
{
    const int w    = blockIdx.x * (blockDim.x >> 5) + (threadIdx.x >> 5);
    const int lane = threadIdx.x & 31;
    const int eb   = w * 8;
    if (eb >= nEdges) return;
    const int n = min(8, nEdges - eb);

    int idx = 0;
    if (lane < 8) {
        if (lane < n) idx = ei[eb + lane];
    } else if (lane < 16) {
        if (lane - 8 < n) idx = ei[nEdges + eb + (lane - 8)];
    }

    float4 v[8];
    #pragma unroll
    for (int i = 0; i < 8; i++) {
        int s = __shfl_sync(0xffffffffu, idx, i);
        if (i < n)
            v[i] = *(const float4*)(src_feat + (size_t)s * 128 + lane * 4);
    }
    #pragma unroll
    for (int i = 0; i < 8; i++) {
        int d = __shfl_sync(0xffffffffu, idx, 8 + i);
        if (i < n) {
            float* dp = dst_feat + (size_t)d * 128 + lane * 4;
            asm volatile("red.global.add.v4.f32 [%0], {%1,%2,%3,%4};"
                         :: "l"(dp), "f"(v[i].x), "f"(v[i].y), "f"(v[i].z), "f"(v[i].w)
                         : "memory");
        }
    }
}

__global__ void __launch_bounds__(256)
scatter_add64_kernel(const float* __restrict__ src_feat,
                     float* __restrict__ dst_feat,
                     const int* __restrict__ ei, int nEdges)
{
    const int w    = blockIdx.x * (blockDim.x >> 5) + (threadIdx.x >> 5);
    const int lane = threadIdx.x & 31;
    const int eb   = w * 16;
    if (eb >= nEdges) return;
    const int n    = min(16, nEdges - eb);
    const int half = lane >> 4;
    const int sub  = lane & 15;

    int idx = 0;
    if (lane < 16) {
        if (lane < n) idx = ei[eb + lane];
    } else {
        if (lane - 16 < n) idx = ei[nEdges + eb + (lane - 16)];
    }

    float4 v[8];
    #pragma unroll
    for (int it = 0; it < 8; it++) {
        int e = it * 2 + half;
        int s = __shfl_sync(0xffffffffu, idx, e);
        if (e < n)
            v[it] = *(const float4*)(src_feat + (size_t)s * 64 + sub * 4);
    }
    #pragma unroll
    for (int it = 0; it < 8; it++) {
        int e = it * 2 + half;
        int d = __shfl_sync(0xffffffffu, idx, 16 + e);
        if (e < n) {
            float* dp = dst_feat + (size_t)d * 64 + sub * 4;
            asm volatile("red.global.add.v4.f32 [%0], {%1,%2,%3,%4};"
                         :: "l"(dp), "f"(v[it].x), "f"(v[it].y), "f"(v[it].z), "f"(v[it].w)
                         : "memory");
        }
    }
}

// ---------------------------------------------------------------------------
// Fused mlp2 + head (unchanged)
// ---------------------------------------------------------------------------
__global__ void __launch_bounds__(256)
mlp2_head_kernel(const float* __restrict__ A,
                 const float* __restrict__ W,
                 const float* __restrict__ b,
                 const float* __restrict__ W3,
                 const float* __restrict__ b3,
                 float* __restrict__ out, int M)
{
    constexpr int BM = 64, BN = 64, BK = 32, TM = 4, TN = 4;
    constexpr int K = 128;
    constexpr int T = 256;
    constexpr int PAD = 4;

    __shared__ float As[BK][BM + PAD];
    __shared__ float Ws[BK][BN];
    __shared__ float Ct[BM][BN + PAD];
    __shared__ float W3s[D4 * NCLS];
    __shared__ float b3s[NCLS];

    const int tid = threadIdx.x;
    const int tx  = tid % (BN / TN);
    const int ty  = tid / (BN / TN);
    const int rowBase = blockIdx.x * BM;

    for (int i = tid; i < D4 * NCLS; i += T) W3s[i] = W3[i];
    if (tid < NCLS) b3s[tid] = b3[tid];

    float acc[TM][TN];
    #pragma unroll
    for (int i = 0; i < TM; i++)
        #pragma unroll
        for (int j = 0; j < TN; j++) acc[i][j] = 0.f;

    for (int k0 = 0; k0 < K; k0 += BK) {
        constexpr int A_IT = BM * BK / 4 / T;
        #pragma unroll
        for (int it = 0; it < A_IT; it++) {
            int i  = tid + it * T;
            int r  = i / (BK / 4);
            int c4 = i % (BK / 4);
            float4 v = make_float4(0.f, 0.f, 0.f, 0.f);
            int gr = rowBase + r;
            if (gr < M)
                v = *(const float4*)(A + (size_t)gr * K + k0 + c4 * 4);
            As[c4 * 4 + 0][r] = v.x;
            As[c4 * 4 + 1][r] = v.y;
            As[c4 * 4 + 2][r] = v.z;
            As[c4 * 4 + 3][r] = v.w;
        }
        constexpr int W_IT = BK * BN / 4 / T;
        #pragma unroll
        for (int it = 0; it < W_IT; it++) {
            int i  = tid + it * T;
            int r  = i / (BN / 4);
            int c4 = i % (BN / 4);
            *(float4*)&Ws[r][c4 * 4] =
                *(const float4*)(W + (size_t)(k0 + r) * BN + c4 * 4);
        }
        __syncthreads();

        #pragma unroll 8
        for (int k = 0; k < BK; k++) {
            float ra[TM], rb[TN];
            *(float4*)ra = *(const float4*)&As[k][ty * TM];
            *(float4*)rb = *(const float4*)&Ws[k][tx * TN];
            #pragma unroll
            for (int i = 0; i < TM; i++)
                #pragma unroll
                for (int j = 0; j < TN; j++)
                    acc[i][j] = fmaf(ra[i], rb[j], acc[i][j]);
        }
        __syncthreads();
    }

    #pragma unroll
    for (int i = 0; i < TM; i++) {
        int r = ty * TM + i;
        #pragma unroll
        for (int j = 0; j < TN; j++) {
            int col = tx * TN + j;
            Ct[r][col] = fmaxf(acc[i][j] + b[col], 0.f);
        }
    }
    __syncthreads();

    int warp = tid >> 5;
    int lane = tid & 31;
    #pragma unroll
    for (int rr = 0; rr < 8; rr++) {
        int r  = warp * 8 + rr;
        int gr = rowBase + r;
        if (gr >= M) continue;

        float acc2 = -1e30f;
        if (lane < NCLS) {
            acc2 = b3s[lane];
            #pragma unroll 8
            for (int k = 0; k < D4; k++)
                acc2 = fmaf(Ct[r][k], W3s[k * NCLS + lane], acc2);
        }
        float m = acc2;
        #pragma unroll
        for (int o = 16; o > 0; o >>= 1)
            m = fmaxf(m, __shfl_xor_sync(0xffffffffu, m, o));
        float ex = (lane < NCLS) ? expf(acc2 - m) : 0.f;
        float ssum = ex;
        #pragma unroll
        for (int o = 16; o > 0; o >>= 1)
            ssum += __shfl_xor_sync(0xffffffffu, ssum, o);
        float lse = m + logf(ssum);
        if (lane < NCLS)
            out[(size_t)gr * NCLS + lane] = acc2 - lse;
    }
}

// ---------------------------------------------------------------------------
// Launch
// ---------------------------------------------------------------------------
extern "C" void kernel_launch(void* const* d_in, const int* in_sizes, int n_in,
                              void* d_out, int out_size)
{
    const float* x      = (const float*)d_in[0];
    const int*   ei     = (const int*)d_in[1];
    const float* W1_rel = (const float*)d_in[2];
    const float* W1_rt  = (const float*)d_in[3];
    const float* b1     = (const float*)d_in[4];
    const float* W2_rel = (const float*)d_in[5];
    const float* W2_rt  = (const float*)d_in[6];
    const float* b2     = (const float*)d_in[7];
    const float* L1w    = (const float*)d_in[8];
    const float* L1b    = (const float*)d_in[9];
    const float* L2w    = (const float*)d_in[10];
    const float* L2b    = (const float*)d_in[11];
    const float* L3w    = (const float*)d_in[12];
    const float* L3b    = (const float*)d_in[13];
    float*       out    = (float*)d_out;

    const int M  = in_sizes[0] / DIN;   // 20000
    const int nE = in_sizes[1] / 2;     // 320000

    float *XR, *H1, *XR2, *H2, *H3;
    cudaGetSymbolAddress((void**)&XR,  g_XR);
    cudaGetSymbolAddress((void**)&H1,  g_H1);
    cudaGetSymbolAddress((void**)&XR2, g_XR2);
    cudaGetSymbolAddress((void**)&H2,  g_H2);
    cudaGetSymbolAddress((void**)&H3,  g_H3);

    const int gM64  = (M + 63) / 64;
    const int gM128 = (M + 127) / 128;

    // bf16 split prep
    {
        int n4 = M * DIN / 4;
        prep_x_kernel<<<(n4 + 255) / 256, 256>>>(x, n4);
        int nw = 2 * DIN * D1;
        prep_w_kernel<<<(nw + 255) / 256, 256>>>(W1_rel, W1_rt);
    }

    // conv1 on tensor cores (mma.sync): XR = x@W1_rel ; H1 = x@W1_root + b1
    conv1_mma_kernel<<<dim3(gM128, 2), 256>>>(b1, M);

    // H1[dst] += XR[src]
    {
        int warps = (nE + 7) / 8;
        int blks  = (warps + 7) / 8;
        scatter_add128_kernel<<<blks, 256>>>(XR, H1, ei, nE);
    }

    // conv2 (dual, relu-in), measured-good config
    gemm_kernel<64,64,32,4,4,true,false>
        <<<dim3(gM64,1,2), 256>>>(H1, W2_rel, W2_rt, nullptr, b2, XR2, H2, M, D1);

    // H2[dst] += XR2[src]
    {
        int warps = (nE + 15) / 16;
        int blks  = (warps + 7) / 8;
        scatter_add64_kernel<<<blks, 256>>>(XR2, H2, ei, nE);
    }

    // mlp1: H3 = relu(H2 @ L1w + L1b)
    gemm_kernel<64,128,32,4,8,false,true>
        <<<dim3(gM64,1,1), 256>>>(H2, L1w, nullptr, L1b, nullptr, H3, nullptr, M, D2);

    // mlp2 + head fused
    mlp2_head_kernel<<<gM64, 256>>>(H3, L2w, L2b, L3w, L3b, out, M);
}

// round 9
// speedup vs baseline: 2.0061x; 1.1585x over previous
#include <cuda_runtime.h>
#include <cuda_bf16.h>
#include <math.h>
#include <stdint.h>

// ---------------------------------------------------------------------------
// Problem constants
// ---------------------------------------------------------------------------
#define N_NODES_MAX 20000
#define DIN 256
#define D1 128
#define D2 64
#define D3 128
#define D4 64
#define NCLS 10

// ---------------------------------------------------------------------------
// Scratch (static device globals; no allocations anywhere)
// ---------------------------------------------------------------------------
__device__ float g_XR [N_NODES_MAX * D1];
__device__ float g_H1 [N_NODES_MAX * D1];
__device__ float g_XR2[N_NODES_MAX * D2];
__device__ float g_H2 [N_NODES_MAX * D2];
__device__ float g_H3 [N_NODES_MAX * D3];

// bf16 hi/lo weights, transposed to [n][k] K-major
// B1: conv1, slot0=W1_rel slot1=W1_root  (2 x 128 x 256)
// B2: conv2 combined [n<64: W2_rel | n>=64: W2_root] (128 x 128)
// B3: mlp1 L1w^T (128 x 64)
__device__ __nv_bfloat16 g_B1hi[2 * D1 * DIN];
__device__ __nv_bfloat16 g_B1lo[2 * D1 * DIN];
__device__ __nv_bfloat16 g_B2hi[128 * 128];
__device__ __nv_bfloat16 g_B2lo[128 * 128];
__device__ __nv_bfloat16 g_B3hi[128 * 64];
__device__ __nv_bfloat16 g_B3lo[128 * 64];

// ---------------------------------------------------------------------------
// mma.sync helpers (sm_80+ baseline ISA; compiles for plain compute_100)
// ---------------------------------------------------------------------------
__device__ __forceinline__ uint32_t smem_u32(const void* p) {
    uint32_t a;
    asm("{ .reg .u64 t; cvta.to.shared.u64 t, %1; cvt.u32.u64 %0, t; }"
        : "=r"(a) : "l"(p));
    return a;
}
__device__ __forceinline__ void ldsm_x4(uint32_t& r0, uint32_t& r1,
                                        uint32_t& r2, uint32_t& r3,
                                        uint32_t addr) {
    asm volatile("ldmatrix.sync.aligned.m8n8.x4.shared.b16 {%0,%1,%2,%3}, [%4];"
                 : "=r"(r0), "=r"(r1), "=r"(r2), "=r"(r3) : "r"(addr));
}
__device__ __forceinline__ void mma_bf16(float& c0, float& c1, float& c2, float& c3,
                                         uint32_t a0, uint32_t a1, uint32_t a2, uint32_t a3,
                                         uint32_t b0, uint32_t b1) {
    asm volatile(
        "mma.sync.aligned.m16n8k16.row.col.f32.bf16.bf16.f32 "
        "{%0,%1,%2,%3}, {%4,%5,%6,%7}, {%8,%9}, {%0,%1,%2,%3};"
        : "+f"(c0), "+f"(c1), "+f"(c2), "+f"(c3)
        : "r"(a0), "r"(a1), "r"(a2), "r"(a3), "r"(b0), "r"(b1));
}

// ---------------------------------------------------------------------------
// Combined weight prep: fp32 -> bf16 hi/lo, transposed to [n][k]
// ---------------------------------------------------------------------------
#define NW1 (2 * DIN * D1)      // 65536
#define NW2 (128 * 128)         // 16384
#define NW3 (128 * 64)          // 8192
__global__ void prep_weights_kernel(const float* __restrict__ W1rel,
                                    const float* __restrict__ W1rt,
                                    const float* __restrict__ W2rel,
                                    const float* __restrict__ W2rt,
                                    const float* __restrict__ L1w)
{
    int idx = blockIdx.x * blockDim.x + threadIdx.x;
    float f;
    __nv_bfloat16* dh;
    __nv_bfloat16* dl;
    size_t off;
    if (idx < NW1) {
        int w   = idx / (DIN * D1);
        int rem = idx % (DIN * D1);
        int k   = rem / D1;
        int n   = rem % D1;
        f   = (w ? W1rt : W1rel)[k * D1 + n];
        off = (size_t)w * D1 * DIN + (size_t)n * DIN + k;
        dh = g_B1hi; dl = g_B1lo;
    } else if (idx < NW1 + NW2) {
        int i = idx - NW1;
        int n = i / 128;
        int k = i % 128;
        f   = (n < 64) ? W2rel[k * 64 + n] : W2rt[k * 64 + (n - 64)];
        off = (size_t)n * 128 + k;
        dh = g_B2hi; dl = g_B2lo;
    } else if (idx < NW1 + NW2 + NW3) {
        int i = idx - NW1 - NW2;
        int n = i / 64;
        int k = i % 64;
        f   = L1w[k * 128 + n];
        off = (size_t)n * 64 + k;
        dh = g_B3hi; dl = g_B3lo;
    } else return;

    __nv_bfloat16 h = __float2bfloat16(f);
    dh[off] = h;
    dl[off] = __float2bfloat16(f - __bfloat162float(h));
}

// ---------------------------------------------------------------------------
// Generic mma.sync bf16-split GEMM, A staged from fp32 (split in-flight).
//   MODE 0 (conv1): blockIdx.y selects B slot (stride 128*KDIM) and dst;
//                   bias only for blockIdx.y==1. C row stride 128.
//   MODE 1 (conv2): cols<64 -> C0 (stride 64, no bias);
//                   cols>=64 -> C1 (stride 64, bias[col-64]).
//   MODE 2 (mlp1):  C0 stride 128, bias, optional relu.
// Block: 256 thr = 8 warps (2x4), tile M128 x N128, K chunks of 32.
// Terms: Ah*Bh + Ah*Bl + Al*Bh (fp32 accum).
// ---------------------------------------------------------------------------
#define SM_AH 0
#define SM_AL 8192
#define SM_BH 16384
#define SM_BL 24576

template<int KDIM, int MODE, bool RELU_A, bool RELU_OUT>
__global__ void __launch_bounds__(256)
mma_gemm_kernel(const float* __restrict__ A,           // [M, KDIM] fp32
                const __nv_bfloat16* __restrict__ Bhi,
                const __nv_bfloat16* __restrict__ Blo,
                const float* __restrict__ bias,
                float* __restrict__ C0, float* __restrict__ C1, int M)
{
    __shared__ char smem[32768];
    const uint32_t sbase = smem_u32(smem);

    const int tid  = threadIdx.x;
    const int wid  = tid >> 5;
    const int lane = tid & 31;
    const int rowBase = blockIdx.x * 128;

    const __nv_bfloat16* __restrict__ Bh = Bhi;
    const __nv_bfloat16* __restrict__ Bl = Blo;
    if (MODE == 0) {
        Bh += (size_t)blockIdx.y * 128 * KDIM;
        Bl += (size_t)blockIdx.y * 128 * KDIM;
    }

    const int mBase = (wid >> 2) * 64;   // 0 or 64
    const int nBase = (wid & 3) * 32;    // 0,32,64,96

    const int qr    = lane & 7;
    const int half1 = (lane >> 3) & 1;
    const int half2 = (lane >> 4) & 1;

    float c[4][4][4];
    #pragma unroll
    for (int i = 0; i < 4; i++)
        #pragma unroll
        for (int j = 0; j < 4; j++)
            #pragma unroll
            for (int q = 0; q < 4; q++) c[i][j][q] = 0.f;

    constexpr int NCH = KDIM / 32;
    for (int ch = 0; ch < NCH; ch++) {
        const int k0 = ch * 32;
        // ---- stage A from fp32 (split hi/lo in-flight) ----
        #pragma unroll
        for (int it = 0; it < 2; it++) {
            int i  = tid + it * 256;       // 0..511
            int r  = i >> 2;               // 0..127
            int kc = i & 3;                // 16B chunk within 64B row
            uint32_t so = (uint32_t)(r * 64 + ((kc ^ (r & 3)) << 4));
            int gr = rowBase + r;
            __nv_bfloat16 h[8], l[8];
            if (gr < M) {
                const float* ap = A + (size_t)gr * KDIM + k0 + kc * 8;
                float4 a0 = *(const float4*)ap;
                float4 a1 = *(const float4*)(ap + 4);
                float f[8] = {a0.x, a0.y, a0.z, a0.w, a1.x, a1.y, a1.z, a1.w};
                #pragma unroll
                for (int j = 0; j < 8; j++) {
                    float fv = RELU_A ? fmaxf(f[j], 0.f) : f[j];
                    h[j] = __float2bfloat16(fv);
                    l[j] = __float2bfloat16(fv - __bfloat162float(h[j]));
                }
            } else {
                #pragma unroll
                for (int j = 0; j < 8; j++) { h[j] = __float2bfloat16(0.f); l[j] = h[j]; }
            }
            *(uint4*)(smem + SM_AH + so) = *(uint4*)h;
            *(uint4*)(smem + SM_AL + so) = *(uint4*)l;
            // ---- stage B hi/lo ----
            uint4 wh = *(const uint4*)(Bh + (size_t)r * KDIM + k0 + kc * 8);
            uint4 wl = *(const uint4*)(Bl + (size_t)r * KDIM + k0 + kc * 8);
            *(uint4*)(smem + SM_BH + so) = wh;
            *(uint4*)(smem + SM_BL + so) = wl;
        }
        __syncthreads();

        // ---- 2 k16 steps ----
        #pragma unroll
        for (int ks = 0; ks < 2; ks++) {
            const int kk = ks * 16;
            uint32_t ah[4][4], al[4][4];
            #pragma unroll
            for (int mt = 0; mt < 4; mt++) {
                int r  = mBase + mt * 16 + qr + half1 * 8;
                int kA = kk + half2 * 8;
                uint32_t so = (uint32_t)(r * 64 + (((kA >> 3) ^ (r & 3)) << 4));
                ldsm_x4(ah[mt][0], ah[mt][1], ah[mt][2], ah[mt][3],
                        sbase + SM_AH + so);
                ldsm_x4(al[mt][0], al[mt][1], al[mt][2], al[mt][3],
                        sbase + SM_AL + so);
            }
            uint32_t bh[2][4], bl[2][4];
            #pragma unroll
            for (int pr = 0; pr < 2; pr++) {
                int r  = nBase + pr * 16 + qr + half2 * 8;
                int kB = kk + half1 * 8;
                uint32_t so = (uint32_t)(r * 64 + (((kB >> 3) ^ (r & 3)) << 4));
                ldsm_x4(bh[pr][0], bh[pr][1], bh[pr][2], bh[pr][3],
                        sbase + SM_BH + so);
                ldsm_x4(bl[pr][0], bl[pr][1], bl[pr][2], bl[pr][3],
                        sbase + SM_BL + so);
            }
            #pragma unroll
            for (int mt = 0; mt < 4; mt++) {
                #pragma unroll
                for (int nt = 0; nt < 4; nt++) {
                    uint32_t b0h = bh[nt >> 1][(nt & 1) * 2];
                    uint32_t b1h = bh[nt >> 1][(nt & 1) * 2 + 1];
                    uint32_t b0l = bl[nt >> 1][(nt & 1) * 2];
                    uint32_t b1l = bl[nt >> 1][(nt & 1) * 2 + 1];
                    float* cc = c[mt][nt];
                    mma_bf16(cc[0], cc[1], cc[2], cc[3],
                             ah[mt][0], ah[mt][1], ah[mt][2], ah[mt][3], b0h, b1h);
                    mma_bf16(cc[0], cc[1], cc[2], cc[3],
                             ah[mt][0], ah[mt][1], ah[mt][2], ah[mt][3], b0l, b1l);
                    mma_bf16(cc[0], cc[1], cc[2], cc[3],
                             al[mt][0], al[mt][1], al[mt][2], al[mt][3], b0h, b1h);
                }
            }
        }
        __syncthreads();
    }

    // ---- epilogue ----
    const int gid = lane >> 2;
    const int tig = lane & 3;
    #pragma unroll
    for (int mt = 0; mt < 4; mt++) {
        #pragma unroll
        for (int nt = 0; nt < 4; nt++) {
            int col  = nBase + nt * 8 + tig * 2;
            int row0 = rowBase + mBase + mt * 16 + gid;
            int row1 = row0 + 8;

            float* dst; int ccol; int stride; float bx = 0.f, by = 0.f;
            if (MODE == 0) {
                dst = blockIdx.y ? C1 : C0; ccol = col; stride = 128;
                if (blockIdx.y) { bx = bias[col]; by = bias[col + 1]; }
            } else if (MODE == 1) {
                if (col < 64) { dst = C0; ccol = col;      stride = 64; }
                else          { dst = C1; ccol = col - 64; stride = 64;
                                bx = bias[ccol]; by = bias[ccol + 1]; }
            } else {
                dst = C0; ccol = col; stride = 128;
                bx = bias[col]; by = bias[col + 1];
            }

            float vx0 = c[mt][nt][0] + bx, vy0 = c[mt][nt][1] + by;
            float vx1 = c[mt][nt][2] + bx, vy1 = c[mt][nt][3] + by;
            if (RELU_OUT) {
                vx0 = fmaxf(vx0, 0.f); vy0 = fmaxf(vy0, 0.f);
                vx1 = fmaxf(vx1, 0.f); vy1 = fmaxf(vy1, 0.f);
            }
            if (row0 < M) {
                float2 v; v.x = vx0; v.y = vy0;
                *(float2*)(dst + (size_t)row0 * stride + ccol) = v;
            }
            if (row1 < M) {
                float2 v; v.x = vx1; v.y = vy1;
                *(float2*)(dst + (size_t)row1 * stride + ccol) = v;
            }
        }
    }
}

// ---------------------------------------------------------------------------
// Batched edge scatters (measured win in R4)
// ---------------------------------------------------------------------------
__global__ void __launch_bounds__(256)
scatter_add128_kernel(const float* __restrict__ src_feat,
                      float* __restrict__ dst_feat,
                      const int* __restrict__ ei, int nEdges)
{
    const int w    = blockIdx.x * (blockDim.x >> 5) + (threadIdx.x >> 5);
    const int lane = threadIdx.x & 31;
    const int eb   = w * 8;
    if (eb >= nEdges) return;
    const int n = min(8, nEdges - eb);

    int idx = 0;
    if (lane < 8) {
        if (lane < n) idx = ei[eb + lane];
    } else if (lane < 16) {
        if (lane - 8 < n) idx = ei[nEdges + eb + (lane - 8)];
    }

    float4 v[8];
    #pragma unroll
    for (int i = 0; i < 8; i++) {
        int s = __shfl_sync(0xffffffffu, idx, i);
        if (i < n)
            v[i] = *(const float4*)(src_feat + (size_t)s * 128 + lane * 4);
    }
    #pragma unroll
    for (int i = 0; i < 8; i++) {
        int d = __shfl_sync(0xffffffffu, idx, 8 + i);
        if (i < n) {
            float* dp = dst_feat + (size_t)d * 128 + lane * 4;
            asm volatile("red.global.add.v4.f32 [%0], {%1,%2,%3,%4};"
                         :: "l"(dp), "f"(v[i].x), "f"(v[i].y), "f"(v[i].z), "f"(v[i].w)
                         : "memory");
        }
    }
}

__global__ void __launch_bounds__(256)
scatter_add64_kernel(const float* __restrict__ src_feat,
                     float* __restrict__ dst_feat,
                     const int* __restrict__ ei, int nEdges)
{
    const int w    = blockIdx.x * (blockDim.x >> 5) + (threadIdx.x >> 5);
    const int lane = threadIdx.x & 31;
    const int eb   = w * 16;
    if (eb >= nEdges) return;
    const int n    = min(16, nEdges - eb);
    const int half = lane >> 4;
    const int sub  = lane & 15;

    int idx = 0;
    if (lane < 16) {
        if (lane < n) idx = ei[eb + lane];
    } else {
        if (lane - 16 < n) idx = ei[nEdges + eb + (lane - 16)];
    }

    float4 v[8];
    #pragma unroll
    for (int it = 0; it < 8; it++) {
        int e = it * 2 + half;
        int s = __shfl_sync(0xffffffffu, idx, e);
        if (e < n)
            v[it] = *(const float4*)(src_feat + (size_t)s * 64 + sub * 4);
    }
    #pragma unroll
    for (int it = 0; it < 8; it++) {
        int e = it * 2 + half;
        int d = __shfl_sync(0xffffffffu, idx, 16 + e);
        if (e < n) {
            float* dp = dst_feat + (size_t)d * 64 + sub * 4;
            asm volatile("red.global.add.v4.f32 [%0], {%1,%2,%3,%4};"
                         :: "l"(dp), "f"(v[it].x), "f"(v[it].y), "f"(v[it].z), "f"(v[it].w)
                         : "memory");
        }
    }
}

// ---------------------------------------------------------------------------
// Fused mlp2 + head (unchanged; fp32)
// ---------------------------------------------------------------------------
__global__ void __launch_bounds__(256)
mlp2_head_kernel(const float* __restrict__ A,
                 const float* __restrict__ W,
                 const float* __restrict__ b,
                 const float* __restrict__ W3,
                 const float* __restrict__ b3,
                 float* __restrict__ out, int M)
{
    constexpr int BM = 64, BN = 64, BK = 32, TM = 4, TN = 4;
    constexpr int K = 128;
    constexpr int T = 256;
    constexpr int PAD = 4;

    __shared__ float As[BK][BM + PAD];
    __shared__ float Ws[BK][BN];
    __shared__ float Ct[BM][BN + PAD];
    __shared__ float W3s[D4 * NCLS];
    __shared__ float b3s[NCLS];

    const int tid = threadIdx.x;
    const int tx  = tid % (BN / TN);
    const int ty  = tid / (BN / TN);
    const int rowBase = blockIdx.x * BM;

    for (int i = tid; i < D4 * NCLS; i += T) W3s[i] = W3[i];
    if (tid < NCLS) b3s[tid] = b3[tid];

    float acc[TM][TN];
    #pragma unroll
    for (int i = 0; i < TM; i++)
        #pragma unroll
        for (int j = 0; j < TN; j++) acc[i][j] = 0.f;

    for (int k0 = 0; k0 < K; k0 += BK) {
        constexpr int A_IT = BM * BK / 4 / T;
        #pragma unroll
        for (int it = 0; it < A_IT; it++) {
            int i  = tid + it * T;
            int r  = i / (BK / 4);
            int c4 = i % (BK / 4);
            float4 v = make_float4(0.f, 0.f, 0.f, 0.f);
            int gr = rowBase + r;
            if (gr < M)
                v = *(const float4*)(A + (size_t)gr * K + k0 + c4 * 4);
            As[c4 * 4 + 0][r] = v.x;
            As[c4 * 4 + 1][r] = v.y;
            As[c4 * 4 + 2][r] = v.z;
            As[c4 * 4 + 3][r] = v.w;
        }
        constexpr int W_IT = BK * BN / 4 / T;
        #pragma unroll
        for (int it = 0; it < W_IT; it++) {
            int i  = tid + it * T;
            int r  = i / (BN / 4);
            int c4 = i % (BN / 4);
            *(float4*)&Ws[r][c4 * 4] =
                *(const float4*)(W + (size_t)(k0 + r) * BN + c4 * 4);
        }
        __syncthreads();

        #pragma unroll 8
        for (int k = 0; k < BK; k++) {
            float ra[TM], rb[TN];
            *(float4*)ra = *(const float4*)&As[k][ty * TM];
            *(float4*)rb = *(const float4*)&Ws[k][tx * TN];
            #pragma unroll
            for (int i = 0; i < TM; i++)
                #pragma unroll
                for (int j = 0; j < TN; j++)
                    acc[i][j] = fmaf(ra[i], rb[j], acc[i][j]);
        }
        __syncthreads();
    }

    #pragma unroll
    for (int i = 0; i < TM; i++) {
        int r = ty * TM + i;
        #pragma unroll
        for (int j = 0; j < TN; j++) {
            int col = tx * TN + j;
            Ct[r][col] = fmaxf(acc[i][j] + b[col], 0.f);
        }
    }
    __syncthreads();

    int warp = tid >> 5;
    int lane = tid & 31;
    #pragma unroll
    for (int rr = 0; rr < 8; rr++) {
        int r  = warp * 8 + rr;
        int gr = rowBase + r;
        if (gr >= M) continue;

        float acc2 = -1e30f;
        if (lane < NCLS) {
            acc2 = b3s[lane];
            #pragma unroll 8
            for (int k = 0; k < D4; k++)
                acc2 = fmaf(Ct[r][k], W3s[k * NCLS + lane], acc2);
        }
        float m = acc2;
        #pragma unroll
        for (int o = 16; o > 0; o >>= 1)
            m = fmaxf(m, __shfl_xor_sync(0xffffffffu, m, o));
        float ex = (lane < NCLS) ? expf(acc2 - m) : 0.f;
        float ssum = ex;
        #pragma unroll
        for (int o = 16; o > 0; o >>= 1)
            ssum += __shfl_xor_sync(0xffffffffu, ssum, o);
        float lse = m + logf(ssum);
        if (lane < NCLS)
            out[(size_t)gr * NCLS + lane] = acc2 - lse;
    }
}

// ---------------------------------------------------------------------------
// Launch
// ---------------------------------------------------------------------------
extern "C" void kernel_launch(void* const* d_in, const int* in_sizes, int n_in,
                              void* d_out, int out_size)
{
    const float* x      = (const float*)d_in[0];
    const int*   ei     = (const int*)d_in[1];
    const float* W1_rel = (const float*)d_in[2];
    const float* W1_rt  = (const float*)d_in[3];
    const float* b1     = (const float*)d_in[4];
    const float* W2_rel = (const float*)d_in[5];
    const float* W2_rt  = (const float*)d_in[6];
    const float* b2     = (const float*)d_in[7];
    const float* L1w    = (const float*)d_in[8];
    const float* L1b    = (const float*)d_in[9];
    const float* L2w    = (const float*)d_in[10];
    const float* L2b    = (const float*)d_in[11];
    const float* L3w    = (const float*)d_in[12];
    const float* L3b    = (const float*)d_in[13];
    float*       out    = (float*)d_out;

    const int M  = in_sizes[0] / DIN;   // 20000
    const int nE = in_sizes[1] / 2;     // 320000

    float *XR, *H1, *XR2, *H2, *H3;
    __nv_bfloat16 *B1hi, *B1lo, *B2hi, *B2lo, *B3hi, *B3lo;
    cudaGetSymbolAddress((void**)&XR,   g_XR);
    cudaGetSymbolAddress((void**)&H1,   g_H1);
    cudaGetSymbolAddress((void**)&XR2,  g_XR2);
    cudaGetSymbolAddress((void**)&H2,   g_H2);
    cudaGetSymbolAddress((void**)&H3,   g_H3);
    cudaGetSymbolAddress((void**)&B1hi, g_B1hi);
    cudaGetSymbolAddress((void**)&B1lo, g_B1lo);
    cudaGetSymbolAddress((void**)&B2hi, g_B2hi);
    cudaGetSymbolAddress((void**)&B2lo, g_B2lo);
    cudaGetSymbolAddress((void**)&B3hi, g_B3hi);
    cudaGetSymbolAddress((void**)&B3lo, g_B3lo);

    const int gM64  = (M + 63) / 64;
    const int gM128 = (M + 127) / 128;

    // weight prep (all layers)
    {
        int ntot = NW1 + NW2 + NW3;
        prep_weights_kernel<<<(ntot + 255) / 256, 256>>>(W1_rel, W1_rt, W2_rel, W2_rt, L1w);
    }

    // conv1: XR = x@W1_rel ; H1 = x@W1_root + b1
    mma_gemm_kernel<256, 0, false, false>
        <<<dim3(gM128, 2), 256>>>(x, B1hi, B1lo, b1, XR, H1, M);

    // H1[dst] += XR[src]
    {
        int warps = (nE + 7) / 8;
        int blks  = (warps + 7) / 8;
        scatter_add128_kernel<<<blks, 256>>>(XR, H1, ei, nE);
    }

    // conv2 (both outputs in one kernel; relu on input A=H1):
    //   XR2 = relu(H1)@W2_rel ; H2 = relu(H1)@W2_root + b2
    mma_gemm_kernel<128, 1, true, false>
        <<<gM128, 256>>>(H1, B2hi, B2lo, b2, XR2, H2, M);

    // H2[dst] += XR2[src]
    {
        int warps = (nE + 15) / 16;
        int blks  = (warps + 7) / 8;
        scatter_add64_kernel<<<blks, 256>>>(XR2, H2, ei, nE);
    }

    // mlp1: H3 = relu(H2 @ L1w + L1b)
    mma_gemm_kernel<64, 2, false, true>
        <<<gM128, 256>>>(H2, B3hi, B3lo, L1b, H3, nullptr, M);

    // mlp2 + head fused
    mlp2_head_kernel<<<gM64, 256>>>(H3, L2w, L2b, L3w, L3b, out, M);
}

// round 11
// speedup vs baseline: 2.1189x; 1.0562x over previous
#include <cuda_runtime.h>
#include <cuda_bf16.h>
#include <math.h>
#include <stdint.h>

// ---------------------------------------------------------------------------
// Problem constants
// ---------------------------------------------------------------------------
#define N_NODES_MAX 20000
#define DIN 256
#define D1 128
#define D2 64
#define D3 128
#define D4 64
#define NCLS 10

// ---------------------------------------------------------------------------
// Scratch (static device globals; no allocations anywhere)
// ---------------------------------------------------------------------------
__device__ float g_XR [N_NODES_MAX * D1];
__device__ float g_H1 [N_NODES_MAX * D1];
__device__ float g_XR2[N_NODES_MAX * D2];
__device__ float g_H2 [N_NODES_MAX * D2];
__device__ float g_H3 [N_NODES_MAX * D3];

// bf16 hi/lo weights, transposed to [n][k] K-major
// B1: conv1, slot0=W1_rel slot1=W1_root  (2 x 128 x 256)
// B2: conv2 combined [n<64: W2_rel | n>=64: W2_root] (128 x 128)
// B3: mlp1 L1w^T (128 x 64)
// B4: mlp2 L2w^T (64 x 128)
__device__ __nv_bfloat16 g_B1hi[2 * D1 * DIN];
__device__ __nv_bfloat16 g_B1lo[2 * D1 * DIN];
__device__ __nv_bfloat16 g_B2hi[128 * 128];
__device__ __nv_bfloat16 g_B2lo[128 * 128];
__device__ __nv_bfloat16 g_B3hi[128 * 64];
__device__ __nv_bfloat16 g_B3lo[128 * 64];
__device__ __nv_bfloat16 g_B4hi[64 * 128];
__device__ __nv_bfloat16 g_B4lo[64 * 128];

// ---------------------------------------------------------------------------
// mma.sync helpers (sm_80+ baseline ISA)
// ---------------------------------------------------------------------------
__device__ __forceinline__ uint32_t smem_u32(const void* p) {
    uint32_t a;
    asm("{ .reg .u64 t; cvta.to.shared.u64 t, %1; cvt.u32.u64 %0, t; }"
        : "=r"(a) : "l"(p));
    return a;
}
__device__ __forceinline__ void ldsm_x4(uint32_t& r0, uint32_t& r1,
                                        uint32_t& r2, uint32_t& r3,
                                        uint32_t addr) {
    asm volatile("ldmatrix.sync.aligned.m8n8.x4.shared.b16 {%0,%1,%2,%3}, [%4];"
                 : "=r"(r0), "=r"(r1), "=r"(r2), "=r"(r3) : "r"(addr));
}
__device__ __forceinline__ void mma_bf16(float& c0, float& c1, float& c2, float& c3,
                                         uint32_t a0, uint32_t a1, uint32_t a2, uint32_t a3,
                                         uint32_t b0, uint32_t b1) {
    asm volatile(
        "mma.sync.aligned.m16n8k16.row.col.f32.bf16.bf16.f32 "
        "{%0,%1,%2,%3}, {%4,%5,%6,%7}, {%8,%9}, {%0,%1,%2,%3};"
        : "+f"(c0), "+f"(c1), "+f"(c2), "+f"(c3)
        : "r"(a0), "r"(a1), "r"(a2), "r"(a3), "r"(b0), "r"(b1));
}

// ---------------------------------------------------------------------------
// Combined weight prep: fp32 -> bf16 hi/lo, transposed to [n][k]
// ---------------------------------------------------------------------------
#define NW1 (2 * DIN * D1)      // 65536
#define NW2 (128 * 128)         // 16384
#define NW3 (128 * 64)          // 8192
#define NW4 (64 * 128)          // 8192
__global__ void prep_weights_kernel(const float* __restrict__ W1rel,
                                    const float* __restrict__ W1rt,
                                    const float* __restrict__ W2rel,
                                    const float* __restrict__ W2rt,
                                    const float* __restrict__ L1w,
                                    const float* __restrict__ L2w)
{
    int idx = blockIdx.x * blockDim.x + threadIdx.x;
    float f;
    __nv_bfloat16* dh;
    __nv_bfloat16* dl;
    size_t off;
    if (idx < NW1) {
        int w   = idx / (DIN * D1);
        int rem = idx % (DIN * D1);
        int k   = rem / D1;
        int n   = rem % D1;
        f   = (w ? W1rt : W1rel)[k * D1 + n];
        off = (size_t)w * D1 * DIN + (size_t)n * DIN + k;
        dh = g_B1hi; dl = g_B1lo;
    } else if (idx < NW1 + NW2) {
        int i = idx - NW1;
        int n = i / 128;
        int k = i % 128;
        f   = (n < 64) ? W2rel[k * 64 + n] : W2rt[k * 64 + (n - 64)];
        off = (size_t)n * 128 + k;
        dh = g_B2hi; dl = g_B2lo;
    } else if (idx < NW1 + NW2 + NW3) {
        int i = idx - NW1 - NW2;
        int n = i / 64;
        int k = i % 64;
        f   = L1w[k * 128 + n];
        off = (size_t)n * 64 + k;
        dh = g_B3hi; dl = g_B3lo;
    } else if (idx < NW1 + NW2 + NW3 + NW4) {
        int i = idx - NW1 - NW2 - NW3;
        int n = i / 128;
        int k = i % 128;
        f   = L2w[k * 64 + n];
        off = (size_t)n * 128 + k;
        dh = g_B4hi; dl = g_B4lo;
    } else return;

    __nv_bfloat16 h = __float2bfloat16(f);
    dh[off] = h;
    dl[off] = __float2bfloat16(f - __bfloat162float(h));
}

// ---------------------------------------------------------------------------
// Shared mma core: stages A (fp32, split hi/lo in-flight, optional relu) and
// B (pre-split bf16) into smem per 32-K chunk, runs 3-term bf16 mma.
// MT = m16 tiles per warp (block M = 2*MT*16); NW = n8 tiles per warp
// (block N = 4*NW*8). 8 warps = 2 (m) x 4 (n).
// smem layout (caller provides buffer of 2*(BM+BN)*64 bytes):
//   [0, BM*64)            A hi     [BM*64, 2*BM*64)        A lo
//   [2*BM*64, +BN*64)     B hi     [.., +BN*64)            B lo
// ---------------------------------------------------------------------------
template<int KDIM, int MT, int NW, bool RELU_A>
__device__ __forceinline__ void mma_core(
    char* smem, uint32_t sbase,
    const float* __restrict__ A,
    const __nv_bfloat16* __restrict__ Bh,
    const __nv_bfloat16* __restrict__ Bl,
    int rowBase, int M,
    float c[MT][NW][4])
{
    constexpr int BM = 2 * MT * 16;
    constexpr int BN = 4 * NW * 8;
    constexpr int OFF_AL = BM * 64;
    constexpr int OFF_BH = 2 * BM * 64;
    constexpr int OFF_BL = 2 * BM * 64 + BN * 64;

    const int tid  = threadIdx.x;
    const int wid  = tid >> 5;
    const int lane = tid & 31;

    const int mBase = (wid >> 2) * (MT * 16);
    const int nBase = (wid & 3) * (NW * 8);

    const int qr    = lane & 7;
    const int half1 = (lane >> 3) & 1;
    const int half2 = (lane >> 4) & 1;

    constexpr int NCH = KDIM / 32;
    for (int ch = 0; ch < NCH; ch++) {
        const int k0 = ch * 32;
        // ---- stage A from fp32 (split hi/lo in-flight) ----
        #pragma unroll
        for (int i0 = 0; i0 < BM * 4; i0 += 256) {
            int i  = tid + i0;
            int r  = i >> 2;
            int kc = i & 3;
            uint32_t so = (uint32_t)(r * 64 + ((kc ^ (r & 3)) << 4));
            int gr = rowBase + r;
            __nv_bfloat16 h[8], l[8];
            if (gr < M) {
                const float* ap = A + (size_t)gr * KDIM + k0 + kc * 8;
                float4 a0 = *(const float4*)ap;
                float4 a1 = *(const float4*)(ap + 4);
                float f[8] = {a0.x, a0.y, a0.z, a0.w, a1.x, a1.y, a1.z, a1.w};
                #pragma unroll
                for (int j = 0; j < 8; j++) {
                    float fv = RELU_A ? fmaxf(f[j], 0.f) : f[j];
                    h[j] = __float2bfloat16(fv);
                    l[j] = __float2bfloat16(fv - __bfloat162float(h[j]));
                }
            } else {
                #pragma unroll
                for (int j = 0; j < 8; j++) { h[j] = __float2bfloat16(0.f); l[j] = h[j]; }
            }
            *(uint4*)(smem + so) = *(uint4*)h;
            *(uint4*)(smem + OFF_AL + so) = *(uint4*)l;
        }
        // ---- stage B hi/lo ----
        #pragma unroll
        for (int i0 = 0; i0 < BN * 4; i0 += 256) {
            int i  = tid + i0;
            int r  = i >> 2;
            int kc = i & 3;
            uint32_t so = (uint32_t)(r * 64 + ((kc ^ (r & 3)) << 4));
            uint4 wh = *(const uint4*)(Bh + (size_t)r * KDIM + k0 + kc * 8);
            uint4 wl = *(const uint4*)(Bl + (size_t)r * KDIM + k0 + kc * 8);
            *(uint4*)(smem + OFF_BH + so) = wh;
            *(uint4*)(smem + OFF_BL + so) = wl;
        }
        __syncthreads();

        // ---- 2 k16 steps ----
        #pragma unroll
        for (int ks = 0; ks < 2; ks++) {
            const int kk = ks * 16;
            uint32_t ah[MT][4], al[MT][4];
            #pragma unroll
            for (int mt = 0; mt < MT; mt++) {
                int r  = mBase + mt * 16 + qr + half1 * 8;
                int kA = kk + half2 * 8;
                uint32_t so = (uint32_t)(r * 64 + (((kA >> 3) ^ (r & 3)) << 4));
                ldsm_x4(ah[mt][0], ah[mt][1], ah[mt][2], ah[mt][3], sbase + so);
                ldsm_x4(al[mt][0], al[mt][1], al[mt][2], al[mt][3],
                        sbase + OFF_AL + so);
            }
            uint32_t bh[NW / 2][4], bl[NW / 2][4];
            #pragma unroll
            for (int pr = 0; pr < NW / 2; pr++) {
                int r  = nBase + pr * 16 + qr + half2 * 8;
                int kB = kk + half1 * 8;
                uint32_t so = (uint32_t)(r * 64 + (((kB >> 3) ^ (r & 3)) << 4));
                ldsm_x4(bh[pr][0], bh[pr][1], bh[pr][2], bh[pr][3],
                        sbase + OFF_BH + so);
                ldsm_x4(bl[pr][0], bl[pr][1], bl[pr][2], bl[pr][3],
                        sbase + OFF_BL + so);
            }
            #pragma unroll
            for (int mt = 0; mt < MT; mt++) {
                #pragma unroll
                for (int nt = 0; nt < NW; nt++) {
                    uint32_t b0h = bh[nt >> 1][(nt & 1) * 2];
                    uint32_t b1h = bh[nt >> 1][(nt & 1) * 2 + 1];
                    uint32_t b0l = bl[nt >> 1][(nt & 1) * 2];
                    uint32_t b1l = bl[nt >> 1][(nt & 1) * 2 + 1];
                    float* cc = c[mt][nt];
                    mma_bf16(cc[0], cc[1], cc[2], cc[3],
                             ah[mt][0], ah[mt][1], ah[mt][2], ah[mt][3], b0h, b1h);
                    mma_bf16(cc[0], cc[1], cc[2], cc[3],
                             ah[mt][0], ah[mt][1], ah[mt][2], ah[mt][3], b0l, b1l);
                    mma_bf16(cc[0], cc[1], cc[2], cc[3],
                             al[mt][0], al[mt][1], al[mt][2], al[mt][3], b0h, b1h);
                }
            }
        }
        __syncthreads();
    }
}

// ---------------------------------------------------------------------------
// GEMM kernels on the mma core.
//   MODE 0 (conv1): blockIdx.y selects B slot / dst; bias for y==1. stride 128.
//   MODE 1 (conv2): cols<64 -> C0 (stride 64); cols>=64 -> C1+bias (stride 64).
//   MODE 2 (mlp1):  C0 stride 128, bias+relu.
// M-tile 64 (MT=2) -> grid 313 per output, 2 blocks/SM.
// ---------------------------------------------------------------------------
template<int KDIM, int MODE, bool RELU_A, bool RELU_OUT>
__global__ void __launch_bounds__(256)
mma_gemm_kernel(const float* __restrict__ A,
                const __nv_bfloat16* __restrict__ Bhi,
                const __nv_bfloat16* __restrict__ Blo,
                const float* __restrict__ bias,
                float* __restrict__ C0, float* __restrict__ C1, int M)
{
    constexpr int MT = 2, NW = 4;
    constexpr int BM = 2 * MT * 16;   // 64
    constexpr int BN = 4 * NW * 8;    // 128
    __shared__ char smem[2 * (BM + BN) * 64];
    const uint32_t sbase = smem_u32(smem);

    const int wid  = threadIdx.x >> 5;
    const int lane = threadIdx.x & 31;
    const int rowBase = blockIdx.x * BM;

    const __nv_bfloat16* Bh = Bhi;
    const __nv_bfloat16* Bl = Blo;
    if (MODE == 0) {
        Bh += (size_t)blockIdx.y * 128 * KDIM;
        Bl += (size_t)blockIdx.y * 128 * KDIM;
    }

    float c[MT][NW][4];
    #pragma unroll
    for (int i = 0; i < MT; i++)
        #pragma unroll
        for (int j = 0; j < NW; j++)
            #pragma unroll
            for (int q = 0; q < 4; q++) c[i][j][q] = 0.f;

    mma_core<KDIM, MT, NW, RELU_A>(smem, sbase, A, Bh, Bl, rowBase, M, c);

    // ---- epilogue ----
    const int mBase = (wid >> 2) * (MT * 16);
    const int nBase = (wid & 3) * (NW * 8);
    const int gid = lane >> 2;
    const int tig = lane & 3;
    #pragma unroll
    for (int mt = 0; mt < MT; mt++) {
        #pragma unroll
        for (int nt = 0; nt < NW; nt++) {
            int col  = nBase + nt * 8 + tig * 2;
            int row0 = rowBase + mBase + mt * 16 + gid;
            int row1 = row0 + 8;

            float* dst; int ccol; int stride; float bx = 0.f, by = 0.f;
            if (MODE == 0) {
                dst = blockIdx.y ? C1 : C0; ccol = col; stride = 128;
                if (blockIdx.y) { bx = bias[col]; by = bias[col + 1]; }
            } else if (MODE == 1) {
                if (col < 64) { dst = C0; ccol = col;      stride = 64; }
                else          { dst = C1; ccol = col - 64; stride = 64;
                                bx = bias[ccol]; by = bias[ccol + 1]; }
            } else {
                dst = C0; ccol = col; stride = 128;
                bx = bias[col]; by = bias[col + 1];
            }

            float vx0 = c[mt][nt][0] + bx, vy0 = c[mt][nt][1] + by;
            float vx1 = c[mt][nt][2] + bx, vy1 = c[mt][nt][3] + by;
            if (RELU_OUT) {
                vx0 = fmaxf(vx0, 0.f); vy0 = fmaxf(vy0, 0.f);
                vx1 = fmaxf(vx1, 0.f); vy1 = fmaxf(vy1, 0.f);
            }
            if (row0 < M) {
                float2 v; v.x = vx0; v.y = vy0;
                *(float2*)(dst + (size_t)row0 * stride + ccol) = v;
            }
            if (row1 < M) {
                float2 v; v.x = vx1; v.y = vy1;
                *(float2*)(dst + (size_t)row1 * stride + ccol) = v;
            }
        }
    }
}

// ---------------------------------------------------------------------------
// mlp2 + head on the mma core: H4 = relu(H3 @ L2w + L2b) (tile in smem),
// then out = log_softmax(H4 @ L3w + b3). Tile M64 x N64, K=128.
// ---------------------------------------------------------------------------
__global__ void __launch_bounds__(256)
mlp2_head_mma_kernel(const float* __restrict__ A,     // H3 [M,128]
                     const __nv_bfloat16* __restrict__ Bhi,
                     const __nv_bfloat16* __restrict__ Blo,
                     const float* __restrict__ b,     // L2b [64]
                     const float* __restrict__ W3,    // L3w [64,10]
                     const float* __restrict__ b3,
                     float* __restrict__ out, int M)
{
    constexpr int MT = 2, NW = 2, KDIM = 128;
    constexpr int BM = 64, BN = 64;
    __shared__ char smem[2 * (BM + BN) * 64];    // 16 KB
    __shared__ float Ct[BM][BN + 4];
    __shared__ float W3s[D4 * NCLS];
    __shared__ float b3s[NCLS];
    const uint32_t sbase = smem_u32(smem);

    const int tid  = threadIdx.x;
    const int wid  = tid >> 5;
    const int lane = tid & 31;
    const int rowBase = blockIdx.x * BM;

    for (int i = tid; i < D4 * NCLS; i += 256) W3s[i] = W3[i];
    if (tid < NCLS) b3s[tid] = b3[tid];
    // covered by first __syncthreads inside mma_core

    float c[MT][NW][4];
    #pragma unroll
    for (int i = 0; i < MT; i++)
        #pragma unroll
        for (int j = 0; j < NW; j++)
            #pragma unroll
            for (int q = 0; q < 4; q++) c[i][j][q] = 0.f;

    mma_core<KDIM, MT, NW, false>(smem, sbase, A, Bhi, Blo, rowBase, M, c);

    // ---- epilogue: bias + relu -> Ct ----
    const int mBase = (wid >> 2) * (MT * 16);
    const int nBase = (wid & 3) * (NW * 8);
    const int gid = lane >> 2;
    const int tig = lane & 3;
    #pragma unroll
    for (int mt = 0; mt < MT; mt++) {
        #pragma unroll
        for (int nt = 0; nt < NW; nt++) {
            int col = nBase + nt * 8 + tig * 2;
            int r0  = mBase + mt * 16 + gid;
            float bx = b[col], by = b[col + 1];
            Ct[r0][col]         = fmaxf(c[mt][nt][0] + bx, 0.f);
            Ct[r0][col + 1]     = fmaxf(c[mt][nt][1] + by, 0.f);
            Ct[r0 + 8][col]     = fmaxf(c[mt][nt][2] + bx, 0.f);
            Ct[r0 + 8][col + 1] = fmaxf(c[mt][nt][3] + by, 0.f);
        }
    }
    __syncthreads();

    // ---- head: per-warp logits + log_softmax ----
    #pragma unroll
    for (int rr = 0; rr < 8; rr++) {
        int r  = wid * 8 + rr;
        int gr = rowBase + r;
        if (gr >= M) continue;

        float acc2 = -1e30f;
        if (lane < NCLS) {
            acc2 = b3s[lane];
            #pragma unroll 8
            for (int k = 0; k < D4; k++)
                acc2 = fmaf(Ct[r][k], W3s[k * NCLS + lane], acc2);
        }
        float m = acc2;
        #pragma unroll
        for (int o = 16; o > 0; o >>= 1)
            m = fmaxf(m, __shfl_xor_sync(0xffffffffu, m, o));
        float ex = (lane < NCLS) ? expf(acc2 - m) : 0.f;
        float ssum = ex;
        #pragma unroll
        for (int o = 16; o > 0; o >>= 1)
            ssum += __shfl_xor_sync(0xffffffffu, ssum, o);
        float lse = m + logf(ssum);
        if (lane < NCLS)
            out[(size_t)gr * NCLS + lane] = acc2 - lse;
    }
}

// ---------------------------------------------------------------------------
// Batched edge scatters (measured win in R4)
// ---------------------------------------------------------------------------
__global__ void __launch_bounds__(256)
scatter_add128_kernel(const float* __restrict__ src_feat,
                      float* __restrict__ dst_feat,
                      const int* __restrict__ ei, int nEdges)
{
    const int w    = blockIdx.x * (blockDim.x >> 5) + (threadIdx.x >> 5);
    const int lane = threadIdx.x & 31;
    const int eb   = w * 8;
    if (eb >= nEdges) return;
    const int n = min(8, nEdges - eb);

    int idx = 0;
    if (lane < 8) {
        if (lane < n) idx = ei[eb + lane];
    } else if (lane < 16) {
        if (lane - 8 < n) idx = ei[nEdges + eb + (lane - 8)];
    }

    float4 v[8];
    #pragma unroll
    for (int i = 0; i < 8; i++) {
        int s = __shfl_sync(0xffffffffu, idx, i);
        if (i < n)
            v[i] = *(const float4*)(src_feat + (size_t)s * 128 + lane * 4);
    }
    #pragma unroll
    for (int i = 0; i < 8; i++) {
        int d = __shfl_sync(0xffffffffu, idx, 8 + i);
        if (i < n) {
            float* dp = dst_feat + (size_t)d * 128 + lane * 4;
            asm volatile("red.global.add.v4.f32 [%0], {%1,%2,%3,%4};"
                         :: "l"(dp), "f"(v[i].x), "f"(v[i].y), "f"(v[i].z), "f"(v[i].w)
                         : "memory");
        }
    }
}

__global__ void __launch_bounds__(256)
scatter_add64_kernel(const float* __restrict__ src_feat,
                     float* __restrict__ dst_feat,
                     const int* __restrict__ ei, int nEdges)
{
    const int w    = blockIdx.x * (blockDim.x >> 5) + (threadIdx.x >> 5);
    const int lane = threadIdx.x & 31;
    const int eb   = w * 16;
    if (eb >= nEdges) return;
    const int n    = min(16, nEdges - eb);
    const int half = lane >> 4;
    const int sub  = lane & 15;

    int idx = 0;
    if (lane < 16) {
        if (lane < n) idx = ei[eb + lane];
    } else {
        if (lane - 16 < n) idx = ei[nEdges + eb + (lane - 16)];
    }

    float4 v[8];
    #pragma unroll
    for (int it = 0; it < 8; it++) {
        int e = it * 2 + half;
        int s = __shfl_sync(0xffffffffu, idx, e);
        if (e < n)
            v[it] = *(const float4*)(src_feat + (size_t)s * 64 + sub * 4);
    }
    #pragma unroll
    for (int it = 0; it < 8; it++) {
        int e = it * 2 + half;
        int d = __shfl_sync(0xffffffffu, idx, 16 + e);
        if (e < n) {
            float* dp = dst_feat + (size_t)d * 64 + sub * 4;
            asm volatile("red.global.add.v4.f32 [%0], {%1,%2,%3,%4};"
                         :: "l"(dp), "f"(v[it].x), "f"(v[it].y), "f"(v[it].z), "f"(v[it].w)
                         : "memory");
        }
    }
}

// ---------------------------------------------------------------------------
// Launch
// ---------------------------------------------------------------------------
extern "C" void kernel_launch(void* const* d_in, const int* in_sizes, int n_in,
                              void* d_out, int out_size)
{
    const float* x      = (const float*)d_in[0];
    const int*   ei     = (const int*)d_in[1];
    const float* W1_rel = (const float*)d_in[2];
    const float* W1_rt  = (const float*)d_in[3];
    const float* b1     = (const float*)d_in[4];
    const float* W2_rel = (const float*)d_in[5];
    const float* W2_rt  = (const float*)d_in[6];
    const float* b2     = (const float*)d_in[7];
    const float* L1w    = (const float*)d_in[8];
    const float* L1b    = (const float*)d_in[9];
    const float* L2w    = (const float*)d_in[10];
    const float* L2b    = (const float*)d_in[11];
    const float* L3w    = (const float*)d_in[12];
    const float* L3b    = (const float*)d_in[13];
    float*       out    = (float*)d_out;

    const int M  = in_sizes[0] / DIN;   // 20000
    const int nE = in_sizes[1] / 2;     // 320000

    float *XR, *H1, *XR2, *H2, *H3;
    __nv_bfloat16 *B1hi, *B1lo, *B2hi, *B2lo, *B3hi, *B3lo, *B4hi, *B4lo;
    cudaGetSymbolAddress((void**)&XR,   g_XR);
    cudaGetSymbolAddress((void**)&H1,   g_H1);
    cudaGetSymbolAddress((void**)&XR2,  g_XR2);
    cudaGetSymbolAddress((void**)&H2,   g_H2);
    cudaGetSymbolAddress((void**)&H3,   g_H3);
    cudaGetSymbolAddress((void**)&B1hi, g_B1hi);
    cudaGetSymbolAddress((void**)&B1lo, g_B1lo);
    cudaGetSymbolAddress((void**)&B2hi, g_B2hi);
    cudaGetSymbolAddress((void**)&B2lo, g_B2lo);
    cudaGetSymbolAddress((void**)&B3hi, g_B3hi);
    cudaGetSymbolAddress((void**)&B3lo, g_B3lo);
    cudaGetSymbolAddress((void**)&B4hi, g_B4hi);
    cudaGetSymbolAddress((void**)&B4lo, g_B4lo);

    const int gM64 = (M + 63) / 64;   // 313

    // weight prep (all layers)
    {
        int ntot = NW1 + NW2 + NW3 + NW4;
        prep_weights_kernel<<<(ntot + 255) / 256, 256>>>(W1_rel, W1_rt, W2_rel,
                                                         W2_rt, L1w, L2w);
    }

    // conv1: XR = x@W1_rel ; H1 = x@W1_root + b1
    mma_gemm_kernel<256, 0, false, false>
        <<<dim3(gM64, 2), 256>>>(x, B1hi, B1lo, b1, XR, H1, M);

    // H1[dst] += XR[src]
    {
        int warps = (nE + 7) / 8;
        int blks  = (warps + 7) / 8;
        scatter_add128_kernel<<<blks, 256>>>(XR, H1, ei, nE);
    }

    // conv2 (both outputs): XR2 = relu(H1)@W2_rel ; H2 = relu(H1)@W2_root + b2
    mma_gemm_kernel<128, 1, true, false>
        <<<gM64, 256>>>(H1, B2hi, B2lo, b2, XR2, H2, M);

    // H2[dst] += XR2[src]
    {
        int warps = (nE + 15) / 16;
        int blks  = (warps + 7) / 8;
        scatter_add64_kernel<<<blks, 256>>>(XR2, H2, ei, nE);
    }

    // mlp1: H3 = relu(H2 @ L1w + L1b)
    mma_gemm_kernel<64, 2, false, true>
        <<<gM64, 256>>>(H2, B3hi, B3lo, L1b, H3, nullptr, M);

    // mlp2 + head (mma)
    mlp2_head_mma_kernel<<<gM64, 256>>>(H3, B4hi, B4lo, L2b, L3w, L3b, out, M);
}

// round 12
// speedup vs baseline: 2.2828x; 1.0774x over previous
#include <cuda_runtime.h>
#include <cuda_bf16.h>
#include <math.h>
#include <stdint.h>

// ---------------------------------------------------------------------------
// Problem constants
// ---------------------------------------------------------------------------
#define N_NODES_MAX 20000
#define DIN 256
#define D1 128
#define D2 64
#define D3 128
#define D4 64
#define NCLS 10

// ---------------------------------------------------------------------------
// Scratch (static device globals; no allocations anywhere)
// ---------------------------------------------------------------------------
__device__ float g_XR [N_NODES_MAX * D1];
__device__ float g_H1 [N_NODES_MAX * D1];
__device__ float g_XR2[N_NODES_MAX * D2];
__device__ float g_H2 [N_NODES_MAX * D2];
__device__ float g_H3 [N_NODES_MAX * D3];

// bf16 hi/lo weights, transposed to [n][k] K-major
__device__ __nv_bfloat16 g_B1hi[2 * D1 * DIN];
__device__ __nv_bfloat16 g_B1lo[2 * D1 * DIN];
__device__ __nv_bfloat16 g_B2hi[128 * 128];
__device__ __nv_bfloat16 g_B2lo[128 * 128];
__device__ __nv_bfloat16 g_B3hi[128 * 64];
__device__ __nv_bfloat16 g_B3lo[128 * 64];
__device__ __nv_bfloat16 g_B4hi[64 * 128];
__device__ __nv_bfloat16 g_B4lo[64 * 128];

// ---------------------------------------------------------------------------
// mma.sync helpers
// ---------------------------------------------------------------------------
__device__ __forceinline__ uint32_t smem_u32(const void* p) {
    uint32_t a;
    asm("{ .reg .u64 t; cvta.to.shared.u64 t, %1; cvt.u32.u64 %0, t; }"
        : "=r"(a) : "l"(p));
    return a;
}
__device__ __forceinline__ void ldsm_x4(uint32_t& r0, uint32_t& r1,
                                        uint32_t& r2, uint32_t& r3,
                                        uint32_t addr) {
    asm volatile("ldmatrix.sync.aligned.m8n8.x4.shared.b16 {%0,%1,%2,%3}, [%4];"
                 : "=r"(r0), "=r"(r1), "=r"(r2), "=r"(r3) : "r"(addr));
}
__device__ __forceinline__ void mma_bf16(float& c0, float& c1, float& c2, float& c3,
                                         uint32_t a0, uint32_t a1, uint32_t a2, uint32_t a3,
                                         uint32_t b0, uint32_t b1) {
    asm volatile(
        "mma.sync.aligned.m16n8k16.row.col.f32.bf16.bf16.f32 "
        "{%0,%1,%2,%3}, {%4,%5,%6,%7}, {%8,%9}, {%0,%1,%2,%3};"
        : "+f"(c0), "+f"(c1), "+f"(c2), "+f"(c3)
        : "r"(a0), "r"(a1), "r"(a2), "r"(a3), "r"(b0), "r"(b1));
}

// ---------------------------------------------------------------------------
// Combined weight prep: fp32 -> bf16 hi/lo, transposed to [n][k]
// ---------------------------------------------------------------------------
#define NW1 (2 * DIN * D1)      // 65536
#define NW2 (128 * 128)         // 16384
#define NW3 (128 * 64)          // 8192
#define NW4 (64 * 128)          // 8192
__global__ void prep_weights_kernel(const float* __restrict__ W1rel,
                                    const float* __restrict__ W1rt,
                                    const float* __restrict__ W2rel,
                                    const float* __restrict__ W2rt,
                                    const float* __restrict__ L1w,
                                    const float* __restrict__ L2w)
{
    int idx = blockIdx.x * blockDim.x + threadIdx.x;
    float f;
    __nv_bfloat16* dh;
    __nv_bfloat16* dl;
    size_t off;
    if (idx < NW1) {
        int w   = idx / (DIN * D1);
        int rem = idx % (DIN * D1);
        int k   = rem / D1;
        int n   = rem % D1;
        f   = (w ? W1rt : W1rel)[k * D1 + n];
        off = (size_t)w * D1 * DIN + (size_t)n * DIN + k;
        dh = g_B1hi; dl = g_B1lo;
    } else if (idx < NW1 + NW2) {
        int i = idx - NW1;
        int n = i / 128;
        int k = i % 128;
        f   = (n < 64) ? W2rel[k * 64 + n] : W2rt[k * 64 + (n - 64)];
        off = (size_t)n * 128 + k;
        dh = g_B2hi; dl = g_B2lo;
    } else if (idx < NW1 + NW2 + NW3) {
        int i = idx - NW1 - NW2;
        int n = i / 64;
        int k = i % 64;
        f   = L1w[k * 128 + n];
        off = (size_t)n * 64 + k;
        dh = g_B3hi; dl = g_B3lo;
    } else if (idx < NW1 + NW2 + NW3 + NW4) {
        int i = idx - NW1 - NW2 - NW3;
        int n = i / 128;
        int k = i % 128;
        f   = L2w[k * 64 + n];
        off = (size_t)n * 128 + k;
        dh = g_B4hi; dl = g_B4lo;
    } else return;

    __nv_bfloat16 h = __float2bfloat16(f);
    dh[off] = h;
    dl[off] = __float2bfloat16(f - __bfloat162float(h));
}

// ---------------------------------------------------------------------------
// Pipelined mma core (register prefetch, 80B row stride => conflict-free
// ldmatrix). BM fixed at 64 (MT=2). NW in {2,4}. 8 warps = 2(m) x 4(n).
// smem buffer: 2*(64+BN)*80 bytes:
//   [0, 64*80)  A hi   [64*80, 2*64*80)  A lo
//   [2*64*80, +BN*80)  B hi   [.., +BN*80)  B lo
// ---------------------------------------------------------------------------
template<int KDIM, int MT, int NW, bool RELU_A>
__device__ __forceinline__ void mma_core(
    char* smem, uint32_t sbase,
    const float* __restrict__ A,
    const __nv_bfloat16* __restrict__ Bh,
    const __nv_bfloat16* __restrict__ Bl,
    int rowBase, int M,
    float c[MT][NW][4])
{
    constexpr int BM = 2 * MT * 16;
    static_assert(BM == 64, "core assumes BM=64");
    constexpr int BN = 4 * NW * 8;
    constexpr int RS = 80;                    // bytes per 64B row (padded)
    constexpr int OFF_AL = BM * RS;
    constexpr int OFF_BH = 2 * BM * RS;
    constexpr int OFF_BL = 2 * BM * RS + BN * RS;
    constexpr int BIT = BN / 64;              // B stage iterations (1 or 2)
    constexpr int NCH = KDIM / 32;

    const int tid  = threadIdx.x;
    const int wid  = tid >> 5;
    const int lane = tid & 31;

    const int mBase = (wid >> 2) * (MT * 16);
    const int nBase = (wid & 3) * (NW * 8);

    const int qr    = lane & 7;
    const int half1 = (lane >> 3) & 1;
    const int half2 = (lane >> 4) & 1;

    // stage slots
    const int rA  = tid >> 2;       // 0..63
    const int kcA = tid & 3;
    const int gA  = rowBase + rA;

    // prefetch registers
    float aR[8];
    uint4 bhR[BIT], blR[BIT];

    // ---- prologue: load chunk 0 ----
    {
        if (gA < M) {
            const float* ap = A + (size_t)gA * KDIM + kcA * 8;
            float4 x0 = *(const float4*)ap;
            float4 x1 = *(const float4*)(ap + 4);
            aR[0]=x0.x; aR[1]=x0.y; aR[2]=x0.z; aR[3]=x0.w;
            aR[4]=x1.x; aR[5]=x1.y; aR[6]=x1.z; aR[7]=x1.w;
        } else {
            #pragma unroll
            for (int j = 0; j < 8; j++) aR[j] = 0.f;
        }
        #pragma unroll
        for (int it = 0; it < BIT; it++) {
            int i = tid + it * 256;
            int r = i >> 2, kc = i & 3;
            bhR[it] = *(const uint4*)(Bh + (size_t)r * KDIM + kc * 8);
            blR[it] = *(const uint4*)(Bl + (size_t)r * KDIM + kc * 8);
        }
    }

    for (int ch = 0; ch < NCH; ch++) {
        // ---- convert + store staged regs to smem ----
        {
            __nv_bfloat16 h[8], l[8];
            #pragma unroll
            for (int j = 0; j < 8; j++) {
                float fv = RELU_A ? fmaxf(aR[j], 0.f) : aR[j];
                h[j] = __float2bfloat16(fv);
                l[j] = __float2bfloat16(fv - __bfloat162float(h[j]));
            }
            uint32_t soA = (uint32_t)(rA * RS + kcA * 16);
            *(uint4*)(smem + soA) = *(uint4*)h;
            *(uint4*)(smem + OFF_AL + soA) = *(uint4*)l;
            #pragma unroll
            for (int it = 0; it < BIT; it++) {
                int i = tid + it * 256;
                int r = i >> 2, kc = i & 3;
                uint32_t soB = (uint32_t)(r * RS + kc * 16);
                *(uint4*)(smem + OFF_BH + soB) = bhR[it];
                *(uint4*)(smem + OFF_BL + soB) = blR[it];
            }
        }
        __syncthreads();

        // ---- prefetch next chunk into registers ----
        if (ch + 1 < NCH) {
            const int k0 = (ch + 1) * 32;
            if (gA < M) {
                const float* ap = A + (size_t)gA * KDIM + k0 + kcA * 8;
                float4 x0 = *(const float4*)ap;
                float4 x1 = *(const float4*)(ap + 4);
                aR[0]=x0.x; aR[1]=x0.y; aR[2]=x0.z; aR[3]=x0.w;
                aR[4]=x1.x; aR[5]=x1.y; aR[6]=x1.z; aR[7]=x1.w;
            } else {
                #pragma unroll
                for (int j = 0; j < 8; j++) aR[j] = 0.f;
            }
            #pragma unroll
            for (int it = 0; it < BIT; it++) {
                int i = tid + it * 256;
                int r = i >> 2, kc = i & 3;
                bhR[it] = *(const uint4*)(Bh + (size_t)r * KDIM + k0 + kc * 8);
                blR[it] = *(const uint4*)(Bl + (size_t)r * KDIM + k0 + kc * 8);
            }
        }

        // ---- compute: 2 k16 steps ----
        #pragma unroll
        for (int ks = 0; ks < 2; ks++) {
            uint32_t ah[MT][4], al[MT][4];
            #pragma unroll
            for (int mt = 0; mt < MT; mt++) {
                int r = mBase + mt * 16 + qr + half1 * 8;
                uint32_t so = (uint32_t)(r * RS + (ks * 2 + half2) * 16);
                ldsm_x4(ah[mt][0], ah[mt][1], ah[mt][2], ah[mt][3], sbase + so);
                ldsm_x4(al[mt][0], al[mt][1], al[mt][2], al[mt][3],
                        sbase + OFF_AL + so);
            }
            uint32_t bh[NW / 2][4], bl[NW / 2][4];
            #pragma unroll
            for (int pr = 0; pr < NW / 2; pr++) {
                int r = nBase + pr * 16 + qr + half2 * 8;
                uint32_t so = (uint32_t)(r * RS + (ks * 2 + half1) * 16);
                ldsm_x4(bh[pr][0], bh[pr][1], bh[pr][2], bh[pr][3],
                        sbase + OFF_BH + so);
                ldsm_x4(bl[pr][0], bl[pr][1], bl[pr][2], bl[pr][3],
                        sbase + OFF_BL + so);
            }
            #pragma unroll
            for (int mt = 0; mt < MT; mt++) {
                #pragma unroll
                for (int nt = 0; nt < NW; nt++) {
                    uint32_t b0h = bh[nt >> 1][(nt & 1) * 2];
                    uint32_t b1h = bh[nt >> 1][(nt & 1) * 2 + 1];
                    uint32_t b0l = bl[nt >> 1][(nt & 1) * 2];
                    uint32_t b1l = bl[nt >> 1][(nt & 1) * 2 + 1];
                    float* cc = c[mt][nt];
                    mma_bf16(cc[0], cc[1], cc[2], cc[3],
                             ah[mt][0], ah[mt][1], ah[mt][2], ah[mt][3], b0h, b1h);
                    mma_bf16(cc[0], cc[1], cc[2], cc[3],
                             ah[mt][0], ah[mt][1], ah[mt][2], ah[mt][3], b0l, b1l);
                    mma_bf16(cc[0], cc[1], cc[2], cc[3],
                             al[mt][0], al[mt][1], al[mt][2], al[mt][3], b0h, b1h);
                }
            }
        }
        __syncthreads();
    }
}

// ---------------------------------------------------------------------------
// GEMM kernels on the mma core.
//   MODE 0 (conv1): blockIdx.y selects B slot / dst; bias for y==1. stride 128.
//   MODE 1 (conv2): cols<64 -> C0 (stride 64); cols>=64 -> C1+bias (stride 64).
//   MODE 2 (mlp1):  C0 stride 128, bias+relu.
// ---------------------------------------------------------------------------
template<int KDIM, int MODE, bool RELU_A, bool RELU_OUT>
__global__ void __launch_bounds__(256, 2)
mma_gemm_kernel(const float* __restrict__ A,
                const __nv_bfloat16* __restrict__ Bhi,
                const __nv_bfloat16* __restrict__ Blo,
                const float* __restrict__ bias,
                float* __restrict__ C0, float* __restrict__ C1, int M)
{
    constexpr int MT = 2, NW = 4;
    constexpr int BM = 64;
    constexpr int BN = 128;
    __shared__ char smem[2 * (BM + BN) * 80];   // 30720 B
    const uint32_t sbase = smem_u32(smem);

    const int wid  = threadIdx.x >> 5;
    const int lane = threadIdx.x & 31;
    const int rowBase = blockIdx.x * BM;

    const __nv_bfloat16* Bh = Bhi;
    const __nv_bfloat16* Bl = Blo;
    if (MODE == 0) {
        Bh += (size_t)blockIdx.y * 128 * KDIM;
        Bl += (size_t)blockIdx.y * 128 * KDIM;
    }

    float c[MT][NW][4];
    #pragma unroll
    for (int i = 0; i < MT; i++)
        #pragma unroll
        for (int j = 0; j < NW; j++)
            #pragma unroll
            for (int q = 0; q < 4; q++) c[i][j][q] = 0.f;

    mma_core<KDIM, MT, NW, RELU_A>(smem, sbase, A, Bh, Bl, rowBase, M, c);

    // ---- epilogue ----
    const int mBase = (wid >> 2) * (MT * 16);
    const int nBase = (wid & 3) * (NW * 8);
    const int gid = lane >> 2;
    const int tig = lane & 3;
    #pragma unroll
    for (int mt = 0; mt < MT; mt++) {
        #pragma unroll
        for (int nt = 0; nt < NW; nt++) {
            int col  = nBase + nt * 8 + tig * 2;
            int row0 = rowBase + mBase + mt * 16 + gid;
            int row1 = row0 + 8;

            float* dst; int ccol; int stride; float bx = 0.f, by = 0.f;
            if (MODE == 0) {
                dst = blockIdx.y ? C1 : C0; ccol = col; stride = 128;
                if (blockIdx.y) { bx = bias[col]; by = bias[col + 1]; }
            } else if (MODE == 1) {
                if (col < 64) { dst = C0; ccol = col;      stride = 64; }
                else          { dst = C1; ccol = col - 64; stride = 64;
                                bx = bias[ccol]; by = bias[ccol + 1]; }
            } else {
                dst = C0; ccol = col; stride = 128;
                bx = bias[col]; by = bias[col + 1];
            }

            float vx0 = c[mt][nt][0] + bx, vy0 = c[mt][nt][1] + by;
            float vx1 = c[mt][nt][2] + bx, vy1 = c[mt][nt][3] + by;
            if (RELU_OUT) {
                vx0 = fmaxf(vx0, 0.f); vy0 = fmaxf(vy0, 0.f);
                vx1 = fmaxf(vx1, 0.f); vy1 = fmaxf(vy1, 0.f);
            }
            if (row0 < M) {
                float2 v; v.x = vx0; v.y = vy0;
                *(float2*)(dst + (size_t)row0 * stride + ccol) = v;
            }
            if (row1 < M) {
                float2 v; v.x = vx1; v.y = vy1;
                *(float2*)(dst + (size_t)row1 * stride + ccol) = v;
            }
        }
    }
}

// ---------------------------------------------------------------------------
// mlp2 + head on the mma core. Tile M64 x N64, K=128.
// ---------------------------------------------------------------------------
__global__ void __launch_bounds__(256, 2)
mlp2_head_mma_kernel(const float* __restrict__ A,     // H3 [M,128]
                     const __nv_bfloat16* __restrict__ Bhi,
                     const __nv_bfloat16* __restrict__ Blo,
                     const float* __restrict__ b,     // L2b [64]
                     const float* __restrict__ W3,    // L3w [64,10]
                     const float* __restrict__ b3,
                     float* __restrict__ out, int M)
{
    constexpr int MT = 2, NW = 2, KDIM = 128;
    constexpr int BM = 64, BN = 64;
    __shared__ char smem[2 * (BM + BN) * 80];    // 20480 B
    __shared__ float Ct[BM][BN + 4];
    __shared__ float W3s[D4 * NCLS];
    __shared__ float b3s[NCLS];
    const uint32_t sbase = smem_u32(smem);

    const int tid  = threadIdx.x;
    const int wid  = tid >> 5;
    const int lane = tid & 31;
    const int rowBase = blockIdx.x * BM;

    for (int i = tid; i < D4 * NCLS; i += 256) W3s[i] = W3[i];
    if (tid < NCLS) b3s[tid] = b3[tid];
    // covered by first __syncthreads inside mma_core

    float c[MT][NW][4];
    #pragma unroll
    for (int i = 0; i < MT; i++)
        #pragma unroll
        for (int j = 0; j < NW; j++)
            #pragma unroll
            for (int q = 0; q < 4; q++) c[i][j][q] = 0.f;

    mma_core<KDIM, MT, NW, false>(smem, sbase, A, Bhi, Blo, rowBase, M, c);

    // ---- epilogue: bias + relu -> Ct ----
    const int mBase = (wid >> 2) * (MT * 16);
    const int nBase = (wid & 3) * (NW * 8);
    const int gid = lane >> 2;
    const int tig = lane & 3;
    #pragma unroll
    for (int mt = 0; mt < MT; mt++) {
        #pragma unroll
        for (int nt = 0; nt < NW; nt++) {
            int col = nBase + nt * 8 + tig * 2;
            int r0  = mBase + mt * 16 + gid;
            float bx = b[col], by = b[col + 1];
            Ct[r0][col]         = fmaxf(c[mt][nt][0] + bx, 0.f);
            Ct[r0][col + 1]     = fmaxf(c[mt][nt][1] + by, 0.f);
            Ct[r0 + 8][col]     = fmaxf(c[mt][nt][2] + bx, 0.f);
            Ct[r0 + 8][col + 1] = fmaxf(c[mt][nt][3] + by, 0.f);
        }
    }
    __syncthreads();

    // ---- head: per-warp logits + log_softmax ----
    #pragma unroll
    for (int rr = 0; rr < 8; rr++) {
        int r  = wid * 8 + rr;
        int gr = rowBase + r;
        if (gr >= M) continue;

        float acc2 = -1e30f;
        if (lane < NCLS) {
            acc2 = b3s[lane];
            #pragma unroll 8
            for (int k = 0; k < D4; k++)
                acc2 = fmaf(Ct[r][k], W3s[k * NCLS + lane], acc2);
        }
        float m = acc2;
        #pragma unroll
        for (int o = 16; o > 0; o >>= 1)
            m = fmaxf(m, __shfl_xor_sync(0xffffffffu, m, o));
        float ex = (lane < NCLS) ? expf(acc2 - m) : 0.f;
        float ssum = ex;
        #pragma unroll
        for (int o = 16; o > 0; o >>= 1)
            ssum += __shfl_xor_sync(0xffffffffu, ssum, o);
        float lse = m + logf(ssum);
        if (lane < NCLS)
            out[(size_t)gr * NCLS + lane] = acc2 - lse;
    }
}

// ---------------------------------------------------------------------------
// Batched edge scatters (measured win in R4)
// ---------------------------------------------------------------------------
__global__ void __launch_bounds__(256)
scatter_add128_kernel(const float* __restrict__ src_feat,
                      float* __restrict__ dst_feat,
                      const int* __restrict__ ei, int nEdges)
{
    const int w    = blockIdx.x * (blockDim.x >> 5) + (threadIdx.x >> 5);
    const int lane = threadIdx.x & 31;
    const int eb   = w * 8;
    if (eb >= nEdges) return;
    const int n = min(8, nEdges - eb);

    int idx = 0;
    if (lane < 8) {
        if (lane < n) idx = ei[eb + lane];
    } else if (lane < 16) {
        if (lane - 8 < n) idx = ei[nEdges + eb + (lane - 8)];
    }

    float4 v[8];
    #pragma unroll
    for (int i = 0; i < 8; i++) {
        int s = __shfl_sync(0xffffffffu, idx, i);
        if (i < n)
            v[i] = *(const float4*)(src_feat + (size_t)s * 128 + lane * 4);
    }
    #pragma unroll
    for (int i = 0; i < 8; i++) {
        int d = __shfl_sync(0xffffffffu, idx, 8 + i);
        if (i < n) {
            float* dp = dst_feat + (size_t)d * 128 + lane * 4;
            asm volatile("red.global.add.v4.f32 [%0], {%1,%2,%3,%4};"
                         :: "l"(dp), "f"(v[i].x), "f"(v[i].y), "f"(v[i].z), "f"(v[i].w)
                         : "memory");
        }
    }
}

__global__ void __launch_bounds__(256)
scatter_add64_kernel(const float* __restrict__ src_feat,
                     float* __restrict__ dst_feat,
                     const int* __restrict__ ei, int nEdges)
{
    const int w    = blockIdx.x * (blockDim.x >> 5) + (threadIdx.x >> 5);
    const int lane = threadIdx.x & 31;
    const int eb   = w * 16;
    if (eb >= nEdges) return;
    const int n    = min(16, nEdges - eb);
    const int half = lane >> 4;
    const int sub  = lane & 15;

    int idx = 0;
    if (lane < 16) {
        if (lane < n) idx = ei[eb + lane];
    } else {
        if (lane - 16 < n) idx = ei[nEdges + eb + (lane - 16)];
    }

    float4 v[8];
    #pragma unroll
    for (int it = 0; it < 8; it++) {
        int e = it * 2 + half;
        int s = __shfl_sync(0xffffffffu, idx, e);
        if (e < n)
            v[it] = *(const float4*)(src_feat + (size_t)s * 64 + sub * 4);
    }
    #pragma unroll
    for (int it = 0; it < 8; it++) {
        int e = it * 2 + half;
        int d = __shfl_sync(0xffffffffu, idx, 16 + e);
        if (e < n) {
            float* dp = dst_feat + (size_t)d * 64 + sub * 4;
            asm volatile("red.global.add.v4.f32 [%0], {%1,%2,%3,%4};"
                         :: "l"(dp), "f"(v[it].x), "f"(v[it].y), "f"(v[it].z), "f"(v[it].w)
                         : "memory");
        }
    }
}

// ---------------------------------------------------------------------------
// Launch
// ---------------------------------------------------------------------------
extern "C" void kernel_launch(void* const* d_in, const int* in_sizes, int n_in,
                              void* d_out, int out_size)
{
    const float* x      = (const float*)d_in[0];
    const int*   ei     = (const int*)d_in[1];
    const float* W1_rel = (const float*)d_in[2];
    const float* W1_rt  = (const float*)d_in[3];
    const float* b1     = (const float*)d_in[4];
    const float* W2_rel = (const float*)d_in[5];
    const float* W2_rt  = (const float*)d_in[6];
    const float* b2     = (const float*)d_in[7];
    const float* L1w    = (const float*)d_in[8];
    const float* L1b    = (const float*)d_in[9];
    const float* L2w    = (const float*)d_in[10];
    const float* L2b    = (const float*)d_in[11];
    const float* L3w    = (const float*)d_in[12];
    const float* L3b    = (const float*)d_in[13];
    float*       out    = (float*)d_out;

    const int M  = in_sizes[0] / DIN;   // 20000
    const int nE = in_sizes[1] / 2;     // 320000

    float *XR, *H1, *XR2, *H2, *H3;
    __nv_bfloat16 *B1hi, *B1lo, *B2hi, *B2lo, *B3hi, *B3lo, *B4hi, *B4lo;
    cudaGetSymbolAddress((void**)&XR,   g_XR);
    cudaGetSymbolAddress((void**)&H1,   g_H1);
    cudaGetSymbolAddress((void**)&XR2,  g_XR2);
    cudaGetSymbolAddress((void**)&H2,   g_H2);
    cudaGetSymbolAddress((void**)&H3,   g_H3);
    cudaGetSymbolAddress((void**)&B1hi, g_B1hi);
    cudaGetSymbolAddress((void**)&B1lo, g_B1lo);
    cudaGetSymbolAddress((void**)&B2hi, g_B2hi);
    cudaGetSymbolAddress((void**)&B2lo, g_B2lo);
    cudaGetSymbolAddress((void**)&B3hi, g_B3hi);
    cudaGetSymbolAddress((void**)&B3lo, g_B3lo);
    cudaGetSymbolAddress((void**)&B4hi, g_B4hi);
    cudaGetSymbolAddress((void**)&B4lo, g_B4lo);

    const int gM64 = (M + 63) / 64;   // 313

    // weight prep (all layers)
    {
        int ntot = NW1 + NW2 + NW3 + NW4;
        prep_weights_kernel<<<(ntot + 255) / 256, 256>>>(W1_rel, W1_rt, W2_rel,
                                                         W2_rt, L1w, L2w);
    }

    // conv1: XR = x@W1_rel ; H1 = x@W1_root + b1
    mma_gemm_kernel<256, 0, false, false>
        <<<dim3(gM64, 2), 256>>>(x, B1hi, B1lo, b1, XR, H1, M);

    // H1[dst] += XR[src]
    {
        int warps = (nE + 7) / 8;
        int blks  = (warps + 7) / 8;
        scatter_add128_kernel<<<blks, 256>>>(XR, H1, ei, nE);
    }

    // conv2 (both outputs): XR2 = relu(H1)@W2_rel ; H2 = relu(H1)@W2_root + b2
    mma_gemm_kernel<128, 1, true, false>
        <<<gM64, 256>>>(H1, B2hi, B2lo, b2, XR2, H2, M);

    // H2[dst] += XR2[src]
    {
        int warps = (nE + 15) / 16;
        int blks  = (warps + 7) / 8;
        scatter_add64_kernel<<<blks, 256>>>(XR2, H2, ei, nE);
    }

    // mlp1: H3 = relu(H2 @ L1w + L1b)
    mma_gemm_kernel<64, 2, false, true>
        <<<gM64, 256>>>(H2, B3hi, B3lo, L1b, H3, nullptr, M);

    // mlp2 + head (mma)
    mlp2_head_mma_kernel<<<gM64, 256>>>(H3, B4hi, B4lo, L2b, L3w, L3b, out, M);
}

// round 13
// speedup vs baseline: 2.3711x; 1.0387x over previous
#include <cuda_runtime.h>
#include <cuda_bf16.h>
#include <math.h>
#include <stdint.h>

// ---------------------------------------------------------------------------
// Problem constants
// ---------------------------------------------------------------------------
#define N_NODES_MAX 20000
#define DIN 256
#define D1 128
#define D2 64
#define D3 128
#define D4 64
#define NCLS 10

// ---------------------------------------------------------------------------
// Scratch (static device globals; no allocations anywhere)
// ---------------------------------------------------------------------------
__device__ float g_XR [N_NODES_MAX * D1];
__device__ float g_H1 [N_NODES_MAX * D1];
__device__ float g_XR2[N_NODES_MAX * D2];
__device__ float g_H2 [N_NODES_MAX * D2];

// bf16 hi/lo weights, transposed to [n][k] K-major
__device__ __nv_bfloat16 g_B1hi[2 * D1 * DIN];
__device__ __nv_bfloat16 g_B1lo[2 * D1 * DIN];
__device__ __nv_bfloat16 g_B2hi[128 * 128];
__device__ __nv_bfloat16 g_B2lo[128 * 128];
__device__ __nv_bfloat16 g_B3hi[128 * 64];
__device__ __nv_bfloat16 g_B3lo[128 * 64];
__device__ __nv_bfloat16 g_B4hi[64 * 128];
__device__ __nv_bfloat16 g_B4lo[64 * 128];

// ---------------------------------------------------------------------------
// mma.sync helpers
// ---------------------------------------------------------------------------
__device__ __forceinline__ uint32_t smem_u32(const void* p) {
    uint32_t a;
    asm("{ .reg .u64 t; cvta.to.shared.u64 t, %1; cvt.u32.u64 %0, t; }"
        : "=r"(a) : "l"(p));
    return a;
}
__device__ __forceinline__ void ldsm_x4(uint32_t& r0, uint32_t& r1,
                                        uint32_t& r2, uint32_t& r3,
                                        uint32_t addr) {
    asm volatile("ldmatrix.sync.aligned.m8n8.x4.shared.b16 {%0,%1,%2,%3}, [%4];"
                 : "=r"(r0), "=r"(r1), "=r"(r2), "=r"(r3) : "r"(addr));
}
__device__ __forceinline__ void mma_bf16(float& c0, float& c1, float& c2, float& c3,
                                         uint32_t a0, uint32_t a1, uint32_t a2, uint32_t a3,
                                         uint32_t b0, uint32_t b1) {
    asm volatile(
        "mma.sync.aligned.m16n8k16.row.col.f32.bf16.bf16.f32 "
        "{%0,%1,%2,%3}, {%4,%5,%6,%7}, {%8,%9}, {%0,%1,%2,%3};"
        : "+f"(c0), "+f"(c1), "+f"(c2), "+f"(c3)
        : "r"(a0), "r"(a1), "r"(a2), "r"(a3), "r"(b0), "r"(b1));
}

// ---------------------------------------------------------------------------
// Combined weight prep: fp32 -> bf16 hi/lo, transposed to [n][k]
// ---------------------------------------------------------------------------
#define NW1 (2 * DIN * D1)      // 65536
#define NW2 (128 * 128)         // 16384
#define NW3 (128 * 64)          // 8192
#define NW4 (64 * 128)          // 8192
__global__ void prep_weights_kernel(const float* __restrict__ W1rel,
                                    const float* __restrict__ W1rt,
                                    const float* __restrict__ W2rel,
                                    const float* __restrict__ W2rt,
                                    const float* __restrict__ L1w,
                                    const float* __restrict__ L2w)
{
    int idx = blockIdx.x * blockDim.x + threadIdx.x;
    float f;
    __nv_bfloat16* dh;
    __nv_bfloat16* dl;
    size_t off;
    if (idx < NW1) {
        int w   = idx / (DIN * D1);
        int rem = idx % (DIN * D1);
        int k   = rem / D1;
        int n   = rem % D1;
        f   = (w ? W1rt : W1rel)[k * D1 + n];
        off = (size_t)w * D1 * DIN + (size_t)n * DIN + k;
        dh = g_B1hi; dl = g_B1lo;
    } else if (idx < NW1 + NW2) {
        int i = idx - NW1;
        int n = i / 128;
        int k = i % 128;
        f   = (n < 64) ? W2rel[k * 64 + n] : W2rt[k * 64 + (n - 64)];
        off = (size_t)n * 128 + k;
        dh = g_B2hi; dl = g_B2lo;
    } else if (idx < NW1 + NW2 + NW3) {
        int i = idx - NW1 - NW2;
        int n = i / 64;
        int k = i % 64;
        f   = L1w[k * 128 + n];
        off = (size_t)n * 64 + k;
        dh = g_B3hi; dl = g_B3lo;
    } else if (idx < NW1 + NW2 + NW3 + NW4) {
        int i = idx - NW1 - NW2 - NW3;
        int n = i / 128;
        int k = i % 128;
        f   = L2w[k * 64 + n];
        off = (size_t)n * 128 + k;
        dh = g_B4hi; dl = g_B4lo;
    } else return;

    __nv_bfloat16 h = __float2bfloat16(f);
    dh[off] = h;
    dl[off] = __float2bfloat16(f - __bfloat162float(h));
}

// ---------------------------------------------------------------------------
// Pipelined mma core (register prefetch, 80B row stride => conflict-free
// ldmatrix). BM fixed at 64 (MT=2). NW in {2,4}. 8 warps = 2(m) x 4(n).
// A may live in GLOBAL or SHARED (generic pointer), row stride ASTRIDE floats.
// Staging buffer layout (from `smem` base):
//   [0, 64*80)  A hi   [64*80, 2*64*80)  A lo
//   [2*64*80, +BN*80)  B hi   [.., +BN*80)  B lo
// ---------------------------------------------------------------------------
template<int KDIM, int ASTRIDE, int MT, int NW, bool RELU_A>
__device__ __forceinline__ void mma_core(
    char* smem, uint32_t sbase,
    const float* __restrict__ A,
    const __nv_bfloat16* __restrict__ Bh,
    const __nv_bfloat16* __restrict__ Bl,
    int rowBase, int M,
    float c[MT][NW][4])
{
    constexpr int BM = 2 * MT * 16;
    static_assert(BM == 64, "core assumes BM=64");
    constexpr int BN = 4 * NW * 8;
    constexpr int RS = 80;
    constexpr int OFF_AL = BM * RS;
    constexpr int OFF_BH = 2 * BM * RS;
    constexpr int OFF_BL = 2 * BM * RS + BN * RS;
    constexpr int BIT = BN / 64;
    constexpr int NCH = KDIM / 32;

    const int tid  = threadIdx.x;
    const int wid  = tid >> 5;
    const int lane = tid & 31;

    const int mBase = (wid >> 2) * (MT * 16);
    const int nBase = (wid & 3) * (NW * 8);

    const int qr    = lane & 7;
    const int half1 = (lane >> 3) & 1;
    const int half2 = (lane >> 4) & 1;

    const int rA  = tid >> 2;
    const int kcA = tid & 3;
    const int gA  = rowBase + rA;

    float aR[8];
    uint4 bhR[BIT], blR[BIT];

    // ---- prologue: load chunk 0 ----
    {
        if (gA < M) {
            const float* ap = A + (size_t)gA * ASTRIDE + kcA * 8;
            float4 x0 = *(const float4*)ap;
            float4 x1 = *(const float4*)(ap + 4);
            aR[0]=x0.x; aR[1]=x0.y; aR[2]=x0.z; aR[3]=x0.w;
            aR[4]=x1.x; aR[5]=x1.y; aR[6]=x1.z; aR[7]=x1.w;
        } else {
            #pragma unroll
            for (int j = 0; j < 8; j++) aR[j] = 0.f;
        }
        #pragma unroll
        for (int it = 0; it < BIT; it++) {
            int i = tid + it * 256;
            int r = i >> 2, kc = i & 3;
            bhR[it] = *(const uint4*)(Bh + (size_t)r * KDIM + kc * 8);
            blR[it] = *(const uint4*)(Bl + (size_t)r * KDIM + kc * 8);
        }
    }

    for (int ch = 0; ch < NCH; ch++) {
        // ---- convert + store staged regs to smem ----
        {
            __nv_bfloat16 h[8], l[8];
            #pragma unroll
            for (int j = 0; j < 8; j++) {
                float fv = RELU_A ? fmaxf(aR[j], 0.f) : aR[j];
                h[j] = __float2bfloat16(fv);
                l[j] = __float2bfloat16(fv - __bfloat162float(h[j]));
            }
            uint32_t soA = (uint32_t)(rA * RS + kcA * 16);
            *(uint4*)(smem + soA) = *(uint4*)h;
            *(uint4*)(smem + OFF_AL + soA) = *(uint4*)l;
            #pragma unroll
            for (int it = 0; it < BIT; it++) {
                int i = tid + it * 256;
                int r = i >> 2, kc = i & 3;
                uint32_t soB = (uint32_t)(r * RS + kc * 16);
                *(uint4*)(smem + OFF_BH + soB) = bhR[it];
                *(uint4*)(smem + OFF_BL + soB) = blR[it];
            }
        }
        __syncthreads();

        // ---- prefetch next chunk into registers ----
        if (ch + 1 < NCH) {
            const int k0 = (ch + 1) * 32;
            if (gA < M) {
                const float* ap = A + (size_t)gA * ASTRIDE + k0 + kcA * 8;
                float4 x0 = *(const float4*)ap;
                float4 x1 = *(const float4*)(ap + 4);
                aR[0]=x0.x; aR[1]=x0.y; aR[2]=x0.z; aR[3]=x0.w;
                aR[4]=x1.x; aR[5]=x1.y; aR[6]=x1.z; aR[7]=x1.w;
            } else {
                #pragma unroll
                for (int j = 0; j < 8; j++) aR[j] = 0.f;
            }
            #pragma unroll
            for (int it = 0; it < BIT; it++) {
                int i = tid + it * 256;
                int r = i >> 2, kc = i & 3;
                bhR[it] = *(const uint4*)(Bh + (size_t)r * KDIM + k0 + kc * 8);
                blR[it] = *(const uint4*)(Bl + (size_t)r * KDIM + k0 + kc * 8);
            }
        }

        // ---- compute: 2 k16 steps ----
        #pragma unroll
        for (int ks = 0; ks < 2; ks++) {
            uint32_t ah[MT][4], al[MT][4];
            #pragma unroll
            for (int mt = 0; mt < MT; mt++) {
                int r = mBase + mt * 16 + qr + half1 * 8;
                uint32_t so = (uint32_t)(r * RS + (ks * 2 + half2) * 16);
                ldsm_x4(ah[mt][0], ah[mt][1], ah[mt][2], ah[mt][3], sbase + so);
                ldsm_x4(al[mt][0], al[mt][1], al[mt][2], al[mt][3],
                        sbase + OFF_AL + so);
            }
            uint32_t bh[NW / 2][4], bl[NW / 2][4];
            #pragma unroll
            for (int pr = 0; pr < NW / 2; pr++) {
                int r = nBase + pr * 16 + qr + half2 * 8;
                uint32_t so = (uint32_t)(r * RS + (ks * 2 + half1) * 16);
                ldsm_x4(bh[pr][0], bh[pr][1], bh[pr][2], bh[pr][3],
                        sbase + OFF_BH + so);
                ldsm_x4(bl[pr][0], bl[pr][1], bl[pr][2], bl[pr][3],
                        sbase + OFF_BL + so);
            }
            #pragma unroll
            for (int mt = 0; mt < MT; mt++) {
                #pragma unroll
                for (int nt = 0; nt < NW; nt++) {
                    uint32_t b0h = bh[nt >> 1][(nt & 1) * 2];
                    uint32_t b1h = bh[nt >> 1][(nt & 1) * 2 + 1];
                    uint32_t b0l = bl[nt >> 1][(nt & 1) * 2];
                    uint32_t b1l = bl[nt >> 1][(nt & 1) * 2 + 1];
                    float* cc = c[mt][nt];
                    mma_bf16(cc[0], cc[1], cc[2], cc[3],
                             ah[mt][0], ah[mt][1], ah[mt][2], ah[mt][3], b0h, b1h);
                    mma_bf16(cc[0], cc[1], cc[2], cc[3],
                             ah[mt][0], ah[mt][1], ah[mt][2], ah[mt][3], b0l, b1l);
                    mma_bf16(cc[0], cc[1], cc[2], cc[3],
                             al[mt][0], al[mt][1], al[mt][2], al[mt][3], b0h, b1h);
                }
            }
        }
        __syncthreads();
    }
}

// ---------------------------------------------------------------------------
// conv GEMM kernels on the mma core.
//   MODE 0 (conv1): blockIdx.y selects B slot / dst; bias for y==1. stride 128.
//   MODE 1 (conv2): cols<64 -> C0 (stride 64); cols>=64 -> C1+bias (stride 64).
// ---------------------------------------------------------------------------
template<int KDIM, int MODE, bool RELU_A>
__global__ void __launch_bounds__(256, 2)
mma_gemm_kernel(const float* __restrict__ A,
                const __nv_bfloat16* __restrict__ Bhi,
                const __nv_bfloat16* __restrict__ Blo,
                const float* __restrict__ bias,
                float* __restrict__ C0, float* __restrict__ C1, int M)
{
    constexpr int MT = 2, NW = 4;
    constexpr int BM = 64;
    constexpr int BN = 128;
    __shared__ char smem[2 * (BM + BN) * 80];   // 30720 B
    const uint32_t sbase = smem_u32(smem);

    const int wid  = threadIdx.x >> 5;
    const int lane = threadIdx.x & 31;
    const int rowBase = blockIdx.x * BM;

    const __nv_bfloat16* Bh = Bhi;
    const __nv_bfloat16* Bl = Blo;
    if (MODE == 0) {
        Bh += (size_t)blockIdx.y * 128 * KDIM;
        Bl += (size_t)blockIdx.y * 128 * KDIM;
    }

    float c[MT][NW][4];
    #pragma unroll
    for (int i = 0; i < MT; i++)
        #pragma unroll
        for (int j = 0; j < NW; j++)
            #pragma unroll
            for (int q = 0; q < 4; q++) c[i][j][q] = 0.f;

    mma_core<KDIM, KDIM, MT, NW, RELU_A>(smem, sbase, A, Bh, Bl, rowBase, M, c);

    // ---- epilogue ----
    const int mBase = (wid >> 2) * (MT * 16);
    const int nBase = (wid & 3) * (NW * 8);
    const int gid = lane >> 2;
    const int tig = lane & 3;
    #pragma unroll
    for (int mt = 0; mt < MT; mt++) {
        #pragma unroll
        for (int nt = 0; nt < NW; nt++) {
            int col  = nBase + nt * 8 + tig * 2;
            int row0 = rowBase + mBase + mt * 16 + gid;
            int row1 = row0 + 8;

            float* dst; int ccol; int stride; float bx = 0.f, by = 0.f;
            if (MODE == 0) {
                dst = blockIdx.y ? C1 : C0; ccol = col; stride = 128;
                if (blockIdx.y) { bx = bias[col]; by = bias[col + 1]; }
            } else {
                if (col < 64) { dst = C0; ccol = col;      stride = 64; }
                else          { dst = C1; ccol = col - 64; stride = 64;
                                bx = bias[ccol]; by = bias[ccol + 1]; }
            }

            float vx0 = c[mt][nt][0] + bx, vy0 = c[mt][nt][1] + by;
            float vx1 = c[mt][nt][2] + bx, vy1 = c[mt][nt][3] + by;
            if (row0 < M) {
                float2 v; v.x = vx0; v.y = vy0;
                *(float2*)(dst + (size_t)row0 * stride + ccol) = v;
            }
            if (row1 < M) {
                float2 v; v.x = vx1; v.y = vy1;
                *(float2*)(dst + (size_t)row1 * stride + ccol) = v;
            }
        }
    }
}

// ---------------------------------------------------------------------------
// Fused MLP: H3 = relu(H2@L1w+L1b) kept in SMEM; H4 = relu(H3@L2w+L2b);
// out = log_softmax(H4@L3w + b3). One kernel, 64 rows per block.
// Dynamic smem layout (manual temporal aliasing):
//   [0, 30720)        mma staging (phase1 NW=4: 30720; phase2 NW=2: 20480)
//   [30720, 64512)    H3 tile fp32, 64 x 132 stride  (alias: H4/Ct later)
//   [64512, 67072)    W3s (64*10 fp32)
//   [67072, 67112)    b3s
// ---------------------------------------------------------------------------
#define FUSED_STAGE   0
#define FUSED_H3OFF   30720
#define FUSED_H3STR   132
#define FUSED_W3OFF   64512
#define FUSED_B3OFF   67072
#define FUSED_SMEM    67200
#define FUSED_CTSTR   68

__global__ void __launch_bounds__(256, 2)
mlp_fused_kernel(const float* __restrict__ A,      // H2 [M,64]
                 const __nv_bfloat16* __restrict__ B3hi,
                 const __nv_bfloat16* __restrict__ B3lo,
                 const float* __restrict__ L1b,    // [128]
                 const __nv_bfloat16* __restrict__ B4hi,
                 const __nv_bfloat16* __restrict__ B4lo,
                 const float* __restrict__ L2b,    // [64]
                 const float* __restrict__ W3,     // [64,10]
                 const float* __restrict__ b3,
                 float* __restrict__ out, int M)
{
    extern __shared__ char dsm[];
    const uint32_t sbase = smem_u32(dsm);
    float* H3t = (float*)(dsm + FUSED_H3OFF);
    float* Ct  = (float*)(dsm + FUSED_H3OFF);     // alias, used after phase 2
    float* W3s = (float*)(dsm + FUSED_W3OFF);
    float* b3s = (float*)(dsm + FUSED_B3OFF);

    const int tid  = threadIdx.x;
    const int wid  = tid >> 5;
    const int lane = tid & 31;
    const int rowBase = blockIdx.x * 64;
    const int Mloc = min(64, M - rowBase);

    for (int i = tid; i < D4 * NCLS; i += 256) W3s[i] = W3[i];
    if (tid < NCLS) b3s[tid] = b3[tid];
    // ordered before use by syncs inside mma_core + later syncs

    const int mBase = (wid >> 2) * 32;
    const int gid = lane >> 2;
    const int tig = lane & 3;

    // ---- phase 1: H3 tile = relu(H2 @ L1w + L1b), N=128 ----
    {
        float c1[2][4][4];
        #pragma unroll
        for (int i = 0; i < 2; i++)
            #pragma unroll
            for (int j = 0; j < 4; j++)
                #pragma unroll
                for (int q = 0; q < 4; q++) c1[i][j][q] = 0.f;

        mma_core<64, 64, 2, 4, false>(dsm, sbase, A, B3hi, B3lo, rowBase, M, c1);

        const int nBase = (wid & 3) * 32;
        #pragma unroll
        for (int mt = 0; mt < 2; mt++) {
            #pragma unroll
            for (int nt = 0; nt < 4; nt++) {
                int col = nBase + nt * 8 + tig * 2;
                int r0  = mBase + mt * 16 + gid;
                float bx = L1b[col], by = L1b[col + 1];
                float2 v0, v1;
                v0.x = fmaxf(c1[mt][nt][0] + bx, 0.f);
                v0.y = fmaxf(c1[mt][nt][1] + by, 0.f);
                v1.x = fmaxf(c1[mt][nt][2] + bx, 0.f);
                v1.y = fmaxf(c1[mt][nt][3] + by, 0.f);
                *(float2*)(H3t + (size_t)r0 * FUSED_H3STR + col) = v0;
                *(float2*)(H3t + (size_t)(r0 + 8) * FUSED_H3STR + col) = v1;
            }
        }
    }
    __syncthreads();   // H3 tile complete before phase-2 staging reads it

    // ---- phase 2: H4 = relu(H3 @ L2w + L2b), N=64, A from smem ----
    float c2[2][2][4];
    #pragma unroll
    for (int i = 0; i < 2; i++)
        #pragma unroll
        for (int j = 0; j < 2; j++)
            #pragma unroll
            for (int q = 0; q < 4; q++) c2[i][j][q] = 0.f;

    mma_core<128, FUSED_H3STR, 2, 2, false>(dsm, sbase, H3t, B4hi, B4lo,
                                            0, Mloc, c2);

    // write H4 (+bias, relu) into Ct (aliases H3 region; H3 dead now)
    {
        const int nBase = (wid & 3) * 16;
        #pragma unroll
        for (int mt = 0; mt < 2; mt++) {
            #pragma unroll
            for (int nt = 0; nt < 2; nt++) {
                int col = nBase + nt * 8 + tig * 2;
                int r0  = mBase + mt * 16 + gid;
                float bx = L2b[col], by = L2b[col + 1];
                Ct[(size_t)r0 * FUSED_CTSTR + col]           = fmaxf(c2[mt][nt][0] + bx, 0.f);
                Ct[(size_t)r0 * FUSED_CTSTR + col + 1]       = fmaxf(c2[mt][nt][1] + by, 0.f);
                Ct[(size_t)(r0 + 8) * FUSED_CTSTR + col]     = fmaxf(c2[mt][nt][2] + bx, 0.f);
                Ct[(size_t)(r0 + 8) * FUSED_CTSTR + col + 1] = fmaxf(c2[mt][nt][3] + by, 0.f);
            }
        }
    }
    __syncthreads();

    // ---- head: per-warp logits + log_softmax ----
    #pragma unroll
    for (int rr = 0; rr < 8; rr++) {
        int r  = wid * 8 + rr;
        int gr = rowBase + r;
        if (gr >= M) continue;

        float acc2 = -1e30f;
        if (lane < NCLS) {
            acc2 = b3s[lane];
            #pragma unroll 8
            for (int k = 0; k < D4; k++)
                acc2 = fmaf(Ct[(size_t)r * FUSED_CTSTR + k], W3s[k * NCLS + lane], acc2);
        }
        float m = acc2;
        #pragma unroll
        for (int o = 16; o > 0; o >>= 1)
            m = fmaxf(m, __shfl_xor_sync(0xffffffffu, m, o));
        float ex = (lane < NCLS) ? expf(acc2 - m) : 0.f;
        float ssum = ex;
        #pragma unroll
        for (int o = 16; o > 0; o >>= 1)
            ssum += __shfl_xor_sync(0xffffffffu, ssum, o);
        float lse = m + logf(ssum);
        if (lane < NCLS)
            out[(size_t)gr * NCLS + lane] = acc2 - lse;
    }
}

// ---------------------------------------------------------------------------
// Batched edge scatters. scatter128: 16 edges per warp (more MLP).
// ---------------------------------------------------------------------------
__global__ void __launch_bounds__(256)
scatter_add128_kernel(const float* __restrict__ src_feat,
                      float* __restrict__ dst_feat,
                      const int* __restrict__ ei, int nEdges)
{
    const int w    = blockIdx.x * (blockDim.x >> 5) + (threadIdx.x >> 5);
    const int lane = threadIdx.x & 31;
    const int eb   = w * 16;
    if (eb >= nEdges) return;
    const int n = min(16, nEdges - eb);

    int idx = 0;
    if (lane < 16) {
        if (lane < n) idx = ei[eb + lane];
    } else {
        if (lane - 16 < n) idx = ei[nEdges + eb + (lane - 16)];
    }

    float4 v[16];
    #pragma unroll
    for (int i = 0; i < 16; i++) {
        int s = __shfl_sync(0xffffffffu, idx, i);
        if (i < n)
            v[i] = *(const float4*)(src_feat + (size_t)s * 128 + lane * 4);
    }
    #pragma unroll
    for (int i = 0; i < 16; i++) {
        int d = __shfl_sync(0xffffffffu, idx, 16 + i);
        if (i < n) {
            float* dp = dst_feat + (size_t)d * 128 + lane * 4;
            asm volatile("red.global.add.v4.f32 [%0], {%1,%2,%3,%4};"
                         :: "l"(dp), "f"(v[i].x), "f"(v[i].y), "f"(v[i].z), "f"(v[i].w)
                         : "memory");
        }
    }
}

__global__ void __launch_bounds__(256)
scatter_add64_kernel(const float* __restrict__ src_feat,
                     float* __restrict__ dst_feat,
                     const int* __restrict__ ei, int nEdges)
{
    const int w    = blockIdx.x * (blockDim.x >> 5) + (threadIdx.x >> 5);
    const int lane = threadIdx.x & 31;
    const int eb   = w * 16;
    if (eb >= nEdges) return;
    const int n    = min(16, nEdges - eb);
    const int half = lane >> 4;
    const int sub  = lane & 15;

    int idx = 0;
    if (lane < 16) {
        if (lane < n) idx = ei[eb + lane];
    } else {
        if (lane - 16 < n) idx = ei[nEdges + eb + (lane - 16)];
    }

    float4 v[8];
    #pragma unroll
    for (int it = 0; it < 8; it++) {
        int e = it * 2 + half;
        int s = __shfl_sync(0xffffffffu, idx, e);
        if (e < n)
            v[it] = *(const float4*)(src_feat + (size_t)s * 64 + sub * 4);
    }
    #pragma unroll
    for (int it = 0; it < 8; it++) {
        int e = it * 2 + half;
        int d = __shfl_sync(0xffffffffu, idx, 16 + e);
        if (e < n) {
            float* dp = dst_feat + (size_t)d * 64 + sub * 4;
            asm volatile("red.global.add.v4.f32 [%0], {%1,%2,%3,%4};"
                         :: "l"(dp), "f"(v[it].x), "f"(v[it].y), "f"(v[it].z), "f"(v[it].w)
                         : "memory");
        }
    }
}

// ---------------------------------------------------------------------------
// Launch
// ---------------------------------------------------------------------------
extern "C" void kernel_launch(void* const* d_in, const int* in_sizes, int n_in,
                              void* d_out, int out_size)
{
    const float* x      = (const float*)d_in[0];
    const int*   ei     = (const int*)d_in[1];
    const float* W1_rel = (const float*)d_in[2];
    const float* W1_rt  = (const float*)d_in[3];
    const float* b1     = (const float*)d_in[4];
    const float* W2_rel = (const float*)d_in[5];
    const float* W2_rt  = (const float*)d_in[6];
    const float* b2     = (const float*)d_in[7];
    const float* L1w    = (const float*)d_in[8];
    const float* L1b    = (const float*)d_in[9];
    const float* L2w    = (const float*)d_in[10];
    const float* L2b    = (const float*)d_in[11];
    const float* L3w    = (const float*)d_in[12];
    const float* L3b    = (const float*)d_in[13];
    float*       out    = (float*)d_out;

    const int M  = in_sizes[0] / DIN;   // 20000
    const int nE = in_sizes[1] / 2;     // 320000

    float *XR, *H1, *XR2, *H2;
    __nv_bfloat16 *B1hi, *B1lo, *B2hi, *B2lo, *B3hi, *B3lo, *B4hi, *B4lo;
    cudaGetSymbolAddress((void**)&XR,   g_XR);
    cudaGetSymbolAddress((void**)&H1,   g_H1);
    cudaGetSymbolAddress((void**)&XR2,  g_XR2);
    cudaGetSymbolAddress((void**)&H2,   g_H2);
    cudaGetSymbolAddress((void**)&B1hi, g_B1hi);
    cudaGetSymbolAddress((void**)&B1lo, g_B1lo);
    cudaGetSymbolAddress((void**)&B2hi, g_B2hi);
    cudaGetSymbolAddress((void**)&B2lo, g_B2lo);
    cudaGetSymbolAddress((void**)&B3hi, g_B3hi);
    cudaGetSymbolAddress((void**)&B3lo, g_B3lo);
    cudaGetSymbolAddress((void**)&B4hi, g_B4hi);
    cudaGetSymbolAddress((void**)&B4lo, g_B4lo);

    cudaFuncSetAttribute(mlp_fused_kernel,
                         cudaFuncAttributeMaxDynamicSharedMemorySize, FUSED_SMEM);

    const int gM64 = (M + 63) / 64;   // 313

    // weight prep (all layers)
    {
        int ntot = NW1 + NW2 + NW3 + NW4;
        prep_weights_kernel<<<(ntot + 255) / 256, 256>>>(W1_rel, W1_rt, W2_rel,
                                                         W2_rt, L1w, L2w);
    }

    // conv1: XR = x@W1_rel ; H1 = x@W1_root + b1
    mma_gemm_kernel<256, 0, false>
        <<<dim3(gM64, 2), 256>>>(x, B1hi, B1lo, b1, XR, H1, M);

    // H1[dst] += XR[src]  (16 edges per warp)
    {
        int warps = (nE + 15) / 16;
        int blks  = (warps + 7) / 8;
        scatter_add128_kernel<<<blks, 256>>>(XR, H1, ei, nE);
    }

    // conv2 (both outputs): XR2 = relu(H1)@W2_rel ; H2 = relu(H1)@W2_root + b2
    mma_gemm_kernel<128, 1, true>
        <<<gM64, 256>>>(H1, B2hi, B2lo, b2, XR2, H2, M);

    // H2[dst] += XR2[src]
    {
        int warps = (nE + 15) / 16;
        int blks  = (warps + 7) / 8;
        scatter_add64_kernel<<<blks, 256>>>(XR2, H2, ei, nE);
    }

    // fused MLP: mlp1 + mlp2 + head
    mlp_fused_kernel<<<gM64, 256, FUSED_SMEM>>>(H2, B3hi, B3lo, L1b,
                                                B4hi, B4lo, L2b, L3w, L3b,
                                                out, M);
}

// round 14
// speedup vs baseline: 2.4092x; 1.0161x over previous
#include <cuda_runtime.h>
#include <cuda_bf16.h>
#include <cuda_fp16.h>
#include <math.h>
#include <stdint.h>

// ---------------------------------------------------------------------------
// Problem constants
// ---------------------------------------------------------------------------
#define N_NODES_MAX 20000
#define DIN 256
#define D1 128
#define D2 64
#define D3 128
#define D4 64
#define NCLS 10

// ---------------------------------------------------------------------------
// Scratch (static device globals; no allocations anywhere)
// ---------------------------------------------------------------------------
__device__ __half g_XRh[N_NODES_MAX * D1];     // fp16: scatter gather source
__device__ float  g_H1 [N_NODES_MAX * D1];
__device__ float  g_XR2[N_NODES_MAX * D2];
__device__ float  g_H2 [N_NODES_MAX * D2];

// bf16 hi/lo weights, transposed to [n][k] K-major
__device__ __nv_bfloat16 g_B1hi[2 * D1 * DIN];
__device__ __nv_bfloat16 g_B1lo[2 * D1 * DIN];
__device__ __nv_bfloat16 g_B2hi[128 * 128];
__device__ __nv_bfloat16 g_B2lo[128 * 128];
__device__ __nv_bfloat16 g_B3hi[128 * 64];
__device__ __nv_bfloat16 g_B3lo[128 * 64];
__device__ __nv_bfloat16 g_B4hi[64 * 128];
__device__ __nv_bfloat16 g_B4lo[64 * 128];

// ---------------------------------------------------------------------------
// mma.sync helpers
// ---------------------------------------------------------------------------
__device__ __forceinline__ uint32_t smem_u32(const void* p) {
    uint32_t a;
    asm("{ .reg .u64 t; cvta.to.shared.u64 t, %1; cvt.u32.u64 %0, t; }"
        : "=r"(a) : "l"(p));
    return a;
}
__device__ __forceinline__ void ldsm_x4(uint32_t& r0, uint32_t& r1,
                                        uint32_t& r2, uint32_t& r3,
                                        uint32_t addr) {
    asm volatile("ldmatrix.sync.aligned.m8n8.x4.shared.b16 {%0,%1,%2,%3}, [%4];"
                 : "=r"(r0), "=r"(r1), "=r"(r2), "=r"(r3) : "r"(addr));
}
__device__ __forceinline__ void mma_bf16(float& c0, float& c1, float& c2, float& c3,
                                         uint32_t a0, uint32_t a1, uint32_t a2, uint32_t a3,
                                         uint32_t b0, uint32_t b1) {
    asm volatile(
        "mma.sync.aligned.m16n8k16.row.col.f32.bf16.bf16.f32 "
        "{%0,%1,%2,%3}, {%4,%5,%6,%7}, {%8,%9}, {%0,%1,%2,%3};"
        : "+f"(c0), "+f"(c1), "+f"(c2), "+f"(c3)
        : "r"(a0), "r"(a1), "r"(a2), "r"(a3), "r"(b0), "r"(b1));
}

// ---------------------------------------------------------------------------
// Combined weight prep: fp32 -> bf16 hi/lo, transposed to [n][k]
// ---------------------------------------------------------------------------
#define NW1 (2 * DIN * D1)      // 65536
#define NW2 (128 * 128)         // 16384
#define NW3 (128 * 64)          // 8192
#define NW4 (64 * 128)          // 8192
__global__ void prep_weights_kernel(const float* __restrict__ W1rel,
                                    const float* __restrict__ W1rt,
                                    const float* __restrict__ W2rel,
                                    const float* __restrict__ W2rt,
                                    const float* __restrict__ L1w,
                                    const float* __restrict__ L2w)
{
    int idx = blockIdx.x * blockDim.x + threadIdx.x;
    float f;
    __nv_bfloat16* dh;
    __nv_bfloat16* dl;
    size_t off;
    if (idx < NW1) {
        int w   = idx / (DIN * D1);
        int rem = idx % (DIN * D1);
        int k   = rem / D1;
        int n   = rem % D1;
        f   = (w ? W1rt : W1rel)[k * D1 + n];
        off = (size_t)w * D1 * DIN + (size_t)n * DIN + k;
        dh = g_B1hi; dl = g_B1lo;
    } else if (idx < NW1 + NW2) {
        int i = idx - NW1;
        int n = i / 128;
        int k = i % 128;
        f   = (n < 64) ? W2rel[k * 64 + n] : W2rt[k * 64 + (n - 64)];
        off = (size_t)n * 128 + k;
        dh = g_B2hi; dl = g_B2lo;
    } else if (idx < NW1 + NW2 + NW3) {
        int i = idx - NW1 - NW2;
        int n = i / 64;
        int k = i % 64;
        f   = L1w[k * 128 + n];
        off = (size_t)n * 64 + k;
        dh = g_B3hi; dl = g_B3lo;
    } else if (idx < NW1 + NW2 + NW3 + NW4) {
        int i = idx - NW1 - NW2 - NW3;
        int n = i / 128;
        int k = i % 128;
        f   = L2w[k * 64 + n];
        off = (size_t)n * 128 + k;
        dh = g_B4hi; dl = g_B4lo;
    } else return;

    __nv_bfloat16 h = __float2bfloat16(f);
    dh[off] = h;
    dl[off] = __float2bfloat16(f - __bfloat162float(h));
}

// ---------------------------------------------------------------------------
// Pipelined mma core (register prefetch, 80B row stride => conflict-free
// ldmatrix). BM fixed at 64 (MT=2). NW in {2,4}. 8 warps = 2(m) x 4(n).
// A may live in GLOBAL or SHARED (generic pointer), row stride ASTRIDE floats.
// ---------------------------------------------------------------------------
template<int KDIM, int ASTRIDE, int MT, int NW, bool RELU_A>
__device__ __forceinline__ void mma_core(
    char* smem, uint32_t sbase,
    const float* __restrict__ A,
    const __nv_bfloat16* __restrict__ Bh,
    const __nv_bfloat16* __restrict__ Bl,
    int rowBase, int M,
    float c[MT][NW][4])
{
    constexpr int BM = 2 * MT * 16;
    static_assert(BM == 64, "core assumes BM=64");
    constexpr int BN = 4 * NW * 8;
    constexpr int RS = 80;
    constexpr int OFF_AL = BM * RS;
    constexpr int OFF_BH = 2 * BM * RS;
    constexpr int OFF_BL = 2 * BM * RS + BN * RS;
    constexpr int BIT = BN / 64;
    constexpr int NCH = KDIM / 32;

    const int tid  = threadIdx.x;
    const int wid  = tid >> 5;
    const int lane = tid & 31;

    const int mBase = (wid >> 2) * (MT * 16);
    const int nBase = (wid & 3) * (NW * 8);

    const int qr    = lane & 7;
    const int half1 = (lane >> 3) & 1;
    const int half2 = (lane >> 4) & 1;

    const int rA  = tid >> 2;
    const int kcA = tid & 3;
    const int gA  = rowBase + rA;

    float aR[8];
    uint4 bhR[BIT], blR[BIT];

    // ---- prologue: load chunk 0 ----
    {
        if (gA < M) {
            const float* ap = A + (size_t)gA * ASTRIDE + kcA * 8;
            float4 x0 = *(const float4*)ap;
            float4 x1 = *(const float4*)(ap + 4);
            aR[0]=x0.x; aR[1]=x0.y; aR[2]=x0.z; aR[3]=x0.w;
            aR[4]=x1.x; aR[5]=x1.y; aR[6]=x1.z; aR[7]=x1.w;
        } else {
            #pragma unroll
            for (int j = 0; j < 8; j++) aR[j] = 0.f;
        }
        #pragma unroll
        for (int it = 0; it < BIT; it++) {
            int i = tid + it * 256;
            int r = i >> 2, kc = i & 3;
            bhR[it] = *(const uint4*)(Bh + (size_t)r * KDIM + kc * 8);
            blR[it] = *(const uint4*)(Bl + (size_t)r * KDIM + kc * 8);
        }
    }

    for (int ch = 0; ch < NCH; ch++) {
        // ---- convert + store staged regs to smem ----
        {
            __nv_bfloat16 h[8], l[8];
            #pragma unroll
            for (int j = 0; j < 8; j++) {
                float fv = RELU_A ? fmaxf(aR[j], 0.f) : aR[j];
                h[j] = __float2bfloat16(fv);
                l[j] = __float2bfloat16(fv - __bfloat162float(h[j]));
            }
            uint32_t soA = (uint32_t)(rA * RS + kcA * 16);
            *(uint4*)(smem + soA) = *(uint4*)h;
            *(uint4*)(smem + OFF_AL + soA) = *(uint4*)l;
            #pragma unroll
            for (int it = 0; it < BIT; it++) {
                int i = tid + it * 256;
                int r = i >> 2, kc = i & 3;
                uint32_t soB = (uint32_t)(r * RS + kc * 16);
                *(uint4*)(smem + OFF_BH + soB) = bhR[it];
                *(uint4*)(smem + OFF_BL + soB) = blR[it];
            }
        }
        __syncthreads();

        // ---- prefetch next chunk into registers ----
        if (ch + 1 < NCH) {
            const int k0 = (ch + 1) * 32;
            if (gA < M) {
                const float* ap = A + (size_t)gA * ASTRIDE + k0 + kcA * 8;
                float4 x0 = *(const float4*)ap;
                float4 x1 = *(const float4*)(ap + 4);
                aR[0]=x0.x; aR[1]=x0.y; aR[2]=x0.z; aR[3]=x0.w;
                aR[4]=x1.x; aR[5]=x1.y; aR[6]=x1.z; aR[7]=x1.w;
            } else {
                #pragma unroll
                for (int j = 0; j < 8; j++) aR[j] = 0.f;
            }
            #pragma unroll
            for (int it = 0; it < BIT; it++) {
                int i = tid + it * 256;
                int r = i >> 2, kc = i & 3;
                bhR[it] = *(const uint4*)(Bh + (size_t)r * KDIM + k0 + kc * 8);
                blR[it] = *(const uint4*)(Bl + (size_t)r * KDIM + k0 + kc * 8);
            }
        }

        // ---- compute: 2 k16 steps ----
        #pragma unroll
        for (int ks = 0; ks < 2; ks++) {
            uint32_t ah[MT][4], al[MT][4];
            #pragma unroll
            for (int mt = 0; mt < MT; mt++) {
                int r = mBase + mt * 16 + qr + half1 * 8;
                uint32_t so = (uint32_t)(r * RS + (ks * 2 + half2) * 16);
                ldsm_x4(ah[mt][0], ah[mt][1], ah[mt][2], ah[mt][3], sbase + so);
                ldsm_x4(al[mt][0], al[mt][1], al[mt][2], al[mt][3],
                        sbase + OFF_AL + so);
            }
            uint32_t bh[NW / 2][4], bl[NW / 2][4];
            #pragma unroll
            for (int pr = 0; pr < NW / 2; pr++) {
                int r = nBase + pr * 16 + qr + half2 * 8;
                uint32_t so = (uint32_t)(r * RS + (ks * 2 + half1) * 16);
                ldsm_x4(bh[pr][0], bh[pr][1], bh[pr][2], bh[pr][3],
                        sbase + OFF_BH + so);
                ldsm_x4(bl[pr][0], bl[pr][1], bl[pr][2], bl[pr][3],
                        sbase + OFF_BL + so);
            }
            #pragma unroll
            for (int mt = 0; mt < MT; mt++) {
                #pragma unroll
                for (int nt = 0; nt < NW; nt++) {
                    uint32_t b0h = bh[nt >> 1][(nt & 1) * 2];
                    uint32_t b1h = bh[nt >> 1][(nt & 1) * 2 + 1];
                    uint32_t b0l = bl[nt >> 1][(nt & 1) * 2];
                    uint32_t b1l = bl[nt >> 1][(nt & 1) * 2 + 1];
                    float* cc = c[mt][nt];
                    mma_bf16(cc[0], cc[1], cc[2], cc[3],
                             ah[mt][0], ah[mt][1], ah[mt][2], ah[mt][3], b0h, b1h);
                    mma_bf16(cc[0], cc[1], cc[2], cc[3],
                             ah[mt][0], ah[mt][1], ah[mt][2], ah[mt][3], b0l, b1l);
                    mma_bf16(cc[0], cc[1], cc[2], cc[3],
                             al[mt][0], al[mt][1], al[mt][2], al[mt][3], b0h, b1h);
                }
            }
        }
        __syncthreads();
    }
}

// ---------------------------------------------------------------------------
// conv GEMM kernels on the mma core.
//   MODE 0 (conv1): blockIdx.y==0 -> XR (fp16, no bias); y==1 -> H1 (+b1).
//   MODE 1 (conv2): cols<64 -> C0 (stride 64); cols>=64 -> C1+bias (stride 64).
// ---------------------------------------------------------------------------
template<int KDIM, int MODE, bool RELU_A>
__global__ void __launch_bounds__(256, 2)
mma_gemm_kernel(const float* __restrict__ A,
                const __nv_bfloat16* __restrict__ Bhi,
                const __nv_bfloat16* __restrict__ Blo,
                const float* __restrict__ bias,
                void* __restrict__ C0v, float* __restrict__ C1, int M)
{
    constexpr int MT = 2, NW = 4;
    constexpr int BM = 64;
    constexpr int BN = 128;
    __shared__ char smem[2 * (BM + BN) * 80];   // 30720 B
    const uint32_t sbase = smem_u32(smem);

    const int wid  = threadIdx.x >> 5;
    const int lane = threadIdx.x & 31;
    const int rowBase = blockIdx.x * BM;

    const __nv_bfloat16* Bh = Bhi;
    const __nv_bfloat16* Bl = Blo;
    if (MODE == 0) {
        Bh += (size_t)blockIdx.y * 128 * KDIM;
        Bl += (size_t)blockIdx.y * 128 * KDIM;
    }

    float c[MT][NW][4];
    #pragma unroll
    for (int i = 0; i < MT; i++)
        #pragma unroll
        for (int j = 0; j < NW; j++)
            #pragma unroll
            for (int q = 0; q < 4; q++) c[i][j][q] = 0.f;

    mma_core<KDIM, KDIM, MT, NW, RELU_A>(smem, sbase, A, Bh, Bl, rowBase, M, c);

    // ---- epilogue ----
    const int mBase = (wid >> 2) * (MT * 16);
    const int nBase = (wid & 3) * (NW * 8);
    const int gid = lane >> 2;
    const int tig = lane & 3;
    #pragma unroll
    for (int mt = 0; mt < MT; mt++) {
        #pragma unroll
        for (int nt = 0; nt < NW; nt++) {
            int col  = nBase + nt * 8 + tig * 2;
            int row0 = rowBase + mBase + mt * 16 + gid;
            int row1 = row0 + 8;

            if (MODE == 0 && blockIdx.y == 0) {
                // XR output in fp16
                __half* dst = (__half*)C0v;
                if (row0 < M)
                    *(__half2*)(dst + (size_t)row0 * 128 + col) =
                        __floats2half2_rn(c[mt][nt][0], c[mt][nt][1]);
                if (row1 < M)
                    *(__half2*)(dst + (size_t)row1 * 128 + col) =
                        __floats2half2_rn(c[mt][nt][2], c[mt][nt][3]);
                continue;
            }

            float* dst; int ccol; int stride; float bx = 0.f, by = 0.f;
            if (MODE == 0) {
                dst = C1; ccol = col; stride = 128;
                bx = bias[col]; by = bias[col + 1];
            } else {
                if (col < 64) { dst = (float*)C0v; ccol = col; stride = 64; }
                else          { dst = C1; ccol = col - 64;     stride = 64;
                                bx = bias[ccol]; by = bias[ccol + 1]; }
            }

            if (row0 < M) {
                float2 v; v.x = c[mt][nt][0] + bx; v.y = c[mt][nt][1] + by;
                *(float2*)(dst + (size_t)row0 * stride + ccol) = v;
            }
            if (row1 < M) {
                float2 v; v.x = c[mt][nt][2] + bx; v.y = c[mt][nt][3] + by;
                *(float2*)(dst + (size_t)row1 * stride + ccol) = v;
            }
        }
    }
}

// ---------------------------------------------------------------------------
// Fused MLP: H3 = relu(H2@L1w+L1b) kept in SMEM; H4 = relu(H3@L2w+L2b);
// out = log_softmax(H4@L3w + b3). One kernel, 64 rows per block.
// ---------------------------------------------------------------------------
#define FUSED_H3OFF   30720
#define FUSED_H3STR   132
#define FUSED_W3OFF   64512
#define FUSED_B3OFF   67072
#define FUSED_SMEM    67200
#define FUSED_CTSTR   68

__global__ void __launch_bounds__(256, 2)
mlp_fused_kernel(const float* __restrict__ A,      // H2 [M,64]
                 const __nv_bfloat16* __restrict__ B3hi,
                 const __nv_bfloat16* __restrict__ B3lo,
                 const float* __restrict__ L1b,
                 const __nv_bfloat16* __restrict__ B4hi,
                 const __nv_bfloat16* __restrict__ B4lo,
                 const float* __restrict__ L2b,
                 const float* __restrict__ W3,
                 const float* __restrict__ b3,
                 float* __restrict__ out, int M)
{
    extern __shared__ char dsm[];
    const uint32_t sbase = smem_u32(dsm);
    float* H3t = (float*)(dsm + FUSED_H3OFF);
    float* Ct  = (float*)(dsm + FUSED_H3OFF);
    float* W3s = (float*)(dsm + FUSED_W3OFF);
    float* b3s = (float*)(dsm + FUSED_B3OFF);

    const int tid  = threadIdx.x;
    const int wid  = tid >> 5;
    const int lane = tid & 31;
    const int rowBase = blockIdx.x * 64;
    const int Mloc = min(64, M - rowBase);

    for (int i = tid; i < D4 * NCLS; i += 256) W3s[i] = W3[i];
    if (tid < NCLS) b3s[tid] = b3[tid];

    const int mBase = (wid >> 2) * 32;
    const int gid = lane >> 2;
    const int tig = lane & 3;

    // ---- phase 1: H3 tile = relu(H2 @ L1w + L1b), N=128 ----
    {
        float c1[2][4][4];
        #pragma unroll
        for (int i = 0; i < 2; i++)
            #pragma unroll
            for (int j = 0; j < 4; j++)
                #pragma unroll
                for (int q = 0; q < 4; q++) c1[i][j][q] = 0.f;

        mma_core<64, 64, 2, 4, false>(dsm, sbase, A, B3hi, B3lo, rowBase, M, c1);

        const int nBase = (wid & 3) * 32;
        #pragma unroll
        for (int mt = 0; mt < 2; mt++) {
            #pragma unroll
            for (int nt = 0; nt < 4; nt++) {
                int col = nBase + nt * 8 + tig * 2;
                int r0  = mBase + mt * 16 + gid;
                float bx = L1b[col], by = L1b[col + 1];
                float2 v0, v1;
                v0.x = fmaxf(c1[mt][nt][0] + bx, 0.f);
                v0.y = fmaxf(c1[mt][nt][1] + by, 0.f);
                v1.x = fmaxf(c1[mt][nt][2] + bx, 0.f);
                v1.y = fmaxf(c1[mt][nt][3] + by, 0.f);
                *(float2*)(H3t + (size_t)r0 * FUSED_H3STR + col) = v0;
                *(float2*)(H3t + (size_t)(r0 + 8) * FUSED_H3STR + col) = v1;
            }
        }
    }
    __syncthreads();

    // ---- phase 2: H4 = relu(H3 @ L2w + L2b), N=64, A from smem ----
    float c2[2][2][4];
    #pragma unroll
    for (int i = 0; i < 2; i++)
        #pragma unroll
        for (int j = 0; j < 2; j++)
            #pragma unroll
            for (int q = 0; q < 4; q++) c2[i][j][q] = 0.f;

    mma_core<128, FUSED_H3STR, 2, 2, false>(dsm, sbase, H3t, B4hi, B4lo,
                                            0, Mloc, c2);

    {
        const int nBase = (wid & 3) * 16;
        #pragma unroll
        for (int mt = 0; mt < 2; mt++) {
            #pragma unroll
            for (int nt = 0; nt < 2; nt++) {
                int col = nBase + nt * 8 + tig * 2;
                int r0  = mBase + mt * 16 + gid;
                float bx = L2b[col], by = L2b[col + 1];
                Ct[(size_t)r0 * FUSED_CTSTR + col]           = fmaxf(c2[mt][nt][0] + bx, 0.f);
                Ct[(size_t)r0 * FUSED_CTSTR + col + 1]       = fmaxf(c2[mt][nt][1] + by, 0.f);
                Ct[(size_t)(r0 + 8) * FUSED_CTSTR + col]     = fmaxf(c2[mt][nt][2] + bx, 0.f);
                Ct[(size_t)(r0 + 8) * FUSED_CTSTR + col + 1] = fmaxf(c2[mt][nt][3] + by, 0.f);
            }
        }
    }
    __syncthreads();

    // ---- head: per-warp logits + log_softmax ----
    #pragma unroll
    for (int rr = 0; rr < 8; rr++) {
        int r  = wid * 8 + rr;
        int gr = rowBase + r;
        if (gr >= M) continue;

        float acc2 = -1e30f;
        if (lane < NCLS) {
            acc2 = b3s[lane];
            #pragma unroll 8
            for (int k = 0; k < D4; k++)
                acc2 = fmaf(Ct[(size_t)r * FUSED_CTSTR + k], W3s[k * NCLS + lane], acc2);
        }
        float m = acc2;
        #pragma unroll
        for (int o = 16; o > 0; o >>= 1)
            m = fmaxf(m, __shfl_xor_sync(0xffffffffu, m, o));
        float ex = (lane < NCLS) ? expf(acc2 - m) : 0.f;
        float ssum = ex;
        #pragma unroll
        for (int o = 16; o > 0; o >>= 1)
            ssum += __shfl_xor_sync(0xffffffffu, ssum, o);
        float lse = m + logf(ssum);
        if (lane < NCLS)
            out[(size_t)gr * NCLS + lane] = acc2 - lse;
    }
}

// ---------------------------------------------------------------------------
// Batched edge scatters.
// scatter128: fp16 source, 16 edges/warp; each lane reads 4 halves (8B).
// ---------------------------------------------------------------------------
__global__ void __launch_bounds__(256)
scatter_add128_kernel(const __half* __restrict__ src_feat,
                      float* __restrict__ dst_feat,
                      const int* __restrict__ ei, int nEdges)
{
    const int w    = blockIdx.x * (blockDim.x >> 5) + (threadIdx.x >> 5);
    const int lane = threadIdx.x & 31;
    const int eb   = w * 16;
    if (eb >= nEdges) return;
    const int n = min(16, nEdges - eb);

    int idx = 0;
    if (lane < 16) {
        if (lane < n) idx = ei[eb + lane];
    } else {
        if (lane - 16 < n) idx = ei[nEdges + eb + (lane - 16)];
    }

    uint2 v[16];
    #pragma unroll
    for (int i = 0; i < 16; i++) {
        int s = __shfl_sync(0xffffffffu, idx, i);
        if (i < n)
            v[i] = *(const uint2*)(src_feat + (size_t)s * 128 + lane * 4);
    }
    #pragma unroll
    for (int i = 0; i < 16; i++) {
        int d = __shfl_sync(0xffffffffu, idx, 16 + i);
        if (i < n) {
            float2 f01 = __half22float2(*(__half2*)&v[i].x);
            float2 f23 = __half22float2(*(__half2*)&v[i].y);
            float* dp = dst_feat + (size_t)d * 128 + lane * 4;
            asm volatile("red.global.add.v4.f32 [%0], {%1,%2,%3,%4};"
                         :: "l"(dp), "f"(f01.x), "f"(f01.y), "f"(f23.x), "f"(f23.y)
                         : "memory");
        }
    }
}

__global__ void __launch_bounds__(256)
scatter_add64_kernel(const float* __restrict__ src_feat,
                     float* __restrict__ dst_feat,
                     const int* __restrict__ ei, int nEdges)
{
    const int w    = blockIdx.x * (blockDim.x >> 5) + (threadIdx.x >> 5);
    const int lane = threadIdx.x & 31;
    const int eb   = w * 16;
    if (eb >= nEdges) return;
    const int n    = min(16, nEdges - eb);
    const int half = lane >> 4;
    const int sub  = lane & 15;

    int idx = 0;
    if (lane < 16) {
        if (lane < n) idx = ei[eb + lane];
    } else {
        if (lane - 16 < n) idx = ei[nEdges + eb + (lane - 16)];
    }

    float4 v[8];
    #pragma unroll
    for (int it = 0; it < 8; it++) {
        int e = it * 2 + half;
        int s = __shfl_sync(0xffffffffu, idx, e);
        if (e < n)
            v[it] = *(const float4*)(src_feat + (size_t)s * 64 + sub * 4);
    }
    #pragma unroll
    for (int it = 0; it < 8; it++) {
        int e = it * 2 + half;
        int d = __shfl_sync(0xffffffffu, idx, 16 + e);
        if (e < n) {
            float* dp = dst_feat + (size_t)d * 64 + sub * 4;
            asm volatile("red.global.add.v4.f32 [%0], {%1,%2,%3,%4};"
                         :: "l"(dp), "f"(v[it].x), "f"(v[it].y), "f"(v[it].z), "f"(v[it].w)
                         : "memory");
        }
    }
}

// ---------------------------------------------------------------------------
// Launch
// ---------------------------------------------------------------------------
extern "C" void kernel_launch(void* const* d_in, const int* in_sizes, int n_in,
                              void* d_out, int out_size)
{
    const float* x      = (const float*)d_in[0];
    const int*   ei     = (const int*)d_in[1];
    const float* W1_rel = (const float*)d_in[2];
    const float* W1_rt  = (const float*)d_in[3];
    const float* b1     = (const float*)d_in[4];
    const float* W2_rel = (const float*)d_in[5];
    const float* W2_rt  = (const float*)d_in[6];
    const float* b2     = (const float*)d_in[7];
    const float* L1w    = (const float*)d_in[8];
    const float* L1b    = (const float*)d_in[9];
    const float* L2w    = (const float*)d_in[10];
    const float* L2b    = (const float*)d_in[11];
    const float* L3w    = (const float*)d_in[12];
    const float* L3b    = (const float*)d_in[13];
    float*       out    = (float*)d_out;

    const int M  = in_sizes[0] / DIN;   // 20000
    const int nE = in_sizes[1] / 2;     // 320000

    __half* XRh;
    float *H1, *XR2, *H2;
    __nv_bfloat16 *B1hi, *B1lo, *B2hi, *B2lo, *B3hi, *B3lo, *B4hi, *B4lo;
    cudaGetSymbolAddress((void**)&XRh,  g_XRh);
    cudaGetSymbolAddress((void**)&H1,   g_H1);
    cudaGetSymbolAddress((void**)&XR2,  g_XR2);
    cudaGetSymbolAddress((void**)&H2,   g_H2);
    cudaGetSymbolAddress((void**)&B1hi, g_B1hi);
    cudaGetSymbolAddress((void**)&B1lo, g_B1lo);
    cudaGetSymbolAddress((void**)&B2hi, g_B2hi);
    cudaGetSymbolAddress((void**)&B2lo, g_B2lo);
    cudaGetSymbolAddress((void**)&B3hi, g_B3hi);
    cudaGetSymbolAddress((void**)&B3lo, g_B3lo);
    cudaGetSymbolAddress((void**)&B4hi, g_B4hi);
    cudaGetSymbolAddress((void**)&B4lo, g_B4lo);

    cudaFuncSetAttribute(mlp_fused_kernel,
                         cudaFuncAttributeMaxDynamicSharedMemorySize, FUSED_SMEM);

    const int gM64 = (M + 63) / 64;   // 313

    // weight prep (all layers)
    {
        int ntot = NW1 + NW2 + NW3 + NW4;
        prep_weights_kernel<<<(ntot + 255) / 256, 256>>>(W1_rel, W1_rt, W2_rel,
                                                         W2_rt, L1w, L2w);
    }

    // conv1: XRh = fp16(x@W1_rel) ; H1 = x@W1_root + b1
    mma_gemm_kernel<256, 0, false>
        <<<dim3(gM64, 2), 256>>>(x, B1hi, B1lo, b1, (void*)XRh, H1, M);

    // H1[dst] += XRh[src]  (fp16 gather, 16 edges per warp)
    {
        int warps = (nE + 15) / 16;
        int blks  = (warps + 7) / 8;
        scatter_add128_kernel<<<blks, 256>>>(XRh, H1, ei, nE);
    }

    // conv2 (both outputs): XR2 = relu(H1)@W2_rel ; H2 = relu(H1)@W2_root + b2
    mma_gemm_kernel<128, 1, true>
        <<<gM64, 256>>>(H1, B2hi, B2lo, b2, (void*)XR2, H2, M);

    // H2[dst] += XR2[src]
    {
        int warps = (nE + 15) / 16;
        int blks  = (warps + 7) / 8;
        scatter_add64_kernel<<<blks, 256>>>(XR2, H2, ei, nE);
    }

    // fused MLP: mlp1 + mlp2 + head
    mlp_fused_kernel<<<gM64, 256, FUSED_SMEM>>>(H2, B3hi, B3lo, L1b,
                                                B4hi, B4lo, L2b, L3w, L3b,
                                                out, M);
}